// round 1
// baseline (speedup 1.0000x reference)
#include <cuda_runtime.h>
#include <math.h>

#define D_MODEL 2048
#define N_HEAD  16
#define HEAD_DIM 128
#define BATCH   2
#define SEQ     2048

// Scratch (static __device__ arrays — allowed; no cudaMalloc anywhere)
static __device__ float g_qkv[(size_t)BATCH * SEQ * 3 * D_MODEL]; // ~100 MB
static __device__ float g_att[(size_t)BATCH * SEQ * D_MODEL];     // ~33 MB

// ---------------------------------------------------------------------------
// SGEMM with bias: C[M,N] = A[M,K] @ B[K,N] + bias[N]
// BM=BN=128, BK=16, 256 threads, 8x8 per thread (split 4+4 for conflict-free LDS)
// ---------------------------------------------------------------------------
__global__ __launch_bounds__(256, 2) void sgemm_bias_kernel(
    const float* __restrict__ A, const float* __restrict__ B,
    const float* __restrict__ bias, float* __restrict__ C,
    int M, int N, int K)
{
    __shared__ float As[16][132];   // A tile, stored transposed [k][m] (+4 pad)
    __shared__ float Bs[16][132];   // B tile [k][n] (+4 pad)

    const int tid = threadIdx.x;
    const int tx  = tid & 15;
    const int ty  = tid >> 4;
    const int bm  = blockIdx.y << 7;
    const int bn  = blockIdx.x << 7;

    float acc[8][8];
#pragma unroll
    for (int r = 0; r < 8; ++r)
#pragma unroll
        for (int c = 0; c < 8; ++c) acc[r][c] = 0.f;

    for (int k0 = 0; k0 < K; k0 += 16) {
        // load A tile (128 rows x 16 k), transpose into As[k][m]
#pragma unroll
        for (int i = 0; i < 2; ++i) {
            int idx = tid * 4 + i * 1024;
            int m = idx >> 4;
            int k = idx & 15;
            float4 a = *(const float4*)(A + (size_t)(bm + m) * K + k0 + k);
            As[k + 0][m] = a.x;
            As[k + 1][m] = a.y;
            As[k + 2][m] = a.z;
            As[k + 3][m] = a.w;
        }
        // load B tile (16 k x 128 n)
#pragma unroll
        for (int i = 0; i < 2; ++i) {
            int idx = tid * 4 + i * 1024;
            int kk = idx >> 7;
            int n  = idx & 127;
            *(float4*)(&Bs[kk][n]) = *(const float4*)(B + (size_t)(k0 + kk) * N + bn + n);
        }
        __syncthreads();

#pragma unroll
        for (int kk = 0; kk < 16; ++kk) {
            float ar[8], br[8];
            float4 a0 = *(const float4*)(&As[kk][ty * 4]);
            float4 a1 = *(const float4*)(&As[kk][64 + ty * 4]);
            float4 b0 = *(const float4*)(&Bs[kk][tx * 4]);
            float4 b1 = *(const float4*)(&Bs[kk][64 + tx * 4]);
            ar[0]=a0.x; ar[1]=a0.y; ar[2]=a0.z; ar[3]=a0.w;
            ar[4]=a1.x; ar[5]=a1.y; ar[6]=a1.z; ar[7]=a1.w;
            br[0]=b0.x; br[1]=b0.y; br[2]=b0.z; br[3]=b0.w;
            br[4]=b1.x; br[5]=b1.y; br[6]=b1.z; br[7]=b1.w;
#pragma unroll
            for (int r = 0; r < 8; ++r)
#pragma unroll
                for (int c = 0; c < 8; ++c)
                    acc[r][c] = fmaf(ar[r], br[c], acc[r][c]);
        }
        __syncthreads();
    }

    // epilogue: bias add + store (rows/cols split 4+4 across 64-halves)
#pragma unroll
    for (int r = 0; r < 8; ++r) {
        int m = bm + (r < 4 ? ty * 4 + r : 64 + ty * 4 + (r - 4));
        float* cp = C + (size_t)m * N + bn;
        int c0 = tx * 4, c1 = 64 + tx * 4;
        float4 bb0 = *(const float4*)(bias + bn + c0);
        float4 bb1 = *(const float4*)(bias + bn + c1);
        float4 v0 = make_float4(acc[r][0] + bb0.x, acc[r][1] + bb0.y,
                                acc[r][2] + bb0.z, acc[r][3] + bb0.w);
        float4 v1 = make_float4(acc[r][4] + bb1.x, acc[r][5] + bb1.y,
                                acc[r][6] + bb1.z, acc[r][7] + bb1.w);
        *(float4*)(cp + c0) = v0;
        *(float4*)(cp + c1) = v1;
    }
}

// ---------------------------------------------------------------------------
// Flash attention with on-the-fly RoPE.
// grid: (T/64 q-tiles, B*H). block: 256 threads (16x16), each 4 rows x (4+4) cols.
// smem (dynamic, 100 KB): Qs[128][68] (d-major, roped), Ks[128][68] (reused as
// P[64][68] after S), Vs[64][128].
// ---------------------------------------------------------------------------
__global__ __launch_bounds__(256, 2) void flash_attn_kernel()
{
    extern __shared__ float sm[];
    float* Qs = sm;                 // 128*68
    float* Ks = sm + 128 * 68;      // 128*68, later reused as P[64][68]
    float* Vs = sm + 2 * 128 * 68;  // 64*128

    const int tid = threadIdx.x;
    const int tx  = tid & 15;
    const int ty  = tid >> 4;
    const int qt  = blockIdx.x;
    const int b   = blockIdx.y >> 4;
    const int h   = blockIdx.y & 15;
    const int q0  = qt << 6;

    const float RATE_C = 0.14391156831212787f; // ln(10000)/64
    const float SCALE  = 0.08838834764831845f; // 1/sqrt(128)

    // ---- load Q tile with RoPE, transposed into Qs[d][t_local] ----
    for (int i = tid; i < 64 * 64; i += 256) {
        int tl = i >> 6, j = i & 63;
        int t = q0 + tl;
        const float* g = g_qkv + (size_t)(b * SEQ + t) * (3 * D_MODEL) + h * HEAD_DIM;
        float x1 = g[j], x2 = g[j + 64];
        float rate = expf(-RATE_C * (float)j);
        float sv, cv;
        sincosf((float)t * rate, &sv, &cv);
        Qs[j * 68 + tl]        = x1 * cv - x2 * sv;
        Qs[(j + 64) * 68 + tl] = x1 * sv + x2 * cv;
    }

    float m_run[4], l_run[4], o[4][8];
#pragma unroll
    for (int r = 0; r < 4; ++r) {
        m_run[r] = -1e30f;
        l_run[r] = 0.f;
#pragma unroll
        for (int c = 0; c < 8; ++c) o[r][c] = 0.f;
    }

    for (int kt = 0; kt <= qt; ++kt) {
        int k0 = kt << 6;
        __syncthreads();  // previous P@V done reading Ks/Vs

        // ---- load K tile with RoPE (transposed) + V tile ----
        for (int i = tid; i < 64 * 64; i += 256) {
            int tl = i >> 6, j = i & 63;
            int t = k0 + tl;
            const float* g = g_qkv + (size_t)(b * SEQ + t) * (3 * D_MODEL) + D_MODEL + h * HEAD_DIM;
            float x1 = g[j], x2 = g[j + 64];
            float rate = expf(-RATE_C * (float)j);
            float sv, cv;
            sincosf((float)t * rate, &sv, &cv);
            Ks[j * 68 + tl]        = x1 * cv - x2 * sv;
            Ks[(j + 64) * 68 + tl] = x1 * sv + x2 * cv;
        }
        for (int i = tid * 4; i < 64 * 128; i += 1024) {
            int tl = i >> 7, dd = i & 127;
            *(float4*)(Vs + tl * 128 + dd) =
                *(const float4*)(g_qkv + (size_t)(b * SEQ + k0 + tl) * (3 * D_MODEL)
                                 + 2 * D_MODEL + h * HEAD_DIM + dd);
        }
        __syncthreads();

        // ---- S = Q @ K^T (64x64 tile; thread computes 4x4) ----
        float s[4][4];
#pragma unroll
        for (int r = 0; r < 4; ++r)
#pragma unroll
            for (int c = 0; c < 4; ++c) s[r][c] = 0.f;

#pragma unroll 8
        for (int kk = 0; kk < 128; ++kk) {
            float4 q4 = *(const float4*)(Qs + kk * 68 + ty * 4);
            float4 k4 = *(const float4*)(Ks + kk * 68 + tx * 4);
            float qv[4] = {q4.x, q4.y, q4.z, q4.w};
            float kv[4] = {k4.x, k4.y, k4.z, k4.w};
#pragma unroll
            for (int r = 0; r < 4; ++r)
#pragma unroll
                for (int c = 0; c < 4; ++c)
                    s[r][c] = fmaf(qv[r], kv[c], s[r][c]);
        }

        // ---- scale + causal mask (only diagonal tile needs masking) ----
        bool diag = (kt == qt);
#pragma unroll
        for (int r = 0; r < 4; ++r)
#pragma unroll
            for (int c = 0; c < 4; ++c) {
                float v = s[r][c] * SCALE;
                if (diag && (tx * 4 + c) > (ty * 4 + r)) v = -1e30f;
                s[r][c] = v;
            }

        // ---- online softmax stats (row reductions across the 16 tx lanes) ----
        float alpha[4];
#pragma unroll
        for (int r = 0; r < 4; ++r) {
            float v = fmaxf(fmaxf(s[r][0], s[r][1]), fmaxf(s[r][2], s[r][3]));
#pragma unroll
            for (int off = 1; off < 16; off <<= 1)
                v = fmaxf(v, __shfl_xor_sync(0xffffffffu, v, off));
            float mnew = fmaxf(m_run[r], v);
            alpha[r] = __expf(m_run[r] - mnew);
            m_run[r] = mnew;
            float sum = 0.f;
#pragma unroll
            for (int c = 0; c < 4; ++c) {
                float p = __expf(s[r][c] - mnew);
                s[r][c] = p;
                sum += p;
            }
#pragma unroll
            for (int off = 1; off < 16; off <<= 1)
                sum += __shfl_xor_sync(0xffffffffu, sum, off);
            l_run[r] = l_run[r] * alpha[r] + sum;
        }

        __syncthreads();  // all S reads of Ks complete before P overwrites it
        float* Ps = Ks;   // reuse K smem for P
#pragma unroll
        for (int r = 0; r < 4; ++r)
            *(float4*)(Ps + (ty * 4 + r) * 68 + tx * 4) =
                make_float4(s[r][0], s[r][1], s[r][2], s[r][3]);
        __syncthreads();

        // ---- O = O*alpha + P @ V ----
#pragma unroll
        for (int r = 0; r < 4; ++r)
#pragma unroll
            for (int c = 0; c < 8; ++c) o[r][c] *= alpha[r];

#pragma unroll 4
        for (int kk = 0; kk < 64; ++kk) {
            float p[4];
            p[0] = Ps[(ty * 4 + 0) * 68 + kk];
            p[1] = Ps[(ty * 4 + 1) * 68 + kk];
            p[2] = Ps[(ty * 4 + 2) * 68 + kk];
            p[3] = Ps[(ty * 4 + 3) * 68 + kk];
            float4 va = *(const float4*)(Vs + kk * 128 + tx * 4);
            float4 vb = *(const float4*)(Vs + kk * 128 + 64 + tx * 4);
            float vv[8] = {va.x, va.y, va.z, va.w, vb.x, vb.y, vb.z, vb.w};
#pragma unroll
            for (int r = 0; r < 4; ++r)
#pragma unroll
                for (int c = 0; c < 8; ++c)
                    o[r][c] = fmaf(p[r], vv[c], o[r][c]);
        }
    }

    // ---- normalize + write y in [B, T, H*hd] layout (head-major within D) ----
#pragma unroll
    for (int r = 0; r < 4; ++r) {
        float inv = 1.f / l_run[r];
        int t = q0 + ty * 4 + r;
        float* op = g_att + (size_t)(b * SEQ + t) * D_MODEL + h * HEAD_DIM;
        *(float4*)(op + tx * 4) =
            make_float4(o[r][0] * inv, o[r][1] * inv, o[r][2] * inv, o[r][3] * inv);
        *(float4*)(op + 64 + tx * 4) =
            make_float4(o[r][4] * inv, o[r][5] * inv, o[r][6] * inv, o[r][7] * inv);
    }
}

// ---------------------------------------------------------------------------
extern "C" void kernel_launch(void* const* d_in, const int* in_sizes, int n_in,
                              void* d_out, int out_size)
{
    (void)in_sizes; (void)n_in; (void)out_size;
    const float* x     = (const float*)d_in[0];
    // d_in[1] is the causal mask (tril) — structure known, not needed.
    const float* Wqkv  = (const float*)d_in[2];
    const float* bqkv  = (const float*)d_in[3];
    const float* Wproj = (const float*)d_in[4];
    const float* bproj = (const float*)d_in[5];
    float* out = (float*)d_out;

    void* qkv_p = nullptr;
    void* att_p = nullptr;
    cudaGetSymbolAddress(&qkv_p, g_qkv);
    cudaGetSymbolAddress(&att_p, g_att);
    float* qkv = (float*)qkv_p;
    float* att = (float*)att_p;

    const int SMEM_FLASH = (2 * 128 * 68 + 64 * 128) * 4;  // 102400 B
    cudaFuncSetAttribute(flash_attn_kernel,
                         cudaFuncAttributeMaxDynamicSharedMemorySize, SMEM_FLASH);

    dim3 blk(256);

    // 1) QKV projection: [4096,2048] @ [2048,6144] + bias
    sgemm_bias_kernel<<<dim3(3 * D_MODEL / 128, BATCH * SEQ / 128), blk>>>(
        x, Wqkv, bqkv, qkv, BATCH * SEQ, 3 * D_MODEL, D_MODEL);

    // 2) causal flash attention with fused RoPE
    flash_attn_kernel<<<dim3(SEQ / 64, BATCH * N_HEAD), blk, SMEM_FLASH>>>();

    // 3) output projection: [4096,2048] @ [2048,2048] + bias
    sgemm_bias_kernel<<<dim3(D_MODEL / 128, BATCH * SEQ / 128), blk>>>(
        att, Wproj, bproj, out, BATCH * SEQ, D_MODEL, D_MODEL);
}

// round 3
// speedup vs baseline: 1.4913x; 1.4913x over previous
#include <cuda_runtime.h>
#include <cuda_bf16.h>
#include <math.h>
#include <stdint.h>

#define D_MODEL 2048
#define N_HEAD  16
#define HEAD_DIM 128
#define BATCH   2
#define SEQ     2048

// ---------------------------------------------------------------------------
// Static scratch (no cudaMalloc anywhere)
// ---------------------------------------------------------------------------
static __device__ float g_qkv[(size_t)BATCH * SEQ * 3 * D_MODEL]; // 100 MB
static __device__ float g_att[(size_t)BATCH * SEQ * D_MODEL];     // 33 MB
static __device__ __nv_bfloat16 g_Ahi[(size_t)BATCH * SEQ * D_MODEL];
static __device__ __nv_bfloat16 g_Alo[(size_t)BATCH * SEQ * D_MODEL];
static __device__ __nv_bfloat16 g_Wqkv_hi[(size_t)3 * D_MODEL * D_MODEL]; // [N=6144][K=2048]
static __device__ __nv_bfloat16 g_Wqkv_lo[(size_t)3 * D_MODEL * D_MODEL];
static __device__ __nv_bfloat16 g_Wproj_hi[(size_t)D_MODEL * D_MODEL];    // [N=2048][K=2048]
static __device__ __nv_bfloat16 g_Wproj_lo[(size_t)D_MODEL * D_MODEL];

// ---------------------------------------------------------------------------
// PTX helpers (sm_80+ only: cp.async / ldmatrix / mma.sync — valid on sm_100)
// ---------------------------------------------------------------------------
__device__ __forceinline__ uint32_t smem_to_u32(const void* smem_ptr) {
    uint32_t addr;
    asm("{ .reg .u64 tmp; cvta.to.shared.u64 tmp, %1; cvt.u32.u64 %0, tmp; }"
        : "=r"(addr) : "l"(smem_ptr));
    return addr;
}

__device__ __forceinline__ void cp_async16(uint32_t smem_dst, const void* gmem_src) {
    asm volatile("cp.async.cg.shared.global.L2::128B [%0], [%1], 16;"
                 :: "r"(smem_dst), "l"(__cvta_generic_to_global(gmem_src)));
}
#define CP_ASYNC_COMMIT() asm volatile("cp.async.commit_group;" ::: "memory")
#define CP_ASYNC_WAIT_1() asm volatile("cp.async.wait_group 1;" ::: "memory")

__device__ __forceinline__ void ldsm4(uint32_t* r, uint32_t addr) {
    asm volatile("ldmatrix.sync.aligned.m8n8.x4.shared.b16 {%0,%1,%2,%3}, [%4];"
                 : "=r"(r[0]), "=r"(r[1]), "=r"(r[2]), "=r"(r[3]) : "r"(addr));
}

__device__ __forceinline__ void mma_bf16(float* c, const uint32_t* a,
                                         uint32_t b0, uint32_t b1) {
    asm volatile(
        "mma.sync.aligned.m16n8k16.row.col.f32.bf16.bf16.f32 "
        "{%0,%1,%2,%3}, {%4,%5,%6,%7}, {%8,%9}, {%0,%1,%2,%3};"
        : "+f"(c[0]), "+f"(c[1]), "+f"(c[2]), "+f"(c[3])
        : "r"(a[0]), "r"(a[1]), "r"(a[2]), "r"(a[3]), "r"(b0), "r"(b1));
}

// ---------------------------------------------------------------------------
// Elementwise split: fp32 -> (hi, lo) bf16 pair.  lo = x - float(hi).
// ---------------------------------------------------------------------------
__global__ void split_kernel(const float* __restrict__ X,
                             __nv_bfloat16* __restrict__ hi,
                             __nv_bfloat16* __restrict__ lo, int n4)
{
    int i = blockIdx.x * blockDim.x + threadIdx.x;
    if (i >= n4) return;
    float4 v = *(const float4*)(X + (size_t)i * 4);
    __nv_bfloat16 h[4], l[4];
    float vv[4] = {v.x, v.y, v.z, v.w};
#pragma unroll
    for (int j = 0; j < 4; ++j) {
        h[j] = __float2bfloat16(vv[j]);
        l[j] = __float2bfloat16(vv[j] - __bfloat162float(h[j]));
    }
    *(uint2*)(hi + (size_t)i * 4) = *(uint2*)h;
    *(uint2*)(lo + (size_t)i * 4) = *(uint2*)l;
}

// ---------------------------------------------------------------------------
// Transpose + split: W[K,N] fp32 -> Thi/Tlo [N,K] bf16 (K-major for MMA B).
// ---------------------------------------------------------------------------
__global__ __launch_bounds__(256) void transpose_split_kernel(
    const float* __restrict__ W,
    __nv_bfloat16* __restrict__ Thi, __nv_bfloat16* __restrict__ Tlo,
    int K, int N)
{
    __shared__ float tile[64][65];
    const int k0 = blockIdx.y * 64;
    const int n0 = blockIdx.x * 64;
    const int tid = threadIdx.x;

#pragma unroll
    for (int j = 0; j < 4; ++j) {
        int idx = tid + j * 256;       // 0..1023 -> 64 rows x 16 float4
        int r  = idx >> 4;
        int c4 = (idx & 15) * 4;
        float4 v = *(const float4*)(W + (size_t)(k0 + r) * N + n0 + c4);
        tile[r][c4 + 0] = v.x; tile[r][c4 + 1] = v.y;
        tile[r][c4 + 2] = v.z; tile[r][c4 + 3] = v.w;
    }
    __syncthreads();

    const int n  = tid >> 2;           // 0..63 output row (N index)
    const int ks = (tid & 3) * 16;     // 16 consecutive K per thread
    __nv_bfloat16 h[16], l[16];
#pragma unroll
    for (int j = 0; j < 16; ++j) {
        float v = tile[ks + j][n];
        h[j] = __float2bfloat16(v);
        l[j] = __float2bfloat16(v - __bfloat162float(h[j]));
    }
    size_t base = (size_t)(n0 + n) * K + k0 + ks;
    *(uint4*)(Thi + base)     = ((uint4*)h)[0];
    *(uint4*)(Thi + base + 8) = ((uint4*)h)[1];
    *(uint4*)(Tlo + base)     = ((uint4*)l)[0];
    *(uint4*)(Tlo + base + 8) = ((uint4*)l)[1];
}

// ---------------------------------------------------------------------------
// bf16x3 HMMA GEMM:  C[M,N] = A[M,K] @ B[N,K]^T + bias  (fp32 out)
// A = (Ahi, Alo) [M,K] bf16; B = (Bhi, Blo) [N,K] bf16 (K-major).
// BM=BN=128, BK=32. 256 threads = 8 warps in 2x4 grid, 64x32 warp tile.
// 3-stage cp.async pipeline. smem rows padded to 80 B (conflict-free ldmatrix).
// ---------------------------------------------------------------------------
#define GB_ROWB   80                        // bytes per 32-bf16 smem row (+8 pad)
#define GB_OP     (128 * GB_ROWB)           // 10240 B per operand tile
#define GB_STAGE  (4 * GB_OP)               // 40960 B (Ahi, Alo, Bhi, Blo)
#define GB_NSTAGE 3
#define GB_SMEM   (GB_NSTAGE * GB_STAGE)    // 122880 B

__device__ __forceinline__ void gemm_load_stage(
    uint32_t st,
    const __nv_bfloat16* __restrict__ Ahi, const __nv_bfloat16* __restrict__ Alo,
    const __nv_bfloat16* __restrict__ Bhi, const __nv_bfloat16* __restrict__ Blo,
    int bm, int bn, int k0, int K, int tid)
{
#pragma unroll
    for (int j = 0; j < 2; ++j) {
        int idx = tid + j * 256;            // 0..511
        int row = idx >> 2;                 // 0..127
        int c   = idx & 3;                  // 16B chunk within 64B row
        uint32_t off = (uint32_t)(row * GB_ROWB + c * 16);
        size_t ga = (size_t)(bm + row) * K + k0 + c * 8;
        size_t gb = (size_t)(bn + row) * K + k0 + c * 8;
        cp_async16(st + off,              Ahi + ga);
        cp_async16(st + GB_OP + off,      Alo + ga);
        cp_async16(st + 2 * GB_OP + off,  Bhi + gb);
        cp_async16(st + 3 * GB_OP + off,  Blo + gb);
    }
}

__global__ __launch_bounds__(256, 1) void gemm_bf16x3_kernel(
    const __nv_bfloat16* __restrict__ Ahi, const __nv_bfloat16* __restrict__ Alo,
    const __nv_bfloat16* __restrict__ Bhi, const __nv_bfloat16* __restrict__ Blo,
    const float* __restrict__ bias, float* __restrict__ C,
    int M, int N, int K)
{
    extern __shared__ __align__(128) char smem[];
    const uint32_t sbase = smem_to_u32(smem);
    const int tid  = threadIdx.x;
    const int lane = tid & 31;
    const int wid  = tid >> 5;
    const int wm   = wid >> 2;              // 0..1  (M direction, 64 rows)
    const int wn   = wid & 3;               // 0..3  (N direction, 32 cols)
    const int bm   = blockIdx.y * 128;
    const int bn   = blockIdx.x * 128;

    float acc[4][4][4];
#pragma unroll
    for (int mi = 0; mi < 4; ++mi)
#pragma unroll
        for (int ni = 0; ni < 4; ++ni)
#pragma unroll
            for (int r = 0; r < 4; ++r) acc[mi][ni][r] = 0.f;

    const int nk = K / 32;                  // 64

    gemm_load_stage(sbase,            Ahi, Alo, Bhi, Blo, bm, bn, 0,  K, tid);
    CP_ASYNC_COMMIT();
    gemm_load_stage(sbase + GB_STAGE, Ahi, Alo, Bhi, Blo, bm, bn, 32, K, tid);
    CP_ASYNC_COMMIT();

    const int lrowA = lane & 15, lcolA = lane >> 4;     // A ldmatrix lanes
    const int bg    = lane >> 3, blr  = lane & 7;       // B ldmatrix lanes

    for (int i = 0; i < nk; ++i) {
        const uint32_t st = sbase + (uint32_t)(i % GB_NSTAGE) * GB_STAGE;
        CP_ASYNC_WAIT_1();
        __syncthreads();

        const uint32_t aHi = st;
        const uint32_t aLo = st + GB_OP;
        const uint32_t bHi = st + 2 * GB_OP;
        const uint32_t bLo = st + 3 * GB_OP;

#pragma unroll
        for (int ks = 0; ks < 2; ++ks) {
            uint32_t ah[4][4], al[4][4], bh[2][4], bl[2][4];
#pragma unroll
            for (int mi = 0; mi < 4; ++mi) {
                uint32_t off = (uint32_t)((wm * 64 + mi * 16 + lrowA) * GB_ROWB
                                          + (ks * 2 + lcolA) * 16);
                ldsm4(ah[mi], aHi + off);
                ldsm4(al[mi], aLo + off);
            }
#pragma unroll
            for (int np = 0; np < 2; ++np) {
                uint32_t off = (uint32_t)((wn * 32 + np * 16 + (bg >> 1) * 8 + blr) * GB_ROWB
                                          + (ks * 2 + (bg & 1)) * 16);
                ldsm4(bh[np], bHi + off);
                ldsm4(bl[np], bLo + off);
            }
#pragma unroll
            for (int mi = 0; mi < 4; ++mi)
#pragma unroll
                for (int ni = 0; ni < 4; ++ni) {
                    int np = ni >> 1, pr = (ni & 1) * 2;
                    mma_bf16(acc[mi][ni], ah[mi], bh[np][pr], bh[np][pr + 1]);
                    mma_bf16(acc[mi][ni], ah[mi], bl[np][pr], bl[np][pr + 1]);
                    mma_bf16(acc[mi][ni], al[mi], bh[np][pr], bh[np][pr + 1]);
                }
        }

        __syncthreads();          // all warps done reading before slot reuse
        if (i + 2 < nk) {
            gemm_load_stage(sbase + (uint32_t)((i + 2) % GB_NSTAGE) * GB_STAGE,
                            Ahi, Alo, Bhi, Blo, bm, bn, (i + 2) * 32, K, tid);
        }
        CP_ASYNC_COMMIT();
    }

    // epilogue: bias + fp32 store
    const int gid = lane >> 2, tig = lane & 3;
#pragma unroll
    for (int mi = 0; mi < 4; ++mi)
#pragma unroll
        for (int ni = 0; ni < 4; ++ni) {
            int row = bm + wm * 64 + mi * 16 + gid;
            int col = bn + wn * 32 + ni * 8 + tig * 2;
            float2 bv = *(const float2*)(bias + col);
            float2 v0 = make_float2(acc[mi][ni][0] + bv.x, acc[mi][ni][1] + bv.y);
            float2 v1 = make_float2(acc[mi][ni][2] + bv.x, acc[mi][ni][3] + bv.y);
            *(float2*)(C + (size_t)row * N + col)       = v0;
            *(float2*)(C + (size_t)(row + 8) * N + col) = v1;
        }
}

// ---------------------------------------------------------------------------
// Flash attention with on-the-fly RoPE (fp32, validated in R1).
// ---------------------------------------------------------------------------
__global__ __launch_bounds__(256, 2) void flash_attn_kernel()
{
    extern __shared__ float sm[];
    float* Qs = sm;                 // 128*68
    float* Ks = sm + 128 * 68;      // 128*68, later reused as P[64][68]
    float* Vs = sm + 2 * 128 * 68;  // 64*128

    const int tid = threadIdx.x;
    const int tx  = tid & 15;
    const int ty  = tid >> 4;
    const int qt  = blockIdx.x;
    const int b   = blockIdx.y >> 4;
    const int h   = blockIdx.y & 15;
    const int q0  = qt << 6;

    const float RATE_C = 0.14391156831212787f; // ln(10000)/64
    const float SCALE  = 0.08838834764831845f; // 1/sqrt(128)

    for (int i = tid; i < 64 * 64; i += 256) {
        int tl = i >> 6, j = i & 63;
        int t = q0 + tl;
        const float* g = g_qkv + (size_t)(b * SEQ + t) * (3 * D_MODEL) + h * HEAD_DIM;
        float x1 = g[j], x2 = g[j + 64];
        float rate = expf(-RATE_C * (float)j);
        float sv, cv;
        sincosf((float)t * rate, &sv, &cv);
        Qs[j * 68 + tl]        = x1 * cv - x2 * sv;
        Qs[(j + 64) * 68 + tl] = x1 * sv + x2 * cv;
    }

    float m_run[4], l_run[4], o[4][8];
#pragma unroll
    for (int r = 0; r < 4; ++r) {
        m_run[r] = -1e30f;
        l_run[r] = 0.f;
#pragma unroll
        for (int c = 0; c < 8; ++c) o[r][c] = 0.f;
    }

    for (int kt = 0; kt <= qt; ++kt) {
        int k0 = kt << 6;
        __syncthreads();

        for (int i = tid; i < 64 * 64; i += 256) {
            int tl = i >> 6, j = i & 63;
            int t = k0 + tl;
            const float* g = g_qkv + (size_t)(b * SEQ + t) * (3 * D_MODEL) + D_MODEL + h * HEAD_DIM;
            float x1 = g[j], x2 = g[j + 64];
            float rate = expf(-RATE_C * (float)j);
            float sv, cv;
            sincosf((float)t * rate, &sv, &cv);
            Ks[j * 68 + tl]        = x1 * cv - x2 * sv;
            Ks[(j + 64) * 68 + tl] = x1 * sv + x2 * cv;
        }
        for (int i = tid * 4; i < 64 * 128; i += 1024) {
            int tl = i >> 7, dd = i & 127;
            *(float4*)(Vs + tl * 128 + dd) =
                *(const float4*)(g_qkv + (size_t)(b * SEQ + k0 + tl) * (3 * D_MODEL)
                                 + 2 * D_MODEL + h * HEAD_DIM + dd);
        }
        __syncthreads();

        float s[4][4];
#pragma unroll
        for (int r = 0; r < 4; ++r)
#pragma unroll
            for (int c = 0; c < 4; ++c) s[r][c] = 0.f;

#pragma unroll 8
        for (int kk = 0; kk < 128; ++kk) {
            float4 q4 = *(const float4*)(Qs + kk * 68 + ty * 4);
            float4 k4 = *(const float4*)(Ks + kk * 68 + tx * 4);
            float qv[4] = {q4.x, q4.y, q4.z, q4.w};
            float kv[4] = {k4.x, k4.y, k4.z, k4.w};
#pragma unroll
            for (int r = 0; r < 4; ++r)
#pragma unroll
                for (int c = 0; c < 4; ++c)
                    s[r][c] = fmaf(qv[r], kv[c], s[r][c]);
        }

        bool diag = (kt == qt);
#pragma unroll
        for (int r = 0; r < 4; ++r)
#pragma unroll
            for (int c = 0; c < 4; ++c) {
                float v = s[r][c] * SCALE;
                if (diag && (tx * 4 + c) > (ty * 4 + r)) v = -1e30f;
                s[r][c] = v;
            }

        float alpha[4];
#pragma unroll
        for (int r = 0; r < 4; ++r) {
            float v = fmaxf(fmaxf(s[r][0], s[r][1]), fmaxf(s[r][2], s[r][3]));
#pragma unroll
            for (int off = 1; off < 16; off <<= 1)
                v = fmaxf(v, __shfl_xor_sync(0xffffffffu, v, off));
            float mnew = fmaxf(m_run[r], v);
            alpha[r] = __expf(m_run[r] - mnew);
            m_run[r] = mnew;
            float sum = 0.f;
#pragma unroll
            for (int c = 0; c < 4; ++c) {
                float p = __expf(s[r][c] - mnew);
                s[r][c] = p;
                sum += p;
            }
#pragma unroll
            for (int off = 1; off < 16; off <<= 1)
                sum += __shfl_xor_sync(0xffffffffu, sum, off);
            l_run[r] = l_run[r] * alpha[r] + sum;
        }

        __syncthreads();
        float* Ps = Ks;
#pragma unroll
        for (int r = 0; r < 4; ++r)
            *(float4*)(Ps + (ty * 4 + r) * 68 + tx * 4) =
                make_float4(s[r][0], s[r][1], s[r][2], s[r][3]);
        __syncthreads();

#pragma unroll
        for (int r = 0; r < 4; ++r)
#pragma unroll
            for (int c = 0; c < 8; ++c) o[r][c] *= alpha[r];

#pragma unroll 4
        for (int kk = 0; kk < 64; ++kk) {
            float p[4];
            p[0] = Ps[(ty * 4 + 0) * 68 + kk];
            p[1] = Ps[(ty * 4 + 1) * 68 + kk];
            p[2] = Ps[(ty * 4 + 2) * 68 + kk];
            p[3] = Ps[(ty * 4 + 3) * 68 + kk];
            float4 va = *(const float4*)(Vs + kk * 128 + tx * 4);
            float4 vb = *(const float4*)(Vs + kk * 128 + 64 + tx * 4);
            float vv[8] = {va.x, va.y, va.z, va.w, vb.x, vb.y, vb.z, vb.w};
#pragma unroll
            for (int r = 0; r < 4; ++r)
#pragma unroll
                for (int c = 0; c < 8; ++c)
                    o[r][c] = fmaf(p[r], vv[c], o[r][c]);
        }
    }

#pragma unroll
    for (int r = 0; r < 4; ++r) {
        float inv = 1.f / l_run[r];
        int t = q0 + ty * 4 + r;
        float* op = g_att + (size_t)(b * SEQ + t) * D_MODEL + h * HEAD_DIM;
        *(float4*)(op + tx * 4) =
            make_float4(o[r][0] * inv, o[r][1] * inv, o[r][2] * inv, o[r][3] * inv);
        *(float4*)(op + 64 + tx * 4) =
            make_float4(o[r][4] * inv, o[r][5] * inv, o[r][6] * inv, o[r][7] * inv);
    }
}

// ---------------------------------------------------------------------------
extern "C" void kernel_launch(void* const* d_in, const int* in_sizes, int n_in,
                              void* d_out, int out_size)
{
    (void)in_sizes; (void)n_in; (void)out_size;
    const float* x     = (const float*)d_in[0];
    const float* Wqkv  = (const float*)d_in[2];
    const float* bqkv  = (const float*)d_in[3];
    const float* Wproj = (const float*)d_in[4];
    const float* bproj = (const float*)d_in[5];
    float* out = (float*)d_out;

    void *qkv_p, *att_p, *ahi_p, *alo_p, *wq_hi_p, *wq_lo_p, *wp_hi_p, *wp_lo_p;
    cudaGetSymbolAddress(&qkv_p, g_qkv);
    cudaGetSymbolAddress(&att_p, g_att);
    cudaGetSymbolAddress(&ahi_p, g_Ahi);
    cudaGetSymbolAddress(&alo_p, g_Alo);
    cudaGetSymbolAddress(&wq_hi_p, g_Wqkv_hi);
    cudaGetSymbolAddress(&wq_lo_p, g_Wqkv_lo);
    cudaGetSymbolAddress(&wp_hi_p, g_Wproj_hi);
    cudaGetSymbolAddress(&wp_lo_p, g_Wproj_lo);
    float* qkv = (float*)qkv_p;
    float* att = (float*)att_p;
    __nv_bfloat16* Ahi = (__nv_bfloat16*)ahi_p;
    __nv_bfloat16* Alo = (__nv_bfloat16*)alo_p;
    __nv_bfloat16* WqH = (__nv_bfloat16*)wq_hi_p;
    __nv_bfloat16* WqL = (__nv_bfloat16*)wq_lo_p;
    __nv_bfloat16* WpH = (__nv_bfloat16*)wp_hi_p;
    __nv_bfloat16* WpL = (__nv_bfloat16*)wp_lo_p;

    const int SMEM_FLASH = (2 * 128 * 68 + 64 * 128) * 4;  // 102400 B
    cudaFuncSetAttribute(flash_attn_kernel,
                         cudaFuncAttributeMaxDynamicSharedMemorySize, SMEM_FLASH);
    cudaFuncSetAttribute(gemm_bf16x3_kernel,
                         cudaFuncAttributeMaxDynamicSharedMemorySize, GB_SMEM);

    const int M = BATCH * SEQ;               // 4096
    const int nelem = M * D_MODEL;           // 8,388,608

    // 1) split activations x -> (Ahi, Alo)
    split_kernel<<<(nelem / 4 + 255) / 256, 256>>>(x, Ahi, Alo, nelem / 4);

    // 2) weight transpose + split (W[K,N] -> [N,K] bf16 hi/lo)
    transpose_split_kernel<<<dim3(3 * D_MODEL / 64, D_MODEL / 64), 256>>>(
        Wqkv, WqH, WqL, D_MODEL, 3 * D_MODEL);
    transpose_split_kernel<<<dim3(D_MODEL / 64, D_MODEL / 64), 256>>>(
        Wproj, WpH, WpL, D_MODEL, D_MODEL);

    // 3) QKV projection on tensor cores: [4096,2048] x [2048,6144] + bias
    gemm_bf16x3_kernel<<<dim3(3 * D_MODEL / 128, M / 128), 256, GB_SMEM>>>(
        Ahi, Alo, WqH, WqL, bqkv, qkv, M, 3 * D_MODEL, D_MODEL);

    // 4) causal flash attention with fused RoPE (fp32)
    flash_attn_kernel<<<dim3(SEQ / 64, BATCH * N_HEAD), 256, SMEM_FLASH>>>();

    // 5) split attention output
    split_kernel<<<(nelem / 4 + 255) / 256, 256>>>(att, Ahi, Alo, nelem / 4);

    // 6) output projection on tensor cores: [4096,2048] x [2048,2048] + bias
    gemm_bf16x3_kernel<<<dim3(D_MODEL / 128, M / 128), 256, GB_SMEM>>>(
        Ahi, Alo, WpH, WpL, bproj, out, M, D_MODEL, D_MODEL);
}

// round 4
// speedup vs baseline: 2.2780x; 1.5275x over previous
#include <cuda_runtime.h>
#include <cuda_bf16.h>
#include <math.h>
#include <stdint.h>

#define D_MODEL 2048
#define N_HEAD  16
#define HEAD_DIM 128
#define BATCH   2
#define SEQ     2048

// ---------------------------------------------------------------------------
// Static scratch (no cudaMalloc anywhere)
// ---------------------------------------------------------------------------
static __device__ float g_qkv[(size_t)BATCH * SEQ * 3 * D_MODEL]; // 100 MB
static __device__ float g_rope[(size_t)SEQ * 128];                // cos/sin table
static __device__ __nv_bfloat16 g_Ahi[(size_t)BATCH * SEQ * D_MODEL];
static __device__ __nv_bfloat16 g_Alo[(size_t)BATCH * SEQ * D_MODEL];
static __device__ __nv_bfloat16 g_Wqkv_hi[(size_t)3 * D_MODEL * D_MODEL]; // [N][K]
static __device__ __nv_bfloat16 g_Wqkv_lo[(size_t)3 * D_MODEL * D_MODEL];
static __device__ __nv_bfloat16 g_Wproj_hi[(size_t)D_MODEL * D_MODEL];
static __device__ __nv_bfloat16 g_Wproj_lo[(size_t)D_MODEL * D_MODEL];

// ---------------------------------------------------------------------------
// PTX helpers (sm_80+ subset: cp.async / ldmatrix / mma.sync)
// ---------------------------------------------------------------------------
__device__ __forceinline__ uint32_t smem_to_u32(const void* smem_ptr) {
    uint32_t addr;
    asm("{ .reg .u64 tmp; cvta.to.shared.u64 tmp, %1; cvt.u32.u64 %0, tmp; }"
        : "=r"(addr) : "l"(smem_ptr));
    return addr;
}

__device__ __forceinline__ void cp_async16(uint32_t smem_dst, const void* gmem_src) {
    asm volatile("cp.async.cg.shared.global.L2::128B [%0], [%1], 16;"
                 :: "r"(smem_dst), "l"(__cvta_generic_to_global(gmem_src)));
}
#define CP_ASYNC_COMMIT() asm volatile("cp.async.commit_group;" ::: "memory")
#define CP_ASYNC_WAIT_1() asm volatile("cp.async.wait_group 1;" ::: "memory")
#define CP_ASYNC_WAIT_0() asm volatile("cp.async.wait_group 0;" ::: "memory")

__device__ __forceinline__ void ldsm4(uint32_t* r, uint32_t addr) {
    asm volatile("ldmatrix.sync.aligned.m8n8.x4.shared.b16 {%0,%1,%2,%3}, [%4];"
                 : "=r"(r[0]), "=r"(r[1]), "=r"(r[2]), "=r"(r[3]) : "r"(addr));
}
__device__ __forceinline__ void ldsm4t(uint32_t* r, uint32_t addr) {
    asm volatile("ldmatrix.sync.aligned.m8n8.x4.trans.shared.b16 {%0,%1,%2,%3}, [%4];"
                 : "=r"(r[0]), "=r"(r[1]), "=r"(r[2]), "=r"(r[3]) : "r"(addr));
}

__device__ __forceinline__ void mma_bf16(float* c, const uint32_t* a,
                                         uint32_t b0, uint32_t b1) {
    asm volatile(
        "mma.sync.aligned.m16n8k16.row.col.f32.bf16.bf16.f32 "
        "{%0,%1,%2,%3}, {%4,%5,%6,%7}, {%8,%9}, {%0,%1,%2,%3};"
        : "+f"(c[0]), "+f"(c[1]), "+f"(c[2]), "+f"(c[3])
        : "r"(a[0]), "r"(a[1]), "r"(a[2]), "r"(a[3]), "r"(b0), "r"(b1));
}

// pack (s0 -> low bf16, s1 -> high bf16) into hi; residuals into lo.
__device__ __forceinline__ void split2(float s0, float s1, uint32_t& hi, uint32_t& lo) {
    asm("cvt.rn.bf16x2.f32 %0, %1, %2;" : "=r"(hi) : "f"(s1), "f"(s0));
    __nv_bfloat162 hv = *reinterpret_cast<__nv_bfloat162*>(&hi);
    float r0 = s0 - __bfloat162float(hv.x);
    float r1 = s1 - __bfloat162float(hv.y);
    asm("cvt.rn.bf16x2.f32 %0, %1, %2;" : "=r"(lo) : "f"(r1), "f"(r0));
}

// ---------------------------------------------------------------------------
// RoPE table: g_rope[t*128 + j] = cos(t*rate_j), [t*128+64+j] = sin(t*rate_j)
// ---------------------------------------------------------------------------
__global__ void rope_table_kernel()
{
    const float RATE_C = 0.14391156831212787f; // ln(10000)/64
    int i = blockIdx.x * blockDim.x + threadIdx.x;  // t*64 + j
    int t = i >> 6, j = i & 63;
    float rate = expf(-RATE_C * (float)j);
    float sv, cv;
    sincosf((float)t * rate, &sv, &cv);
    g_rope[t * 128 + j]      = cv;
    g_rope[t * 128 + 64 + j] = sv;
}

// ---------------------------------------------------------------------------
// Elementwise split: fp32 -> (hi, lo) bf16 pair.
// ---------------------------------------------------------------------------
__global__ void split_kernel(const float* __restrict__ X,
                             __nv_bfloat16* __restrict__ hi,
                             __nv_bfloat16* __restrict__ lo, int n4)
{
    int i = blockIdx.x * blockDim.x + threadIdx.x;
    if (i >= n4) return;
    float4 v = *(const float4*)(X + (size_t)i * 4);
    __nv_bfloat16 h[4], l[4];
    float vv[4] = {v.x, v.y, v.z, v.w};
#pragma unroll
    for (int j = 0; j < 4; ++j) {
        h[j] = __float2bfloat16(vv[j]);
        l[j] = __float2bfloat16(vv[j] - __bfloat162float(h[j]));
    }
    *(uint2*)(hi + (size_t)i * 4) = *(uint2*)h;
    *(uint2*)(lo + (size_t)i * 4) = *(uint2*)l;
}

// ---------------------------------------------------------------------------
// Transpose + split: W[K,N] fp32 -> Thi/Tlo [N,K] bf16 (K-major for MMA B).
// ---------------------------------------------------------------------------
__global__ __launch_bounds__(256) void transpose_split_kernel(
    const float* __restrict__ W,
    __nv_bfloat16* __restrict__ Thi, __nv_bfloat16* __restrict__ Tlo,
    int K, int N)
{
    __shared__ float tile[64][65];
    const int k0 = blockIdx.y * 64;
    const int n0 = blockIdx.x * 64;
    const int tid = threadIdx.x;

#pragma unroll
    for (int j = 0; j < 4; ++j) {
        int idx = tid + j * 256;
        int r  = idx >> 4;
        int c4 = (idx & 15) * 4;
        float4 v = *(const float4*)(W + (size_t)(k0 + r) * N + n0 + c4);
        tile[r][c4 + 0] = v.x; tile[r][c4 + 1] = v.y;
        tile[r][c4 + 2] = v.z; tile[r][c4 + 3] = v.w;
    }
    __syncthreads();

    const int n  = tid >> 2;
    const int ks = (tid & 3) * 16;
    __nv_bfloat16 h[16], l[16];
#pragma unroll
    for (int j = 0; j < 16; ++j) {
        float v = tile[ks + j][n];
        h[j] = __float2bfloat16(v);
        l[j] = __float2bfloat16(v - __bfloat162float(h[j]));
    }
    size_t base = (size_t)(n0 + n) * K + k0 + ks;
    *(uint4*)(Thi + base)     = ((uint4*)h)[0];
    *(uint4*)(Thi + base + 8) = ((uint4*)h)[1];
    *(uint4*)(Tlo + base)     = ((uint4*)l)[0];
    *(uint4*)(Tlo + base + 8) = ((uint4*)l)[1];
}

// ---------------------------------------------------------------------------
// bf16x3 HMMA GEMM:  C[M,N] = A[M,K] @ B[N,K]^T + bias  (fp32 out)
// BM=BN=128, BK=32. 256 threads, 2x4 warp grid, 64x32 warp tile.
// 2-stage cp.async pipeline -> 2 CTAs/SM.
// ---------------------------------------------------------------------------
#define GB_ROWB   80
#define GB_OP     (128 * GB_ROWB)
#define GB_STAGE  (4 * GB_OP)               // 40960 B
#define GB_NSTAGE 2
#define GB_SMEM   (GB_NSTAGE * GB_STAGE)    // 81920 B

__device__ __forceinline__ void gemm_load_stage(
    uint32_t st,
    const __nv_bfloat16* __restrict__ Ahi, const __nv_bfloat16* __restrict__ Alo,
    const __nv_bfloat16* __restrict__ Bhi, const __nv_bfloat16* __restrict__ Blo,
    int bm, int bn, int k0, int K, int tid)
{
#pragma unroll
    for (int j = 0; j < 2; ++j) {
        int idx = tid + j * 256;
        int row = idx >> 2;
        int c   = idx & 3;
        uint32_t off = (uint32_t)(row * GB_ROWB + c * 16);
        size_t ga = (size_t)(bm + row) * K + k0 + c * 8;
        size_t gb = (size_t)(bn + row) * K + k0 + c * 8;
        cp_async16(st + off,              Ahi + ga);
        cp_async16(st + GB_OP + off,      Alo + ga);
        cp_async16(st + 2 * GB_OP + off,  Bhi + gb);
        cp_async16(st + 3 * GB_OP + off,  Blo + gb);
    }
}

__global__ __launch_bounds__(256, 2) void gemm_bf16x3_kernel(
    const __nv_bfloat16* __restrict__ Ahi, const __nv_bfloat16* __restrict__ Alo,
    const __nv_bfloat16* __restrict__ Bhi, const __nv_bfloat16* __restrict__ Blo,
    const float* __restrict__ bias, float* __restrict__ C,
    int M, int N, int K)
{
    extern __shared__ __align__(128) char smem[];
    const uint32_t sbase = smem_to_u32(smem);
    const int tid  = threadIdx.x;
    const int lane = tid & 31;
    const int wid  = tid >> 5;
    const int wm   = wid >> 2;
    const int wn   = wid & 3;
    const int bm   = blockIdx.y * 128;
    const int bn   = blockIdx.x * 128;

    float acc[4][4][4];
#pragma unroll
    for (int mi = 0; mi < 4; ++mi)
#pragma unroll
        for (int ni = 0; ni < 4; ++ni)
#pragma unroll
            for (int r = 0; r < 4; ++r) acc[mi][ni][r] = 0.f;

    const int nk = K / 32;

    gemm_load_stage(sbase,            Ahi, Alo, Bhi, Blo, bm, bn, 0,  K, tid);
    CP_ASYNC_COMMIT();
    gemm_load_stage(sbase + GB_STAGE, Ahi, Alo, Bhi, Blo, bm, bn, 32, K, tid);
    CP_ASYNC_COMMIT();

    const int lrowA = lane & 15, lcolA = lane >> 4;
    const int bg    = lane >> 3, blr  = lane & 7;

    for (int i = 0; i < nk; ++i) {
        const uint32_t st = sbase + (uint32_t)(i % GB_NSTAGE) * GB_STAGE;
        CP_ASYNC_WAIT_1();
        __syncthreads();

        const uint32_t aHi = st;
        const uint32_t aLo = st + GB_OP;
        const uint32_t bHi = st + 2 * GB_OP;
        const uint32_t bLo = st + 3 * GB_OP;

#pragma unroll
        for (int ks = 0; ks < 2; ++ks) {
            uint32_t ah[4][4], al[4][4], bh[2][4], bl[2][4];
#pragma unroll
            for (int mi = 0; mi < 4; ++mi) {
                uint32_t off = (uint32_t)((wm * 64 + mi * 16 + lrowA) * GB_ROWB
                                          + (ks * 2 + lcolA) * 16);
                ldsm4(ah[mi], aHi + off);
                ldsm4(al[mi], aLo + off);
            }
#pragma unroll
            for (int np = 0; np < 2; ++np) {
                uint32_t off = (uint32_t)((wn * 32 + np * 16 + (bg >> 1) * 8 + blr) * GB_ROWB
                                          + (ks * 2 + (bg & 1)) * 16);
                ldsm4(bh[np], bHi + off);
                ldsm4(bl[np], bLo + off);
            }
#pragma unroll
            for (int mi = 0; mi < 4; ++mi)
#pragma unroll
                for (int ni = 0; ni < 4; ++ni) {
                    int np = ni >> 1, pr = (ni & 1) * 2;
                    mma_bf16(acc[mi][ni], ah[mi], bh[np][pr], bh[np][pr + 1]);
                    mma_bf16(acc[mi][ni], ah[mi], bl[np][pr], bl[np][pr + 1]);
                    mma_bf16(acc[mi][ni], al[mi], bh[np][pr], bh[np][pr + 1]);
                }
        }

        __syncthreads();
        if (i + 2 < nk) {
            gemm_load_stage(sbase + (uint32_t)((i + 2) % GB_NSTAGE) * GB_STAGE,
                            Ahi, Alo, Bhi, Blo, bm, bn, (i + 2) * 32, K, tid);
        }
        CP_ASYNC_COMMIT();
    }

    const int gid = lane >> 2, tig = lane & 3;
#pragma unroll
    for (int mi = 0; mi < 4; ++mi)
#pragma unroll
        for (int ni = 0; ni < 4; ++ni) {
            int row = bm + wm * 64 + mi * 16 + gid;
            int col = bn + wn * 32 + ni * 8 + tig * 2;
            float2 bv = *(const float2*)(bias + col);
            float2 v0 = make_float2(acc[mi][ni][0] + bv.x, acc[mi][ni][1] + bv.y);
            float2 v1 = make_float2(acc[mi][ni][2] + bv.x, acc[mi][ni][3] + bv.y);
            *(float2*)(C + (size_t)row * N + col)       = v0;
            *(float2*)(C + (size_t)(row + 8) * N + col) = v1;
        }
}

// ---------------------------------------------------------------------------
// MMA flash attention, bf16x3 for QK^T and PV. 128-row Q tiles, 64-col K tiles.
// 256 threads = 8 warps; warp w owns rows w*16..w*16+15 and the FULL K-tile.
// RoPE from g_rope table; scale folded into Q. Output -> g_Ahi/g_Alo directly.
// ---------------------------------------------------------------------------
#define FA_TQ 128
#define FA_TK 64
#define QK_STRIDE 136                 // bf16 per smem row (128 + 8 pad)
#define STG_STRIDE 132                // floats per stage row (128 + 4 pad)
#define FA_QHI  0
#define FA_QLO  34816
#define FA_KHI  69632
#define FA_KLO  87040
#define FA_VHI  104448
#define FA_VLO  121856
#define FA_STGK 139264
#define FA_STGV 173056
#define FA_SMEM 206848

__global__ __launch_bounds__(256, 1) void flash_attn_mma_kernel()
{
    extern __shared__ __align__(128) char sm[];
    const uint32_t sbase = smem_to_u32(sm);
    __nv_bfloat16* qhi = (__nv_bfloat16*)(sm + FA_QHI);
    __nv_bfloat16* qlo = (__nv_bfloat16*)(sm + FA_QLO);
    __nv_bfloat16* khi = (__nv_bfloat16*)(sm + FA_KHI);
    __nv_bfloat16* klo = (__nv_bfloat16*)(sm + FA_KLO);
    __nv_bfloat16* vhi = (__nv_bfloat16*)(sm + FA_VHI);
    __nv_bfloat16* vlo = (__nv_bfloat16*)(sm + FA_VLO);
    float* stgK = (float*)(sm + FA_STGK);
    float* stgV = (float*)(sm + FA_STGV);

    const int tid  = threadIdx.x;
    const int lane = tid & 31;
    const int wid  = tid >> 5;
    const int qt   = (gridDim.x - 1) - blockIdx.x;   // heavy tiles first
    const int q0   = qt * FA_TQ;
    const int b    = blockIdx.y >> 4;
    const int h    = blockIdx.y & 15;
    const float SCALE = 0.08838834764831845f;        // 1/sqrt(128)

    // ---- Q tile: load fp32, rope, scale, split -> smem ----
    for (int i = tid; i < FA_TQ * 64; i += 256) {
        int tl = i >> 6, j = i & 63;
        int t = q0 + tl;
        const float* g = g_qkv + (size_t)(b * SEQ + t) * (3 * D_MODEL) + h * HEAD_DIM;
        float x1 = g[j], x2 = g[j + 64];
        float cv = g_rope[t * 128 + j], sv = g_rope[t * 128 + 64 + j];
        float y1 = (x1 * cv - x2 * sv) * SCALE;
        float y2 = (x1 * sv + x2 * cv) * SCALE;
        __nv_bfloat16 h1 = __float2bfloat16(y1);
        __nv_bfloat16 h2 = __float2bfloat16(y2);
        qhi[tl * QK_STRIDE + j]      = h1;
        qhi[tl * QK_STRIDE + j + 64] = h2;
        qlo[tl * QK_STRIDE + j]      = __float2bfloat16(y1 - __bfloat162float(h1));
        qlo[tl * QK_STRIDE + j + 64] = __float2bfloat16(y2 - __bfloat162float(h2));
    }

    float oacc[16][4];
#pragma unroll
    for (int ni = 0; ni < 16; ++ni)
#pragma unroll
        for (int r = 0; r < 4; ++r) oacc[ni][r] = 0.f;
    float m0 = -1e30f, m1 = -1e30f, l0 = 0.f, l1 = 0.f;

    const int ktmax = 2 * qt + 1;
    const int gid = lane >> 2, tig = lane & 3;
    const int lrowA = lane & 15, lcolA = lane >> 4;
    const int bg = lane >> 3, blr = lane & 7;
    const int wrow_lo = q0 + wid * 16;               // warp's lowest q row

    // prologue stage load (KV tile 0)
    {
        const int k0 = 0;
        for (int i = tid; i < FA_TK * 32; i += 256) {
            int tl = i >> 5, c = i & 31;
            const float* gk = g_qkv + (size_t)(b * SEQ + k0 + tl) * (3 * D_MODEL)
                              + D_MODEL + h * HEAD_DIM + c * 4;
            cp_async16(sbase + FA_STGK + (uint32_t)(tl * STG_STRIDE + c * 4) * 4, gk);
            cp_async16(sbase + FA_STGV + (uint32_t)(tl * STG_STRIDE + c * 4) * 4, gk + D_MODEL);
        }
        CP_ASYNC_COMMIT();
    }

    for (int kt = 0; kt <= ktmax; ++kt) {
        const int k0 = kt * FA_TK;
        CP_ASYNC_WAIT_0();
        __syncthreads();     // stage ready; all warps done with prev MMA reads

        // ---- convert K (rope, no scale) + V (split) from stage -> bf16 smem ----
        for (int i = tid; i < FA_TK * 64; i += 256) {
            int tl = i >> 6, j = i & 63;
            int t = k0 + tl;
            float x1 = stgK[tl * STG_STRIDE + j], x2 = stgK[tl * STG_STRIDE + j + 64];
            float cv = g_rope[t * 128 + j], sv = g_rope[t * 128 + 64 + j];
            float y1 = x1 * cv - x2 * sv;
            float y2 = x1 * sv + x2 * cv;
            __nv_bfloat16 h1 = __float2bfloat16(y1);
            __nv_bfloat16 h2 = __float2bfloat16(y2);
            khi[tl * QK_STRIDE + j]      = h1;
            khi[tl * QK_STRIDE + j + 64] = h2;
            klo[tl * QK_STRIDE + j]      = __float2bfloat16(y1 - __bfloat162float(h1));
            klo[tl * QK_STRIDE + j + 64] = __float2bfloat16(y2 - __bfloat162float(h2));
        }
        for (int i = tid; i < FA_TK * 128; i += 256) {
            int tl = i >> 7, dd = i & 127;
            float v = stgV[tl * STG_STRIDE + dd];
            __nv_bfloat16 hv = __float2bfloat16(v);
            vhi[tl * QK_STRIDE + dd] = hv;
            vlo[tl * QK_STRIDE + dd] = __float2bfloat16(v - __bfloat162float(hv));
        }
        __syncthreads();     // bf16 tiles ready; stage free for next prefetch

        if (kt < ktmax) {    // prefetch next KV tile (overlaps MMA below)
            const int kn = (kt + 1) * FA_TK;
            for (int i = tid; i < FA_TK * 32; i += 256) {
                int tl = i >> 5, c = i & 31;
                const float* gk = g_qkv + (size_t)(b * SEQ + kn + tl) * (3 * D_MODEL)
                                  + D_MODEL + h * HEAD_DIM + c * 4;
                cp_async16(sbase + FA_STGK + (uint32_t)(tl * STG_STRIDE + c * 4) * 4, gk);
                cp_async16(sbase + FA_STGV + (uint32_t)(tl * STG_STRIDE + c * 4) * 4, gk + D_MODEL);
            }
        }
        CP_ASYNC_COMMIT();

        // warp-level skip: this warp's rows entirely masked by this K tile
        if (k0 > wrow_lo + 15) continue;

        // ---- S = Q @ K^T (warp: 16 rows x 64 cols), bf16x3 ----
        float sacc[8][4];
#pragma unroll
        for (int ni = 0; ni < 8; ++ni)
#pragma unroll
            for (int r = 0; r < 4; ++r) sacc[ni][r] = 0.f;

#pragma unroll
        for (int ks = 0; ks < 8; ++ks) {
            uint32_t qh[4], ql[4];
            uint32_t qoff = (uint32_t)((wid * 16 + lrowA) * (QK_STRIDE * 2)
                                       + (ks * 16 + lcolA * 8) * 2);
            ldsm4(qh, sbase + FA_QHI + qoff);
            ldsm4(ql, sbase + FA_QLO + qoff);
            uint32_t kh[4][4], kl[4][4];
#pragma unroll
            for (int np = 0; np < 4; ++np) {
                uint32_t koff = (uint32_t)((np * 16 + (bg >> 1) * 8 + blr) * (QK_STRIDE * 2)
                                           + (ks * 16 + (bg & 1) * 8) * 2);
                ldsm4(kh[np], sbase + FA_KHI + koff);
                ldsm4(kl[np], sbase + FA_KLO + koff);
            }
#pragma unroll
            for (int ni = 0; ni < 8; ++ni) {
                int np = ni >> 1, pr = (ni & 1) * 2;
                mma_bf16(sacc[ni], qh, kh[np][pr], kh[np][pr + 1]);
                mma_bf16(sacc[ni], qh, kl[np][pr], kl[np][pr + 1]);
                mma_bf16(sacc[ni], ql, kh[np][pr], kh[np][pr + 1]);
            }
        }

        // ---- causal mask (partial tiles only) ----
        const int row0 = wrow_lo + gid, row1 = row0 + 8;
        if (k0 + FA_TK - 1 > q0) {
#pragma unroll
            for (int ni = 0; ni < 8; ++ni) {
                int col = k0 + ni * 8 + tig * 2;
                if (col     > row0) sacc[ni][0] = -1e30f;
                if (col + 1 > row0) sacc[ni][1] = -1e30f;
                if (col     > row1) sacc[ni][2] = -1e30f;
                if (col + 1 > row1) sacc[ni][3] = -1e30f;
            }
        }

        // ---- online softmax (rows row0/row1 per thread, reduce over tig) ----
        float mx0 = -1e30f, mx1 = -1e30f;
#pragma unroll
        for (int ni = 0; ni < 8; ++ni) {
            mx0 = fmaxf(mx0, fmaxf(sacc[ni][0], sacc[ni][1]));
            mx1 = fmaxf(mx1, fmaxf(sacc[ni][2], sacc[ni][3]));
        }
#pragma unroll
        for (int off = 1; off < 4; off <<= 1) {
            mx0 = fmaxf(mx0, __shfl_xor_sync(0xffffffffu, mx0, off));
            mx1 = fmaxf(mx1, __shfl_xor_sync(0xffffffffu, mx1, off));
        }
        float mn0 = fmaxf(m0, mx0), mn1 = fmaxf(m1, mx1);
        float a0 = __expf(m0 - mn0), a1 = __expf(m1 - mn1);
        m0 = mn0; m1 = mn1;
        float sum0 = 0.f, sum1 = 0.f;
#pragma unroll
        for (int ni = 0; ni < 8; ++ni) {
            sacc[ni][0] = __expf(sacc[ni][0] - mn0);
            sacc[ni][1] = __expf(sacc[ni][1] - mn0);
            sacc[ni][2] = __expf(sacc[ni][2] - mn1);
            sacc[ni][3] = __expf(sacc[ni][3] - mn1);
            sum0 += sacc[ni][0] + sacc[ni][1];
            sum1 += sacc[ni][2] + sacc[ni][3];
        }
#pragma unroll
        for (int off = 1; off < 4; off <<= 1) {
            sum0 += __shfl_xor_sync(0xffffffffu, sum0, off);
            sum1 += __shfl_xor_sync(0xffffffffu, sum1, off);
        }
        l0 = l0 * a0 + sum0;
        l1 = l1 * a1 + sum1;
#pragma unroll
        for (int ni = 0; ni < 16; ++ni) {
            oacc[ni][0] *= a0; oacc[ni][1] *= a0;
            oacc[ni][2] *= a1; oacc[ni][3] *= a1;
        }

        // ---- O += P @ V  (P hi/lo from regs, V hi/lo via trans ldmatrix) ----
#pragma unroll
        for (int kc = 0; kc < 4; ++kc) {
            uint32_t ah[4], al[4];
            split2(sacc[2 * kc][0],     sacc[2 * kc][1],     ah[0], al[0]);
            split2(sacc[2 * kc][2],     sacc[2 * kc][3],     ah[1], al[1]);
            split2(sacc[2 * kc + 1][0], sacc[2 * kc + 1][1], ah[2], al[2]);
            split2(sacc[2 * kc + 1][2], sacc[2 * kc + 1][3], ah[3], al[3]);
#pragma unroll
            for (int np = 0; np < 8; ++np) {
                uint32_t vh[4], vl[4];
                uint32_t voff = (uint32_t)((kc * 16 + (lane & 15)) * (QK_STRIDE * 2)
                                           + (np * 16 + (lane >> 4) * 8) * 2);
                ldsm4t(vh, sbase + FA_VHI + voff);
                ldsm4t(vl, sbase + FA_VLO + voff);
#pragma unroll
                for (int q = 0; q < 2; ++q) {
                    int ni = np * 2 + q, pr = q * 2;
                    mma_bf16(oacc[ni], ah, vh[pr], vh[pr + 1]);
                    mma_bf16(oacc[ni], ah, vl[pr], vl[pr + 1]);
                    mma_bf16(oacc[ni], al, vh[pr], vh[pr + 1]);
                }
            }
        }
    }

    // ---- epilogue: normalize, split to bf16 hi/lo, store (skips split pass) ----
    {
        float inv0 = 1.f / l0, inv1 = 1.f / l1;
        int t0 = wrow_lo + gid;
        size_t base0 = (size_t)(b * SEQ + t0) * D_MODEL + h * HEAD_DIM;
        size_t base1 = (size_t)(b * SEQ + t0 + 8) * D_MODEL + h * HEAD_DIM;
#pragma unroll
        for (int ni = 0; ni < 16; ++ni) {
            int col = ni * 8 + tig * 2;
            uint32_t hi, lo;
            split2(oacc[ni][0] * inv0, oacc[ni][1] * inv0, hi, lo);
            *(uint32_t*)(g_Ahi + base0 + col) = hi;
            *(uint32_t*)(g_Alo + base0 + col) = lo;
            split2(oacc[ni][2] * inv1, oacc[ni][3] * inv1, hi, lo);
            *(uint32_t*)(g_Ahi + base1 + col) = hi;
            *(uint32_t*)(g_Alo + base1 + col) = lo;
        }
    }
}

// ---------------------------------------------------------------------------
extern "C" void kernel_launch(void* const* d_in, const int* in_sizes, int n_in,
                              void* d_out, int out_size)
{
    (void)in_sizes; (void)n_in; (void)out_size;
    const float* x     = (const float*)d_in[0];
    const float* Wqkv  = (const float*)d_in[2];
    const float* bqkv  = (const float*)d_in[3];
    const float* Wproj = (const float*)d_in[4];
    const float* bproj = (const float*)d_in[5];
    float* out = (float*)d_out;

    void *qkv_p, *ahi_p, *alo_p, *wq_hi_p, *wq_lo_p, *wp_hi_p, *wp_lo_p;
    cudaGetSymbolAddress(&qkv_p, g_qkv);
    cudaGetSymbolAddress(&ahi_p, g_Ahi);
    cudaGetSymbolAddress(&alo_p, g_Alo);
    cudaGetSymbolAddress(&wq_hi_p, g_Wqkv_hi);
    cudaGetSymbolAddress(&wq_lo_p, g_Wqkv_lo);
    cudaGetSymbolAddress(&wp_hi_p, g_Wproj_hi);
    cudaGetSymbolAddress(&wp_lo_p, g_Wproj_lo);
    float* qkv = (float*)qkv_p;
    __nv_bfloat16* Ahi = (__nv_bfloat16*)ahi_p;
    __nv_bfloat16* Alo = (__nv_bfloat16*)alo_p;
    __nv_bfloat16* WqH = (__nv_bfloat16*)wq_hi_p;
    __nv_bfloat16* WqL = (__nv_bfloat16*)wq_lo_p;
    __nv_bfloat16* WpH = (__nv_bfloat16*)wp_hi_p;
    __nv_bfloat16* WpL = (__nv_bfloat16*)wp_lo_p;

    cudaFuncSetAttribute(gemm_bf16x3_kernel,
                         cudaFuncAttributeMaxDynamicSharedMemorySize, GB_SMEM);
    cudaFuncSetAttribute(flash_attn_mma_kernel,
                         cudaFuncAttributeMaxDynamicSharedMemorySize, FA_SMEM);

    const int M = BATCH * SEQ;               // 4096
    const int nelem = M * D_MODEL;

    // 0) RoPE cos/sin table
    rope_table_kernel<<<SEQ * 64 / 256, 256>>>();

    // 1) split activations x -> (Ahi, Alo)
    split_kernel<<<(nelem / 4 + 255) / 256, 256>>>(x, Ahi, Alo, nelem / 4);

    // 2) weight transpose + split
    transpose_split_kernel<<<dim3(3 * D_MODEL / 64, D_MODEL / 64), 256>>>(
        Wqkv, WqH, WqL, D_MODEL, 3 * D_MODEL);
    transpose_split_kernel<<<dim3(D_MODEL / 64, D_MODEL / 64), 256>>>(
        Wproj, WpH, WpL, D_MODEL, D_MODEL);

    // 3) QKV projection (tensor cores)
    gemm_bf16x3_kernel<<<dim3(3 * D_MODEL / 128, M / 128), 256, GB_SMEM>>>(
        Ahi, Alo, WqH, WqL, bqkv, qkv, M, 3 * D_MODEL, D_MODEL);

    // 4) MMA flash attention (writes bf16 hi/lo directly)
    flash_attn_mma_kernel<<<dim3(SEQ / FA_TQ, BATCH * N_HEAD), 256, FA_SMEM>>>();

    // 5) output projection (tensor cores)
    gemm_bf16x3_kernel<<<dim3(D_MODEL / 128, M / 128), 256, GB_SMEM>>>(
        Ahi, Alo, WpH, WpL, bproj, out, M, D_MODEL, D_MODEL);
}

// round 6
// speedup vs baseline: 2.5417x; 1.1158x over previous
#include <cuda_runtime.h>
#include <cuda_bf16.h>
#include <math.h>
#include <stdint.h>

#define D_MODEL 2048
#define N_HEAD  16
#define HEAD_DIM 128
#define BATCH   2
#define SEQ     2048

// ---------------------------------------------------------------------------
// Static scratch (no cudaMalloc anywhere)
// ---------------------------------------------------------------------------
static __device__ float g_qkv[(size_t)BATCH * SEQ * 3 * D_MODEL]; // 100 MB
static __device__ float g_rope[(size_t)SEQ * 128];                // cos/sin table
static __device__ __nv_bfloat16 g_Ahi[(size_t)BATCH * SEQ * D_MODEL];
static __device__ __nv_bfloat16 g_Alo[(size_t)BATCH * SEQ * D_MODEL];
static __device__ __nv_bfloat16 g_Wqkv_hi[(size_t)3 * D_MODEL * D_MODEL]; // [N][K]
static __device__ __nv_bfloat16 g_Wqkv_lo[(size_t)3 * D_MODEL * D_MODEL];
static __device__ __nv_bfloat16 g_Wproj_hi[(size_t)D_MODEL * D_MODEL];
static __device__ __nv_bfloat16 g_Wproj_lo[(size_t)D_MODEL * D_MODEL];
// head-major prepped attention operands: [b][h][t][d]
static __device__ __nv_bfloat16 g_Qhi[(size_t)BATCH * SEQ * D_MODEL];
static __device__ __nv_bfloat16 g_Qlo[(size_t)BATCH * SEQ * D_MODEL];
static __device__ __nv_bfloat16 g_Khi[(size_t)BATCH * SEQ * D_MODEL];
static __device__ __nv_bfloat16 g_Klo[(size_t)BATCH * SEQ * D_MODEL];
static __device__ __nv_bfloat16 g_Vhi[(size_t)BATCH * SEQ * D_MODEL];
static __device__ __nv_bfloat16 g_Vlo[(size_t)BATCH * SEQ * D_MODEL];

// ---------------------------------------------------------------------------
// PTX helpers (sm_80+ subset: cp.async / ldmatrix / mma.sync)
// ---------------------------------------------------------------------------
__device__ __forceinline__ uint32_t smem_to_u32(const void* smem_ptr) {
    uint32_t addr;
    asm("{ .reg .u64 tmp; cvta.to.shared.u64 tmp, %1; cvt.u32.u64 %0, tmp; }"
        : "=r"(addr) : "l"(smem_ptr));
    return addr;
}

__device__ __forceinline__ void cp_async16(uint32_t smem_dst, const void* gmem_src) {
    asm volatile("cp.async.cg.shared.global.L2::128B [%0], [%1], 16;"
                 :: "r"(smem_dst), "l"(__cvta_generic_to_global(gmem_src)));
}
#define CP_ASYNC_COMMIT() asm volatile("cp.async.commit_group;" ::: "memory")
#define CP_ASYNC_WAIT_1() asm volatile("cp.async.wait_group 1;" ::: "memory")

__device__ __forceinline__ void ldsm4(uint32_t* r, uint32_t addr) {
    asm volatile("ldmatrix.sync.aligned.m8n8.x4.shared.b16 {%0,%1,%2,%3}, [%4];"
                 : "=r"(r[0]), "=r"(r[1]), "=r"(r[2]), "=r"(r[3]) : "r"(addr));
}
__device__ __forceinline__ void ldsm4t(uint32_t* r, uint32_t addr) {
    asm volatile("ldmatrix.sync.aligned.m8n8.x4.trans.shared.b16 {%0,%1,%2,%3}, [%4];"
                 : "=r"(r[0]), "=r"(r[1]), "=r"(r[2]), "=r"(r[3]) : "r"(addr));
}

__device__ __forceinline__ void mma_bf16(float* c, const uint32_t* a,
                                         uint32_t b0, uint32_t b1) {
    asm volatile(
        "mma.sync.aligned.m16n8k16.row.col.f32.bf16.bf16.f32 "
        "{%0,%1,%2,%3}, {%4,%5,%6,%7}, {%8,%9}, {%0,%1,%2,%3};"
        : "+f"(c[0]), "+f"(c[1]), "+f"(c[2]), "+f"(c[3])
        : "r"(a[0]), "r"(a[1]), "r"(a[2]), "r"(a[3]), "r"(b0), "r"(b1));
}

// pack (s0 -> low bf16, s1 -> high bf16) into hi; residuals into lo.
__device__ __forceinline__ void split2(float s0, float s1, uint32_t& hi, uint32_t& lo) {
    asm("cvt.rn.bf16x2.f32 %0, %1, %2;" : "=r"(hi) : "f"(s1), "f"(s0));
    __nv_bfloat162 hv = *reinterpret_cast<__nv_bfloat162*>(&hi);
    float r0 = s0 - __bfloat162float(hv.x);
    float r1 = s1 - __bfloat162float(hv.y);
    asm("cvt.rn.bf16x2.f32 %0, %1, %2;" : "=r"(lo) : "f"(r1), "f"(r0));
}

// ---------------------------------------------------------------------------
// RoPE table
// ---------------------------------------------------------------------------
__global__ void rope_table_kernel()
{
    const float RATE_C = 0.14391156831212787f; // ln(10000)/64
    int i = blockIdx.x * blockDim.x + threadIdx.x;  // t*64 + j
    int t = i >> 6, j = i & 63;
    float rate = expf(-RATE_C * (float)j);
    float sv, cv;
    sincosf((float)t * rate, &sv, &cv);
    g_rope[t * 128 + j]      = cv;
    g_rope[t * 128 + 64 + j] = sv;
}

// ---------------------------------------------------------------------------
// One-shot Q/K prep: rope (+scale for Q), split to bf16 hi/lo, head-major out.
// blockIdx.y: 0 = Q (scale folded), 1 = K.
// ---------------------------------------------------------------------------
__global__ __launch_bounds__(256) void qk_prep_kernel()
{
    const int sel = blockIdx.y;                  // 0=Q, 1=K
    int i = blockIdx.x * blockDim.x + threadIdx.x;   // [0, B*T*1024)
    int tg = i >> 10;                            // b*SEQ + t
    int r  = i & 1023;
    int h  = r >> 6;
    int j  = r & 63;
    int t  = tg & (SEQ - 1);
    int b  = tg >> 11;                           // SEQ = 2048

    const float* g = g_qkv + (size_t)tg * (3 * D_MODEL) + sel * D_MODEL + h * HEAD_DIM;
    float x1 = g[j], x2 = g[j + 64];
    float cv = g_rope[t * 128 + j], sv = g_rope[t * 128 + 64 + j];
    float y1 = x1 * cv - x2 * sv;
    float y2 = x1 * sv + x2 * cv;
    if (sel == 0) { y1 *= 0.08838834764831845f; y2 *= 0.08838834764831845f; }

    __nv_bfloat16 h1 = __float2bfloat16(y1);
    __nv_bfloat16 h2 = __float2bfloat16(y2);
    __nv_bfloat16 l1 = __float2bfloat16(y1 - __bfloat162float(h1));
    __nv_bfloat16 l2 = __float2bfloat16(y2 - __bfloat162float(h2));

    size_t base = ((size_t)(b * N_HEAD + h) * SEQ + t) * HEAD_DIM;
    __nv_bfloat16* dh = sel == 0 ? g_Qhi : g_Khi;
    __nv_bfloat16* dl = sel == 0 ? g_Qlo : g_Klo;
    dh[base + j] = h1;  dh[base + j + 64] = h2;
    dl[base + j] = l1;  dl[base + j + 64] = l2;
}

// V prep: straight split, head-major out.
__global__ __launch_bounds__(256) void v_prep_kernel()
{
    int i = blockIdx.x * blockDim.x + threadIdx.x;   // [0, B*T*512)
    int tg = i >> 9;
    int r  = i & 511;
    int h  = r >> 5;
    int c  = r & 31;
    int t  = tg & (SEQ - 1);
    int b  = tg >> 11;

    float4 v = *(const float4*)(g_qkv + (size_t)tg * (3 * D_MODEL) + 2 * D_MODEL
                                + h * HEAD_DIM + c * 4);
    float vv[4] = {v.x, v.y, v.z, v.w};
    __nv_bfloat16 hh[4], ll[4];
#pragma unroll
    for (int q = 0; q < 4; ++q) {
        hh[q] = __float2bfloat16(vv[q]);
        ll[q] = __float2bfloat16(vv[q] - __bfloat162float(hh[q]));
    }
    size_t base = ((size_t)(b * N_HEAD + h) * SEQ + t) * HEAD_DIM + c * 4;
    *(uint2*)(g_Vhi + base) = *(uint2*)hh;
    *(uint2*)(g_Vlo + base) = *(uint2*)ll;
}

// ---------------------------------------------------------------------------
// Elementwise split: fp32 -> (hi, lo) bf16 pair.
// ---------------------------------------------------------------------------
__global__ void split_kernel(const float* __restrict__ X,
                             __nv_bfloat16* __restrict__ hi,
                             __nv_bfloat16* __restrict__ lo, int n4)
{
    int i = blockIdx.x * blockDim.x + threadIdx.x;
    if (i >= n4) return;
    float4 v = *(const float4*)(X + (size_t)i * 4);
    __nv_bfloat16 h[4], l[4];
    float vv[4] = {v.x, v.y, v.z, v.w};
#pragma unroll
    for (int j = 0; j < 4; ++j) {
        h[j] = __float2bfloat16(vv[j]);
        l[j] = __float2bfloat16(vv[j] - __bfloat162float(h[j]));
    }
    *(uint2*)(hi + (size_t)i * 4) = *(uint2*)h;
    *(uint2*)(lo + (size_t)i * 4) = *(uint2*)l;
}

// ---------------------------------------------------------------------------
// Transpose + split: W[K,N] fp32 -> Thi/Tlo [N,K] bf16 (K-major for MMA B).
// ---------------------------------------------------------------------------
__global__ __launch_bounds__(256) void transpose_split_kernel(
    const float* __restrict__ W,
    __nv_bfloat16* __restrict__ Thi, __nv_bfloat16* __restrict__ Tlo,
    int K, int N)
{
    __shared__ float tile[64][65];
    const int k0 = blockIdx.y * 64;
    const int n0 = blockIdx.x * 64;
    const int tid = threadIdx.x;

#pragma unroll
    for (int j = 0; j < 4; ++j) {
        int idx = tid + j * 256;
        int r  = idx >> 4;
        int c4 = (idx & 15) * 4;
        float4 v = *(const float4*)(W + (size_t)(k0 + r) * N + n0 + c4);
        tile[r][c4 + 0] = v.x; tile[r][c4 + 1] = v.y;
        tile[r][c4 + 2] = v.z; tile[r][c4 + 3] = v.w;
    }
    __syncthreads();

    const int n  = tid >> 2;
    const int ks = (tid & 3) * 16;
    __nv_bfloat16 h[16], l[16];
#pragma unroll
    for (int j = 0; j < 16; ++j) {
        float v = tile[ks + j][n];
        h[j] = __float2bfloat16(v);
        l[j] = __float2bfloat16(v - __bfloat162float(h[j]));
    }
    size_t base = (size_t)(n0 + n) * K + k0 + ks;
    *(uint4*)(Thi + base)     = ((uint4*)h)[0];
    *(uint4*)(Thi + base + 8) = ((uint4*)h)[1];
    *(uint4*)(Tlo + base)     = ((uint4*)l)[0];
    *(uint4*)(Tlo + base + 8) = ((uint4*)l)[1];
}

// ---------------------------------------------------------------------------
// bf16x3 HMMA GEMM: 2-stage cp.async, 2 CTAs/SM.
// ---------------------------------------------------------------------------
#define GB_ROWB   80
#define GB_OP     (128 * GB_ROWB)
#define GB_STAGE  (4 * GB_OP)
#define GB_NSTAGE 2
#define GB_SMEM   (GB_NSTAGE * GB_STAGE)    // 81920 B

__device__ __forceinline__ void gemm_load_stage(
    uint32_t st,
    const __nv_bfloat16* __restrict__ Ahi, const __nv_bfloat16* __restrict__ Alo,
    const __nv_bfloat16* __restrict__ Bhi, const __nv_bfloat16* __restrict__ Blo,
    int bm, int bn, int k0, int K, int tid)
{
#pragma unroll
    for (int j = 0; j < 2; ++j) {
        int idx = tid + j * 256;
        int row = idx >> 2;
        int c   = idx & 3;
        uint32_t off = (uint32_t)(row * GB_ROWB + c * 16);
        size_t ga = (size_t)(bm + row) * K + k0 + c * 8;
        size_t gb = (size_t)(bn + row) * K + k0 + c * 8;
        cp_async16(st + off,              Ahi + ga);
        cp_async16(st + GB_OP + off,      Alo + ga);
        cp_async16(st + 2 * GB_OP + off,  Bhi + gb);
        cp_async16(st + 3 * GB_OP + off,  Blo + gb);
    }
}

__global__ __launch_bounds__(256, 2) void gemm_bf16x3_kernel(
    const __nv_bfloat16* __restrict__ Ahi, const __nv_bfloat16* __restrict__ Alo,
    const __nv_bfloat16* __restrict__ Bhi, const __nv_bfloat16* __restrict__ Blo,
    const float* __restrict__ bias, float* __restrict__ C,
    int M, int N, int K)
{
    extern __shared__ __align__(128) char smem[];
    const uint32_t sbase = smem_to_u32(smem);
    const int tid  = threadIdx.x;
    const int lane = tid & 31;
    const int wid  = tid >> 5;
    const int wm   = wid >> 2;
    const int wn   = wid & 3;
    const int bm   = blockIdx.y * 128;
    const int bn   = blockIdx.x * 128;

    float acc[4][4][4];
#pragma unroll
    for (int mi = 0; mi < 4; ++mi)
#pragma unroll
        for (int ni = 0; ni < 4; ++ni)
#pragma unroll
            for (int r = 0; r < 4; ++r) acc[mi][ni][r] = 0.f;

    const int nk = K / 32;

    gemm_load_stage(sbase,            Ahi, Alo, Bhi, Blo, bm, bn, 0,  K, tid);
    CP_ASYNC_COMMIT();
    gemm_load_stage(sbase + GB_STAGE, Ahi, Alo, Bhi, Blo, bm, bn, 32, K, tid);
    CP_ASYNC_COMMIT();

    const int lrowA = lane & 15, lcolA = lane >> 4;
    const int bg    = lane >> 3, blr  = lane & 7;

    for (int i = 0; i < nk; ++i) {
        const uint32_t st = sbase + (uint32_t)(i % GB_NSTAGE) * GB_STAGE;
        CP_ASYNC_WAIT_1();
        __syncthreads();

        const uint32_t aHi = st;
        const uint32_t aLo = st + GB_OP;
        const uint32_t bHi = st + 2 * GB_OP;
        const uint32_t bLo = st + 3 * GB_OP;

#pragma unroll
        for (int ks = 0; ks < 2; ++ks) {
            uint32_t ah[4][4], al[4][4], bh[2][4], bl[2][4];
#pragma unroll
            for (int mi = 0; mi < 4; ++mi) {
                uint32_t off = (uint32_t)((wm * 64 + mi * 16 + lrowA) * GB_ROWB
                                          + (ks * 2 + lcolA) * 16);
                ldsm4(ah[mi], aHi + off);
                ldsm4(al[mi], aLo + off);
            }
#pragma unroll
            for (int np = 0; np < 2; ++np) {
                uint32_t off = (uint32_t)((wn * 32 + np * 16 + (bg >> 1) * 8 + blr) * GB_ROWB
                                          + (ks * 2 + (bg & 1)) * 16);
                ldsm4(bh[np], bHi + off);
                ldsm4(bl[np], bLo + off);
            }
#pragma unroll
            for (int mi = 0; mi < 4; ++mi)
#pragma unroll
                for (int ni = 0; ni < 4; ++ni) {
                    int np = ni >> 1, pr = (ni & 1) * 2;
                    mma_bf16(acc[mi][ni], ah[mi], bh[np][pr], bh[np][pr + 1]);
                    mma_bf16(acc[mi][ni], ah[mi], bl[np][pr], bl[np][pr + 1]);
                    mma_bf16(acc[mi][ni], al[mi], bh[np][pr], bh[np][pr + 1]);
                }
        }

        __syncthreads();
        if (i + 2 < nk) {
            gemm_load_stage(sbase + (uint32_t)((i + 2) % GB_NSTAGE) * GB_STAGE,
                            Ahi, Alo, Bhi, Blo, bm, bn, (i + 2) * 32, K, tid);
        }
        CP_ASYNC_COMMIT();
    }

    const int gid = lane >> 2, tig = lane & 3;
#pragma unroll
    for (int mi = 0; mi < 4; ++mi)
#pragma unroll
        for (int ni = 0; ni < 4; ++ni) {
            int row = bm + wm * 64 + mi * 16 + gid;
            int col = bn + wn * 32 + ni * 8 + tig * 2;
            float2 bv = *(const float2*)(bias + col);
            float2 v0 = make_float2(acc[mi][ni][0] + bv.x, acc[mi][ni][1] + bv.y);
            float2 v1 = make_float2(acc[mi][ni][2] + bv.x, acc[mi][ni][3] + bv.y);
            *(float2*)(C + (size_t)row * N + col)       = v0;
            *(float2*)(C + (size_t)(row + 8) * N + col) = v1;
        }
}

// ---------------------------------------------------------------------------
// MMA flash attention over PREPPED bf16 operands. Pure cp.async + MMA + softmax.
// 128-row Q tiles, 64-col K tiles, double-buffered KV smem.
// ---------------------------------------------------------------------------
#define FA_TQ 128
#define FA_TK 64
#define FA_STRIDE 136                 // bf16 per smem row (128 + 8 pad), 272 B
#define FA_ROWB   272
#define FA_QHI  0
#define FA_QLO  34816
#define FA_KV0  69632                 // per buffer: KHI,+17408 KLO,+34816 VHI,+52224 VLO
#define FA_KVSZ 69632
#define FA_SMEM 208896

__device__ __forceinline__ void fa_load_kv(uint32_t buf, size_t bh_elem, int k0, int tid)
{
    size_t gbase = bh_elem + (size_t)k0 * HEAD_DIM;
    for (int i = tid; i < FA_TK * 16; i += 256) {
        int row = i >> 4, c = i & 15;
        uint32_t soff = (uint32_t)(row * FA_ROWB + c * 16);
        size_t   goff = gbase + (size_t)row * HEAD_DIM + c * 8;
        cp_async16(buf + soff,         g_Khi + goff);
        cp_async16(buf + 17408 + soff, g_Klo + goff);
        cp_async16(buf + 34816 + soff, g_Vhi + goff);
        cp_async16(buf + 52224 + soff, g_Vlo + goff);
    }
}

__global__ __launch_bounds__(256, 1) void flash_attn_mma_kernel()
{
    extern __shared__ __align__(128) char sm[];
    const uint32_t sbase = smem_to_u32(sm);

    const int tid  = threadIdx.x;
    const int lane = tid & 31;
    const int wid  = tid >> 5;
    const int qt   = (gridDim.x - 1) - blockIdx.x;   // heavy tiles first
    const int q0   = qt * FA_TQ;
    const int b    = blockIdx.y >> 4;
    const int h    = blockIdx.y & 15;

    const size_t bh_elem = (size_t)(b * N_HEAD + h) * SEQ * HEAD_DIM;

    // ---- Q tile load (prepped bf16 hi/lo) ----
    {
        size_t qbase = bh_elem + (size_t)q0 * HEAD_DIM;
        for (int i = tid; i < FA_TQ * 16; i += 256) {
            int row = i >> 4, c = i & 15;
            uint32_t soff = (uint32_t)(row * FA_ROWB + c * 16);
            size_t   goff = qbase + (size_t)row * HEAD_DIM + c * 8;
            cp_async16(sbase + FA_QHI + soff, g_Qhi + goff);
            cp_async16(sbase + FA_QLO + soff, g_Qlo + goff);
        }
    }
    const int ktmax = 2 * qt + 1;
    fa_load_kv(sbase + FA_KV0, bh_elem, 0, tid);
    CP_ASYNC_COMMIT();                               // group: Q + KV0
    fa_load_kv(sbase + FA_KV0 + FA_KVSZ, bh_elem, FA_TK, tid);  // ktmax >= 1 always
    CP_ASYNC_COMMIT();                               // group: KV1

    float oacc[16][4];
#pragma unroll
    for (int ni = 0; ni < 16; ++ni)
#pragma unroll
        for (int r = 0; r < 4; ++r) oacc[ni][r] = 0.f;
    float m0 = -1e30f, m1 = -1e30f, l0 = 0.f, l1 = 0.f;

    const int gid = lane >> 2, tig = lane & 3;
    const int lrowA = lane & 15, lcolA = lane >> 4;
    const int bg = lane >> 3, blr = lane & 7;
    const int wrow_lo = q0 + wid * 16;

    for (int kt = 0; kt <= ktmax; ++kt) {
        const int k0 = kt * FA_TK;
        const uint32_t buf = sbase + FA_KV0 + (uint32_t)(kt & 1) * FA_KVSZ;
        CP_ASYNC_WAIT_1();          // KV[kt] (and Q) resident; KV[kt+1] may pend
        __syncthreads();

        if (k0 <= wrow_lo + 15) {   // warp-level causal skip
            // ---- S = Q @ K^T, bf16x3 ----
            float sacc[8][4];
#pragma unroll
            for (int ni = 0; ni < 8; ++ni)
#pragma unroll
                for (int r = 0; r < 4; ++r) sacc[ni][r] = 0.f;

#pragma unroll
            for (int ks = 0; ks < 8; ++ks) {
                uint32_t qh[4], ql[4];
                uint32_t qoff = (uint32_t)((wid * 16 + lrowA) * FA_ROWB
                                           + (ks * 16 + lcolA * 8) * 2);
                ldsm4(qh, sbase + FA_QHI + qoff);
                ldsm4(ql, sbase + FA_QLO + qoff);
                uint32_t kh[4][4], kl[4][4];
#pragma unroll
                for (int np = 0; np < 4; ++np) {
                    uint32_t koff = (uint32_t)((np * 16 + (bg >> 1) * 8 + blr) * FA_ROWB
                                               + (ks * 16 + (bg & 1) * 8) * 2);
                    ldsm4(kh[np], buf + koff);
                    ldsm4(kl[np], buf + 17408 + koff);
                }
#pragma unroll
                for (int ni = 0; ni < 8; ++ni) {
                    int np = ni >> 1, pr = (ni & 1) * 2;
                    mma_bf16(sacc[ni], qh, kh[np][pr], kh[np][pr + 1]);
                    mma_bf16(sacc[ni], qh, kl[np][pr], kl[np][pr + 1]);
                    mma_bf16(sacc[ni], ql, kh[np][pr], kh[np][pr + 1]);
                }
            }

            // ---- causal mask (partial tiles only) ----
            const int row0 = wrow_lo + gid, row1 = row0 + 8;
            if (k0 + FA_TK - 1 > q0) {
#pragma unroll
                for (int ni = 0; ni < 8; ++ni) {
                    int col = k0 + ni * 8 + tig * 2;
                    if (col     > row0) sacc[ni][0] = -1e30f;
                    if (col + 1 > row0) sacc[ni][1] = -1e30f;
                    if (col     > row1) sacc[ni][2] = -1e30f;
                    if (col + 1 > row1) sacc[ni][3] = -1e30f;
                }
            }

            // ---- online softmax ----
            float mx0 = -1e30f, mx1 = -1e30f;
#pragma unroll
            for (int ni = 0; ni < 8; ++ni) {
                mx0 = fmaxf(mx0, fmaxf(sacc[ni][0], sacc[ni][1]));
                mx1 = fmaxf(mx1, fmaxf(sacc[ni][2], sacc[ni][3]));
            }
#pragma unroll
            for (int off = 1; off < 4; off <<= 1) {
                mx0 = fmaxf(mx0, __shfl_xor_sync(0xffffffffu, mx0, off));
                mx1 = fmaxf(mx1, __shfl_xor_sync(0xffffffffu, mx1, off));
            }
            float mn0 = fmaxf(m0, mx0), mn1 = fmaxf(m1, mx1);
            float a0 = __expf(m0 - mn0), a1 = __expf(m1 - mn1);
            m0 = mn0; m1 = mn1;
            float sum0 = 0.f, sum1 = 0.f;
#pragma unroll
            for (int ni = 0; ni < 8; ++ni) {
                sacc[ni][0] = __expf(sacc[ni][0] - mn0);
                sacc[ni][1] = __expf(sacc[ni][1] - mn0);
                sacc[ni][2] = __expf(sacc[ni][2] - mn1);
                sacc[ni][3] = __expf(sacc[ni][3] - mn1);
                sum0 += sacc[ni][0] + sacc[ni][1];
                sum1 += sacc[ni][2] + sacc[ni][3];
            }
#pragma unroll
            for (int off = 1; off < 4; off <<= 1) {
                sum0 += __shfl_xor_sync(0xffffffffu, sum0, off);
                sum1 += __shfl_xor_sync(0xffffffffu, sum1, off);
            }
            l0 = l0 * a0 + sum0;
            l1 = l1 * a1 + sum1;
#pragma unroll
            for (int ni = 0; ni < 16; ++ni) {
                oacc[ni][0] *= a0; oacc[ni][1] *= a0;
                oacc[ni][2] *= a1; oacc[ni][3] *= a1;
            }

            // ---- O += P @ V, bf16x3 (V via trans ldmatrix) ----
            const uint32_t vhi = buf + 34816, vlo = buf + 52224;
#pragma unroll
            for (int kc = 0; kc < 4; ++kc) {
                uint32_t ah[4], al[4];
                split2(sacc[2 * kc][0],     sacc[2 * kc][1],     ah[0], al[0]);
                split2(sacc[2 * kc][2],     sacc[2 * kc][3],     ah[1], al[1]);
                split2(sacc[2 * kc + 1][0], sacc[2 * kc + 1][1], ah[2], al[2]);
                split2(sacc[2 * kc + 1][2], sacc[2 * kc + 1][3], ah[3], al[3]);
#pragma unroll
                for (int np = 0; np < 8; ++np) {
                    uint32_t vh[4], vl[4];
                    uint32_t voff = (uint32_t)((kc * 16 + (lane & 15)) * FA_ROWB
                                               + (np * 16 + (lane >> 4) * 8) * 2);
                    ldsm4t(vh, vhi + voff);
                    ldsm4t(vl, vlo + voff);
#pragma unroll
                    for (int q = 0; q < 2; ++q) {
                        int ni = np * 2 + q, pr = q * 2;
                        mma_bf16(oacc[ni], ah, vh[pr], vh[pr + 1]);
                        mma_bf16(oacc[ni], ah, vl[pr], vl[pr + 1]);
                        mma_bf16(oacc[ni], al, vh[pr], vh[pr + 1]);
                    }
                }
            }
        }

        __syncthreads();            // all warps done reading buf before overwrite
        if (kt + 2 <= ktmax)
            fa_load_kv(sbase + FA_KV0 + (uint32_t)(kt & 1) * FA_KVSZ,
                       bh_elem, (kt + 2) * FA_TK, tid);
        CP_ASYNC_COMMIT();
    }

    // ---- epilogue: normalize, split to bf16 hi/lo, store ----
    {
        float inv0 = 1.f / l0, inv1 = 1.f / l1;
        int t0 = wrow_lo + gid;
        size_t base0 = (size_t)(b * SEQ + t0) * D_MODEL + h * HEAD_DIM;
        size_t base1 = (size_t)(b * SEQ + t0 + 8) * D_MODEL + h * HEAD_DIM;
#pragma unroll
        for (int ni = 0; ni < 16; ++ni) {
            int col = ni * 8 + tig * 2;
            uint32_t hi, lo;
            split2(oacc[ni][0] * inv0, oacc[ni][1] * inv0, hi, lo);
            *(uint32_t*)(g_Ahi + base0 + col) = hi;
            *(uint32_t*)(g_Alo + base0 + col) = lo;
            split2(oacc[ni][2] * inv1, oacc[ni][3] * inv1, hi, lo);
            *(uint32_t*)(g_Ahi + base1 + col) = hi;
            *(uint32_t*)(g_Alo + base1 + col) = lo;
        }
    }
}

// ---------------------------------------------------------------------------
extern "C" void kernel_launch(void* const* d_in, const int* in_sizes, int n_in,
                              void* d_out, int out_size)
{
    (void)in_sizes; (void)n_in; (void)out_size;
    const float* x     = (const float*)d_in[0];
    const float* Wqkv  = (const float*)d_in[2];
    const float* bqkv  = (const float*)d_in[3];
    const float* Wproj = (const float*)d_in[4];
    const float* bproj = (const float*)d_in[5];
    float* out = (float*)d_out;

    void *qkv_p, *ahi_p, *alo_p, *wq_hi_p, *wq_lo_p, *wp_hi_p, *wp_lo_p;
    cudaGetSymbolAddress(&qkv_p, g_qkv);
    cudaGetSymbolAddress(&ahi_p, g_Ahi);
    cudaGetSymbolAddress(&alo_p, g_Alo);
    cudaGetSymbolAddress(&wq_hi_p, g_Wqkv_hi);
    cudaGetSymbolAddress(&wq_lo_p, g_Wqkv_lo);
    cudaGetSymbolAddress(&wp_hi_p, g_Wproj_hi);
    cudaGetSymbolAddress(&wp_lo_p, g_Wproj_lo);
    float* qkv = (float*)qkv_p;
    __nv_bfloat16* Ahi = (__nv_bfloat16*)ahi_p;
    __nv_bfloat16* Alo = (__nv_bfloat16*)alo_p;
    __nv_bfloat16* WqH = (__nv_bfloat16*)wq_hi_p;
    __nv_bfloat16* WqL = (__nv_bfloat16*)wq_lo_p;
    __nv_bfloat16* WpH = (__nv_bfloat16*)wp_hi_p;
    __nv_bfloat16* WpL = (__nv_bfloat16*)wp_lo_p;

    cudaFuncSetAttribute(gemm_bf16x3_kernel,
                         cudaFuncAttributeMaxDynamicSharedMemorySize, GB_SMEM);
    cudaFuncSetAttribute(flash_attn_mma_kernel,
                         cudaFuncAttributeMaxDynamicSharedMemorySize, FA_SMEM);

    const int M = BATCH * SEQ;               // 4096
    const int nelem = M * D_MODEL;

    // 0) RoPE cos/sin table
    rope_table_kernel<<<SEQ * 64 / 256, 256>>>();

    // 1) split activations x -> (Ahi, Alo)
    split_kernel<<<(nelem / 4 + 255) / 256, 256>>>(x, Ahi, Alo, nelem / 4);

    // 2) weight transpose + split
    transpose_split_kernel<<<dim3(3 * D_MODEL / 64, D_MODEL / 64), 256>>>(
        Wqkv, WqH, WqL, D_MODEL, 3 * D_MODEL);
    transpose_split_kernel<<<dim3(D_MODEL / 64, D_MODEL / 64), 256>>>(
        Wproj, WpH, WpL, D_MODEL, D_MODEL);

    // 3) QKV projection (tensor cores)
    gemm_bf16x3_kernel<<<dim3(3 * D_MODEL / 128, M / 128), 256, GB_SMEM>>>(
        Ahi, Alo, WqH, WqL, bqkv, qkv, M, 3 * D_MODEL, D_MODEL);

    // 4) one-shot Q/K rope+split and V split (head-major bf16 hi/lo)
    qk_prep_kernel<<<dim3(M * 1024 / 256, 2), 256>>>();
    v_prep_kernel<<<M * 512 / 256, 256>>>();

    // 5) MMA flash attention on prepped operands (writes bf16 hi/lo directly)
    flash_attn_mma_kernel<<<dim3(SEQ / FA_TQ, BATCH * N_HEAD), 256, FA_SMEM>>>();

    // 6) output projection (tensor cores)
    gemm_bf16x3_kernel<<<dim3(D_MODEL / 128, M / 128), 256, GB_SMEM>>>(
        Ahi, Alo, WpH, WpL, bproj, out, M, D_MODEL, D_MODEL);
}

// round 7
// speedup vs baseline: 2.6014x; 1.0235x over previous
#include <cuda_runtime.h>
#include <cuda_bf16.h>
#include <math.h>
#include <stdint.h>

#define D_MODEL 2048
#define N_HEAD  16
#define HEAD_DIM 128
#define BATCH   2
#define SEQ     2048

// ---------------------------------------------------------------------------
// Static scratch (no cudaMalloc anywhere)
// ---------------------------------------------------------------------------
static __device__ float g_rope[(size_t)SEQ * 128];                // cos/sin table
static __device__ __nv_bfloat16 g_Ahi[(size_t)BATCH * SEQ * D_MODEL];
static __device__ __nv_bfloat16 g_Alo[(size_t)BATCH * SEQ * D_MODEL];
static __device__ __nv_bfloat16 g_Wqkv_hi[(size_t)3 * D_MODEL * D_MODEL]; // [N][K]
static __device__ __nv_bfloat16 g_Wqkv_lo[(size_t)3 * D_MODEL * D_MODEL];
static __device__ __nv_bfloat16 g_Wproj_hi[(size_t)D_MODEL * D_MODEL];
static __device__ __nv_bfloat16 g_Wproj_lo[(size_t)D_MODEL * D_MODEL];
// head-major prepped attention operands: [b][h][t][d]
static __device__ __nv_bfloat16 g_Qhi[(size_t)BATCH * SEQ * D_MODEL];
static __device__ __nv_bfloat16 g_Qlo[(size_t)BATCH * SEQ * D_MODEL];
static __device__ __nv_bfloat16 g_Khi[(size_t)BATCH * SEQ * D_MODEL];
static __device__ __nv_bfloat16 g_Klo[(size_t)BATCH * SEQ * D_MODEL];
static __device__ __nv_bfloat16 g_Vhi[(size_t)BATCH * SEQ * D_MODEL];
static __device__ __nv_bfloat16 g_Vlo[(size_t)BATCH * SEQ * D_MODEL];

// ---------------------------------------------------------------------------
// PTX helpers (sm_80+ subset: cp.async / ldmatrix / mma.sync)
// ---------------------------------------------------------------------------
__device__ __forceinline__ uint32_t smem_to_u32(const void* smem_ptr) {
    uint32_t addr;
    asm("{ .reg .u64 tmp; cvta.to.shared.u64 tmp, %1; cvt.u32.u64 %0, tmp; }"
        : "=r"(addr) : "l"(smem_ptr));
    return addr;
}

__device__ __forceinline__ void cp_async16(uint32_t smem_dst, const void* gmem_src) {
    asm volatile("cp.async.cg.shared.global.L2::128B [%0], [%1], 16;"
                 :: "r"(smem_dst), "l"(__cvta_generic_to_global(gmem_src)));
}
#define CP_ASYNC_COMMIT() asm volatile("cp.async.commit_group;" ::: "memory")
#define CP_ASYNC_WAIT_1() asm volatile("cp.async.wait_group 1;" ::: "memory")

__device__ __forceinline__ void ldsm4(uint32_t* r, uint32_t addr) {
    asm volatile("ldmatrix.sync.aligned.m8n8.x4.shared.b16 {%0,%1,%2,%3}, [%4];"
                 : "=r"(r[0]), "=r"(r[1]), "=r"(r[2]), "=r"(r[3]) : "r"(addr));
}
__device__ __forceinline__ void ldsm4t(uint32_t* r, uint32_t addr) {
    asm volatile("ldmatrix.sync.aligned.m8n8.x4.trans.shared.b16 {%0,%1,%2,%3}, [%4];"
                 : "=r"(r[0]), "=r"(r[1]), "=r"(r[2]), "=r"(r[3]) : "r"(addr));
}

__device__ __forceinline__ void mma_bf16(float* c, const uint32_t* a,
                                         uint32_t b0, uint32_t b1) {
    asm volatile(
        "mma.sync.aligned.m16n8k16.row.col.f32.bf16.bf16.f32 "
        "{%0,%1,%2,%3}, {%4,%5,%6,%7}, {%8,%9}, {%0,%1,%2,%3};"
        : "+f"(c[0]), "+f"(c[1]), "+f"(c[2]), "+f"(c[3])
        : "r"(a[0]), "r"(a[1]), "r"(a[2]), "r"(a[3]), "r"(b0), "r"(b1));
}

// pack (s0 -> low bf16, s1 -> high bf16) into hi; residuals into lo.
__device__ __forceinline__ void split2(float s0, float s1, uint32_t& hi, uint32_t& lo) {
    asm("cvt.rn.bf16x2.f32 %0, %1, %2;" : "=r"(hi) : "f"(s1), "f"(s0));
    __nv_bfloat162 hv = *reinterpret_cast<__nv_bfloat162*>(&hi);
    float r0 = s0 - __bfloat162float(hv.x);
    float r1 = s1 - __bfloat162float(hv.y);
    asm("cvt.rn.bf16x2.f32 %0, %1, %2;" : "=r"(lo) : "f"(r1), "f"(r0));
}

// ---------------------------------------------------------------------------
// RoPE table
// ---------------------------------------------------------------------------
__global__ void rope_table_kernel()
{
    const float RATE_C = 0.14391156831212787f; // ln(10000)/64
    int i = blockIdx.x * blockDim.x + threadIdx.x;  // t*64 + j
    int t = i >> 6, j = i & 63;
    float rate = expf(-RATE_C * (float)j);
    float sv, cv;
    sincosf((float)t * rate, &sv, &cv);
    g_rope[t * 128 + j]      = cv;
    g_rope[t * 128 + 64 + j] = sv;
}

// ---------------------------------------------------------------------------
// Elementwise split: fp32 -> (hi, lo) bf16 pair.
// ---------------------------------------------------------------------------
__global__ void split_kernel(const float* __restrict__ X,
                             __nv_bfloat16* __restrict__ hi,
                             __nv_bfloat16* __restrict__ lo, int n4)
{
    int i = blockIdx.x * blockDim.x + threadIdx.x;
    if (i >= n4) return;
    float4 v = *(const float4*)(X + (size_t)i * 4);
    __nv_bfloat16 h[4], l[4];
    float vv[4] = {v.x, v.y, v.z, v.w};
#pragma unroll
    for (int j = 0; j < 4; ++j) {
        h[j] = __float2bfloat16(vv[j]);
        l[j] = __float2bfloat16(vv[j] - __bfloat162float(h[j]));
    }
    *(uint2*)(hi + (size_t)i * 4) = *(uint2*)h;
    *(uint2*)(lo + (size_t)i * 4) = *(uint2*)l;
}

// ---------------------------------------------------------------------------
// Transpose + split: W[K,N] fp32 -> Thi/Tlo [N,K] bf16 (K-major for MMA B).
// ---------------------------------------------------------------------------
__global__ __launch_bounds__(256) void transpose_split_kernel(
    const float* __restrict__ W,
    __nv_bfloat16* __restrict__ Thi, __nv_bfloat16* __restrict__ Tlo,
    int K, int N)
{
    __shared__ float tile[64][65];
    const int k0 = blockIdx.y * 64;
    const int n0 = blockIdx.x * 64;
    const int tid = threadIdx.x;

#pragma unroll
    for (int j = 0; j < 4; ++j) {
        int idx = tid + j * 256;
        int r  = idx >> 4;
        int c4 = (idx & 15) * 4;
        float4 v = *(const float4*)(W + (size_t)(k0 + r) * N + n0 + c4);
        tile[r][c4 + 0] = v.x; tile[r][c4 + 1] = v.y;
        tile[r][c4 + 2] = v.z; tile[r][c4 + 3] = v.w;
    }
    __syncthreads();

    const int n  = tid >> 2;
    const int ks = (tid & 3) * 16;
    __nv_bfloat16 h[16], l[16];
#pragma unroll
    for (int j = 0; j < 16; ++j) {
        float v = tile[ks + j][n];
        h[j] = __float2bfloat16(v);
        l[j] = __float2bfloat16(v - __bfloat162float(h[j]));
    }
    size_t base = (size_t)(n0 + n) * K + k0 + ks;
    *(uint4*)(Thi + base)     = ((uint4*)h)[0];
    *(uint4*)(Thi + base + 8) = ((uint4*)h)[1];
    *(uint4*)(Tlo + base)     = ((uint4*)l)[0];
    *(uint4*)(Tlo + base + 8) = ((uint4*)l)[1];
}

// ---------------------------------------------------------------------------
// bf16x3 HMMA GEMM: 2-stage cp.async, 2 CTAs/SM.
// fuse_qkv == 0: C = A@B^T + bias (fp32 out).
// fuse_qkv == 1: QKV mode. Each CTA's 128 output cols = exactly one
//   (q|k|v, head) block; epilogue stages the fp32 tile through smem, applies
//   RoPE (+scale for Q), splits to bf16 hi/lo, stores head-major. C unused.
// ---------------------------------------------------------------------------
#define GB_ROWB   80
#define GB_OP     (128 * GB_ROWB)
#define GB_STAGE  (4 * GB_OP)
#define GB_NSTAGE 2
#define GB_SMEM   (GB_NSTAGE * GB_STAGE)    // 81920 B  (>= 128*132*4 = 67584)

__device__ __forceinline__ void gemm_load_stage(
    uint32_t st,
    const __nv_bfloat16* __restrict__ Ahi, const __nv_bfloat16* __restrict__ Alo,
    const __nv_bfloat16* __restrict__ Bhi, const __nv_bfloat16* __restrict__ Blo,
    int bm, int bn, int k0, int K, int tid)
{
#pragma unroll
    for (int j = 0; j < 2; ++j) {
        int idx = tid + j * 256;
        int row = idx >> 2;
        int c   = idx & 3;
        uint32_t off = (uint32_t)(row * GB_ROWB + c * 16);
        size_t ga = (size_t)(bm + row) * K + k0 + c * 8;
        size_t gb = (size_t)(bn + row) * K + k0 + c * 8;
        cp_async16(st + off,              Ahi + ga);
        cp_async16(st + GB_OP + off,      Alo + ga);
        cp_async16(st + 2 * GB_OP + off,  Bhi + gb);
        cp_async16(st + 3 * GB_OP + off,  Blo + gb);
    }
}

__global__ __launch_bounds__(256, 2) void gemm_bf16x3_kernel(
    const __nv_bfloat16* __restrict__ Ahi, const __nv_bfloat16* __restrict__ Alo,
    const __nv_bfloat16* __restrict__ Bhi, const __nv_bfloat16* __restrict__ Blo,
    const float* __restrict__ bias, float* __restrict__ C,
    int M, int N, int K, int fuse_qkv)
{
    extern __shared__ __align__(128) char smem[];
    const uint32_t sbase = smem_to_u32(smem);
    const int tid  = threadIdx.x;
    const int lane = tid & 31;
    const int wid  = tid >> 5;
    const int wm   = wid >> 2;
    const int wn   = wid & 3;
    const int bm   = blockIdx.y * 128;
    const int bn   = blockIdx.x * 128;

    float acc[4][4][4];
#pragma unroll
    for (int mi = 0; mi < 4; ++mi)
#pragma unroll
        for (int ni = 0; ni < 4; ++ni)
#pragma unroll
            for (int r = 0; r < 4; ++r) acc[mi][ni][r] = 0.f;

    const int nk = K / 32;

    gemm_load_stage(sbase,            Ahi, Alo, Bhi, Blo, bm, bn, 0,  K, tid);
    CP_ASYNC_COMMIT();
    gemm_load_stage(sbase + GB_STAGE, Ahi, Alo, Bhi, Blo, bm, bn, 32, K, tid);
    CP_ASYNC_COMMIT();

    const int lrowA = lane & 15, lcolA = lane >> 4;
    const int bg    = lane >> 3, blr  = lane & 7;

    for (int i = 0; i < nk; ++i) {
        const uint32_t st = sbase + (uint32_t)(i % GB_NSTAGE) * GB_STAGE;
        CP_ASYNC_WAIT_1();
        __syncthreads();

        const uint32_t aHi = st;
        const uint32_t aLo = st + GB_OP;
        const uint32_t bHi = st + 2 * GB_OP;
        const uint32_t bLo = st + 3 * GB_OP;

#pragma unroll
        for (int ks = 0; ks < 2; ++ks) {
            uint32_t ah[4][4], al[4][4], bh[2][4], bl[2][4];
#pragma unroll
            for (int mi = 0; mi < 4; ++mi) {
                uint32_t off = (uint32_t)((wm * 64 + mi * 16 + lrowA) * GB_ROWB
                                          + (ks * 2 + lcolA) * 16);
                ldsm4(ah[mi], aHi + off);
                ldsm4(al[mi], aLo + off);
            }
#pragma unroll
            for (int np = 0; np < 2; ++np) {
                uint32_t off = (uint32_t)((wn * 32 + np * 16 + (bg >> 1) * 8 + blr) * GB_ROWB
                                          + (ks * 2 + (bg & 1)) * 16);
                ldsm4(bh[np], bHi + off);
                ldsm4(bl[np], bLo + off);
            }
#pragma unroll
            for (int mi = 0; mi < 4; ++mi)
#pragma unroll
                for (int ni = 0; ni < 4; ++ni) {
                    int np = ni >> 1, pr = (ni & 1) * 2;
                    mma_bf16(acc[mi][ni], ah[mi], bh[np][pr], bh[np][pr + 1]);
                    mma_bf16(acc[mi][ni], ah[mi], bl[np][pr], bl[np][pr + 1]);
                    mma_bf16(acc[mi][ni], al[mi], bh[np][pr], bh[np][pr + 1]);
                }
        }

        __syncthreads();
        if (i + 2 < nk) {
            gemm_load_stage(sbase + (uint32_t)((i + 2) % GB_NSTAGE) * GB_STAGE,
                            Ahi, Alo, Bhi, Blo, bm, bn, (i + 2) * 32, K, tid);
        }
        CP_ASYNC_COMMIT();
    }

    const int gid = lane >> 2, tig = lane & 3;

    if (fuse_qkv == 0) {
        // ---- plain epilogue: bias + fp32 store ----
#pragma unroll
        for (int mi = 0; mi < 4; ++mi)
#pragma unroll
            for (int ni = 0; ni < 4; ++ni) {
                int row = bm + wm * 64 + mi * 16 + gid;
                int col = bn + wn * 32 + ni * 8 + tig * 2;
                float2 bv = *(const float2*)(bias + col);
                float2 v0 = make_float2(acc[mi][ni][0] + bv.x, acc[mi][ni][1] + bv.y);
                float2 v1 = make_float2(acc[mi][ni][2] + bv.x, acc[mi][ni][3] + bv.y);
                *(float2*)(C + (size_t)row * N + col)       = v0;
                *(float2*)(C + (size_t)(row + 8) * N + col) = v1;
            }
        return;
    }

    // ---- fused QKV epilogue: rope/scale/split, head-major bf16 hi/lo ----
    // (all MMA smem reads complete: final loop iteration synced after MMA)
    float* Cs = (float*)smem;                 // 128 x 132 fp32, reuses stages
#pragma unroll
    for (int mi = 0; mi < 4; ++mi)
#pragma unroll
        for (int ni = 0; ni < 4; ++ni) {
            int row = wm * 64 + mi * 16 + gid;
            int col = wn * 32 + ni * 8 + tig * 2;
            float2 bv = *(const float2*)(bias + bn + col);
            Cs[row * 132 + col]           = acc[mi][ni][0] + bv.x;
            Cs[row * 132 + col + 1]       = acc[mi][ni][1] + bv.y;
            Cs[(row + 8) * 132 + col]     = acc[mi][ni][2] + bv.x;
            Cs[(row + 8) * 132 + col + 1] = acc[mi][ni][3] + bv.y;
        }
    __syncthreads();

    const int sel = bn >> 11;                 // 0=Q, 1=K, 2=V
    const int hh  = (bn & 2047) >> 7;         // head
    __nv_bfloat16 *dh, *dl;
    if (sel == 0)      { dh = g_Qhi; dl = g_Qlo; }
    else if (sel == 1) { dh = g_Khi; dl = g_Klo; }
    else               { dh = g_Vhi; dl = g_Vlo; }
    const float SCALE = 0.08838834764831845f; // 1/sqrt(128)

    for (int i = tid; i < 128 * 32; i += 256) {
        int row = i >> 5, jp = (i & 31) * 2;  // two adjacent j's: jp, jp+1
        int tg = bm + row, t = tg & (SEQ - 1), bb = tg >> 11;
        float x1a = Cs[row * 132 + jp],      x1b = Cs[row * 132 + jp + 1];
        float x2a = Cs[row * 132 + jp + 64], x2b = Cs[row * 132 + jp + 65];
        float y1a, y1b, y2a, y2b;
        if (sel < 2) {
            float cva = g_rope[t * 128 + jp],     sva = g_rope[t * 128 + 64 + jp];
            float cvb = g_rope[t * 128 + jp + 1], svb = g_rope[t * 128 + 64 + jp + 1];
            y1a = x1a * cva - x2a * sva;  y2a = x1a * sva + x2a * cva;
            y1b = x1b * cvb - x2b * svb;  y2b = x1b * svb + x2b * cvb;
            if (sel == 0) { y1a *= SCALE; y2a *= SCALE; y1b *= SCALE; y2b *= SCALE; }
        } else {
            y1a = x1a; y1b = x1b; y2a = x2a; y2b = x2b;
        }
        size_t base = ((size_t)(bb * N_HEAD + hh) * SEQ + t) * HEAD_DIM;
        uint32_t hi, lo;
        split2(y1a, y1b, hi, lo);
        *(uint32_t*)(dh + base + jp)      = hi;
        *(uint32_t*)(dl + base + jp)      = lo;
        split2(y2a, y2b, hi, lo);
        *(uint32_t*)(dh + base + jp + 64) = hi;
        *(uint32_t*)(dl + base + jp + 64) = lo;
    }
}

// ---------------------------------------------------------------------------
// MMA flash attention over PREPPED bf16 operands (unchanged from R6).
// ---------------------------------------------------------------------------
#define FA_TQ 128
#define FA_TK 64
#define FA_ROWB   272
#define FA_QHI  0
#define FA_QLO  34816
#define FA_KV0  69632                 // per buffer: KHI,+17408 KLO,+34816 VHI,+52224 VLO
#define FA_KVSZ 69632
#define FA_SMEM 208896

__device__ __forceinline__ void fa_load_kv(uint32_t buf, size_t bh_elem, int k0, int tid)
{
    size_t gbase = bh_elem + (size_t)k0 * HEAD_DIM;
    for (int i = tid; i < FA_TK * 16; i += 256) {
        int row = i >> 4, c = i & 15;
        uint32_t soff = (uint32_t)(row * FA_ROWB + c * 16);
        size_t   goff = gbase + (size_t)row * HEAD_DIM + c * 8;
        cp_async16(buf + soff,         g_Khi + goff);
        cp_async16(buf + 17408 + soff, g_Klo + goff);
        cp_async16(buf + 34816 + soff, g_Vhi + goff);
        cp_async16(buf + 52224 + soff, g_Vlo + goff);
    }
}

__global__ __launch_bounds__(256, 1) void flash_attn_mma_kernel()
{
    extern __shared__ __align__(128) char sm[];
    const uint32_t sbase = smem_to_u32(sm);

    const int tid  = threadIdx.x;
    const int lane = tid & 31;
    const int wid  = tid >> 5;
    const int qt   = (gridDim.x - 1) - blockIdx.x;   // heavy tiles first
    const int q0   = qt * FA_TQ;
    const int b    = blockIdx.y >> 4;
    const int h    = blockIdx.y & 15;

    const size_t bh_elem = (size_t)(b * N_HEAD + h) * SEQ * HEAD_DIM;

    // ---- Q tile load (prepped bf16 hi/lo) ----
    {
        size_t qbase = bh_elem + (size_t)q0 * HEAD_DIM;
        for (int i = tid; i < FA_TQ * 16; i += 256) {
            int row = i >> 4, c = i & 15;
            uint32_t soff = (uint32_t)(row * FA_ROWB + c * 16);
            size_t   goff = qbase + (size_t)row * HEAD_DIM + c * 8;
            cp_async16(sbase + FA_QHI + soff, g_Qhi + goff);
            cp_async16(sbase + FA_QLO + soff, g_Qlo + goff);
        }
    }
    const int ktmax = 2 * qt + 1;
    fa_load_kv(sbase + FA_KV0, bh_elem, 0, tid);
    CP_ASYNC_COMMIT();                               // group: Q + KV0
    fa_load_kv(sbase + FA_KV0 + FA_KVSZ, bh_elem, FA_TK, tid);  // ktmax >= 1 always
    CP_ASYNC_COMMIT();                               // group: KV1

    float oacc[16][4];
#pragma unroll
    for (int ni = 0; ni < 16; ++ni)
#pragma unroll
        for (int r = 0; r < 4; ++r) oacc[ni][r] = 0.f;
    float m0 = -1e30f, m1 = -1e30f, l0 = 0.f, l1 = 0.f;

    const int gid = lane >> 2, tig = lane & 3;
    const int lrowA = lane & 15, lcolA = lane >> 4;
    const int bg = lane >> 3, blr = lane & 7;
    const int wrow_lo = q0 + wid * 16;

    for (int kt = 0; kt <= ktmax; ++kt) {
        const int k0 = kt * FA_TK;
        const uint32_t buf = sbase + FA_KV0 + (uint32_t)(kt & 1) * FA_KVSZ;
        CP_ASYNC_WAIT_1();          // KV[kt] (and Q) resident; KV[kt+1] may pend
        __syncthreads();

        if (k0 <= wrow_lo + 15) {   // warp-level causal skip
            // ---- S = Q @ K^T, bf16x3 ----
            float sacc[8][4];
#pragma unroll
            for (int ni = 0; ni < 8; ++ni)
#pragma unroll
                for (int r = 0; r < 4; ++r) sacc[ni][r] = 0.f;

#pragma unroll
            for (int ks = 0; ks < 8; ++ks) {
                uint32_t qh[4], ql[4];
                uint32_t qoff = (uint32_t)((wid * 16 + lrowA) * FA_ROWB
                                           + (ks * 16 + lcolA * 8) * 2);
                ldsm4(qh, sbase + FA_QHI + qoff);
                ldsm4(ql, sbase + FA_QLO + qoff);
                uint32_t kh[4][4], kl[4][4];
#pragma unroll
                for (int np = 0; np < 4; ++np) {
                    uint32_t koff = (uint32_t)((np * 16 + (bg >> 1) * 8 + blr) * FA_ROWB
                                               + (ks * 16 + (bg & 1) * 8) * 2);
                    ldsm4(kh[np], buf + koff);
                    ldsm4(kl[np], buf + 17408 + koff);
                }
#pragma unroll
                for (int ni = 0; ni < 8; ++ni) {
                    int np = ni >> 1, pr = (ni & 1) * 2;
                    mma_bf16(sacc[ni], qh, kh[np][pr], kh[np][pr + 1]);
                    mma_bf16(sacc[ni], qh, kl[np][pr], kl[np][pr + 1]);
                    mma_bf16(sacc[ni], ql, kh[np][pr], kh[np][pr + 1]);
                }
            }

            // ---- causal mask (partial tiles only) ----
            const int row0 = wrow_lo + gid, row1 = row0 + 8;
            if (k0 + FA_TK - 1 > q0) {
#pragma unroll
                for (int ni = 0; ni < 8; ++ni) {
                    int col = k0 + ni * 8 + tig * 2;
                    if (col     > row0) sacc[ni][0] = -1e30f;
                    if (col + 1 > row0) sacc[ni][1] = -1e30f;
                    if (col     > row1) sacc[ni][2] = -1e30f;
                    if (col + 1 > row1) sacc[ni][3] = -1e30f;
                }
            }

            // ---- online softmax ----
            float mx0 = -1e30f, mx1 = -1e30f;
#pragma unroll
            for (int ni = 0; ni < 8; ++ni) {
                mx0 = fmaxf(mx0, fmaxf(sacc[ni][0], sacc[ni][1]));
                mx1 = fmaxf(mx1, fmaxf(sacc[ni][2], sacc[ni][3]));
            }
#pragma unroll
            for (int off = 1; off < 4; off <<= 1) {
                mx0 = fmaxf(mx0, __shfl_xor_sync(0xffffffffu, mx0, off));
                mx1 = fmaxf(mx1, __shfl_xor_sync(0xffffffffu, mx1, off));
            }
            float mn0 = fmaxf(m0, mx0), mn1 = fmaxf(m1, mx1);
            float a0 = __expf(m0 - mn0), a1 = __expf(m1 - mn1);
            m0 = mn0; m1 = mn1;
            float sum0 = 0.f, sum1 = 0.f;
#pragma unroll
            for (int ni = 0; ni < 8; ++ni) {
                sacc[ni][0] = __expf(sacc[ni][0] - mn0);
                sacc[ni][1] = __expf(sacc[ni][1] - mn0);
                sacc[ni][2] = __expf(sacc[ni][2] - mn1);
                sacc[ni][3] = __expf(sacc[ni][3] - mn1);
                sum0 += sacc[ni][0] + sacc[ni][1];
                sum1 += sacc[ni][2] + sacc[ni][3];
            }
#pragma unroll
            for (int off = 1; off < 4; off <<= 1) {
                sum0 += __shfl_xor_sync(0xffffffffu, sum0, off);
                sum1 += __shfl_xor_sync(0xffffffffu, sum1, off);
            }
            l0 = l0 * a0 + sum0;
            l1 = l1 * a1 + sum1;
#pragma unroll
            for (int ni = 0; ni < 16; ++ni) {
                oacc[ni][0] *= a0; oacc[ni][1] *= a0;
                oacc[ni][2] *= a1; oacc[ni][3] *= a1;
            }

            // ---- O += P @ V, bf16x3 (V via trans ldmatrix) ----
            const uint32_t vhi = buf + 34816, vlo = buf + 52224;
#pragma unroll
            for (int kc = 0; kc < 4; ++kc) {
                uint32_t ah[4], al[4];
                split2(sacc[2 * kc][0],     sacc[2 * kc][1],     ah[0], al[0]);
                split2(sacc[2 * kc][2],     sacc[2 * kc][3],     ah[1], al[1]);
                split2(sacc[2 * kc + 1][0], sacc[2 * kc + 1][1], ah[2], al[2]);
                split2(sacc[2 * kc + 1][2], sacc[2 * kc + 1][3], ah[3], al[3]);
#pragma unroll
                for (int np = 0; np < 8; ++np) {
                    uint32_t vh[4], vl[4];
                    uint32_t voff = (uint32_t)((kc * 16 + (lane & 15)) * FA_ROWB
                                               + (np * 16 + (lane >> 4) * 8) * 2);
                    ldsm4t(vh, vhi + voff);
                    ldsm4t(vl, vlo + voff);
#pragma unroll
                    for (int q = 0; q < 2; ++q) {
                        int ni = np * 2 + q, pr = q * 2;
                        mma_bf16(oacc[ni], ah, vh[pr], vh[pr + 1]);
                        mma_bf16(oacc[ni], ah, vl[pr], vl[pr + 1]);
                        mma_bf16(oacc[ni], al, vh[pr], vh[pr + 1]);
                    }
                }
            }
        }

        __syncthreads();            // all warps done reading buf before overwrite
        if (kt + 2 <= ktmax)
            fa_load_kv(sbase + FA_KV0 + (uint32_t)(kt & 1) * FA_KVSZ,
                       bh_elem, (kt + 2) * FA_TK, tid);
        CP_ASYNC_COMMIT();
    }

    // ---- epilogue: normalize, split to bf16 hi/lo, store ----
    {
        float inv0 = 1.f / l0, inv1 = 1.f / l1;
        int t0 = wrow_lo + gid;
        size_t base0 = (size_t)(b * SEQ + t0) * D_MODEL + h * HEAD_DIM;
        size_t base1 = (size_t)(b * SEQ + t0 + 8) * D_MODEL + h * HEAD_DIM;
#pragma unroll
        for (int ni = 0; ni < 16; ++ni) {
            int col = ni * 8 + tig * 2;
            uint32_t hi, lo;
            split2(oacc[ni][0] * inv0, oacc[ni][1] * inv0, hi, lo);
            *(uint32_t*)(g_Ahi + base0 + col) = hi;
            *(uint32_t*)(g_Alo + base0 + col) = lo;
            split2(oacc[ni][2] * inv1, oacc[ni][3] * inv1, hi, lo);
            *(uint32_t*)(g_Ahi + base1 + col) = hi;
            *(uint32_t*)(g_Alo + base1 + col) = lo;
        }
    }
}

// ---------------------------------------------------------------------------
extern "C" void kernel_launch(void* const* d_in, const int* in_sizes, int n_in,
                              void* d_out, int out_size)
{
    (void)in_sizes; (void)n_in; (void)out_size;
    const float* x     = (const float*)d_in[0];
    const float* Wqkv  = (const float*)d_in[2];
    const float* bqkv  = (const float*)d_in[3];
    const float* Wproj = (const float*)d_in[4];
    const float* bproj = (const float*)d_in[5];
    float* out = (float*)d_out;

    void *ahi_p, *alo_p, *wq_hi_p, *wq_lo_p, *wp_hi_p, *wp_lo_p;
    cudaGetSymbolAddress(&ahi_p, g_Ahi);
    cudaGetSymbolAddress(&alo_p, g_Alo);
    cudaGetSymbolAddress(&wq_hi_p, g_Wqkv_hi);
    cudaGetSymbolAddress(&wq_lo_p, g_Wqkv_lo);
    cudaGetSymbolAddress(&wp_hi_p, g_Wproj_hi);
    cudaGetSymbolAddress(&wp_lo_p, g_Wproj_lo);
    __nv_bfloat16* Ahi = (__nv_bfloat16*)ahi_p;
    __nv_bfloat16* Alo = (__nv_bfloat16*)alo_p;
    __nv_bfloat16* WqH = (__nv_bfloat16*)wq_hi_p;
    __nv_bfloat16* WqL = (__nv_bfloat16*)wq_lo_p;
    __nv_bfloat16* WpH = (__nv_bfloat16*)wp_hi_p;
    __nv_bfloat16* WpL = (__nv_bfloat16*)wp_lo_p;

    cudaFuncSetAttribute(gemm_bf16x3_kernel,
                         cudaFuncAttributeMaxDynamicSharedMemorySize, GB_SMEM);
    cudaFuncSetAttribute(flash_attn_mma_kernel,
                         cudaFuncAttributeMaxDynamicSharedMemorySize, FA_SMEM);

    const int M = BATCH * SEQ;               // 4096
    const int nelem = M * D_MODEL;

    // 0) RoPE cos/sin table
    rope_table_kernel<<<SEQ * 64 / 256, 256>>>();

    // 1) split activations x -> (Ahi, Alo)
    split_kernel<<<(nelem / 4 + 255) / 256, 256>>>(x, Ahi, Alo, nelem / 4);

    // 2) weight transpose + split
    transpose_split_kernel<<<dim3(3 * D_MODEL / 64, D_MODEL / 64), 256>>>(
        Wqkv, WqH, WqL, D_MODEL, 3 * D_MODEL);
    transpose_split_kernel<<<dim3(D_MODEL / 64, D_MODEL / 64), 256>>>(
        Wproj, WpH, WpL, D_MODEL, D_MODEL);

    // 3) QKV projection with FUSED rope/split epilogue (no fp32 qkv, no prep)
    gemm_bf16x3_kernel<<<dim3(3 * D_MODEL / 128, M / 128), 256, GB_SMEM>>>(
        Ahi, Alo, WqH, WqL, bqkv, nullptr, M, 3 * D_MODEL, D_MODEL, 1);

    // 4) MMA flash attention on prepped operands (writes bf16 hi/lo directly)
    flash_attn_mma_kernel<<<dim3(SEQ / FA_TQ, BATCH * N_HEAD), 256, FA_SMEM>>>();

    // 5) output projection (plain epilogue)
    gemm_bf16x3_kernel<<<dim3(D_MODEL / 128, M / 128), 256, GB_SMEM>>>(
        Ahi, Alo, WpH, WpL, bproj, out, M, D_MODEL, D_MODEL, 0);
}

// round 8
// speedup vs baseline: 2.7116x; 1.0424x over previous
#include <cuda_runtime.h>
#include <cuda_bf16.h>
#include <math.h>
#include <stdint.h>

#define D_MODEL 2048
#define N_HEAD  16
#define HEAD_DIM 128
#define BATCH   2
#define SEQ     2048

// ---------------------------------------------------------------------------
// Static scratch (no cudaMalloc anywhere)
// ---------------------------------------------------------------------------
static __device__ float g_rope[(size_t)SEQ * 128];                // cos/sin table
static __device__ __nv_bfloat16 g_Ahi[(size_t)BATCH * SEQ * D_MODEL];
static __device__ __nv_bfloat16 g_Alo[(size_t)BATCH * SEQ * D_MODEL];
static __device__ __nv_bfloat16 g_Wqkv_hi[(size_t)3 * D_MODEL * D_MODEL]; // [N][K]
static __device__ __nv_bfloat16 g_Wqkv_lo[(size_t)3 * D_MODEL * D_MODEL];
static __device__ __nv_bfloat16 g_Wproj_hi[(size_t)D_MODEL * D_MODEL];
static __device__ __nv_bfloat16 g_Wproj_lo[(size_t)D_MODEL * D_MODEL];
// head-major prepped attention operands: [b][h][t][d]
static __device__ __nv_bfloat16 g_Qhi[(size_t)BATCH * SEQ * D_MODEL];
static __device__ __nv_bfloat16 g_Qlo[(size_t)BATCH * SEQ * D_MODEL];
static __device__ __nv_bfloat16 g_Khi[(size_t)BATCH * SEQ * D_MODEL];
static __device__ __nv_bfloat16 g_Klo[(size_t)BATCH * SEQ * D_MODEL];
static __device__ __nv_bfloat16 g_Vhi[(size_t)BATCH * SEQ * D_MODEL];
static __device__ __nv_bfloat16 g_Vlo[(size_t)BATCH * SEQ * D_MODEL];

// ---------------------------------------------------------------------------
// PTX helpers (sm_80+ subset: cp.async / ldmatrix / mma.sync)
// ---------------------------------------------------------------------------
__device__ __forceinline__ uint32_t smem_to_u32(const void* smem_ptr) {
    uint32_t addr;
    asm("{ .reg .u64 tmp; cvta.to.shared.u64 tmp, %1; cvt.u32.u64 %0, tmp; }"
        : "=r"(addr) : "l"(smem_ptr));
    return addr;
}

__device__ __forceinline__ void cp_async16(uint32_t smem_dst, const void* gmem_src) {
    asm volatile("cp.async.cg.shared.global.L2::128B [%0], [%1], 16;"
                 :: "r"(smem_dst), "l"(__cvta_generic_to_global(gmem_src)));
}
#define CP_ASYNC_COMMIT() asm volatile("cp.async.commit_group;" ::: "memory")
#define CP_ASYNC_WAIT_1() asm volatile("cp.async.wait_group 1;" ::: "memory")

__device__ __forceinline__ void ldsm4(uint32_t* r, uint32_t addr) {
    asm volatile("ldmatrix.sync.aligned.m8n8.x4.shared.b16 {%0,%1,%2,%3}, [%4];"
                 : "=r"(r[0]), "=r"(r[1]), "=r"(r[2]), "=r"(r[3]) : "r"(addr));
}
__device__ __forceinline__ void ldsm4t(uint32_t* r, uint32_t addr) {
    asm volatile("ldmatrix.sync.aligned.m8n8.x4.trans.shared.b16 {%0,%1,%2,%3}, [%4];"
                 : "=r"(r[0]), "=r"(r[1]), "=r"(r[2]), "=r"(r[3]) : "r"(addr));
}

__device__ __forceinline__ void mma_bf16(float* c, const uint32_t* a,
                                         uint32_t b0, uint32_t b1) {
    asm volatile(
        "mma.sync.aligned.m16n8k16.row.col.f32.bf16.bf16.f32 "
        "{%0,%1,%2,%3}, {%4,%5,%6,%7}, {%8,%9}, {%0,%1,%2,%3};"
        : "+f"(c[0]), "+f"(c[1]), "+f"(c[2]), "+f"(c[3])
        : "r"(a[0]), "r"(a[1]), "r"(a[2]), "r"(a[3]), "r"(b0), "r"(b1));
}

// pack (s0 -> low bf16, s1 -> high bf16) into hi; residuals into lo.
__device__ __forceinline__ void split2(float s0, float s1, uint32_t& hi, uint32_t& lo) {
    asm("cvt.rn.bf16x2.f32 %0, %1, %2;" : "=r"(hi) : "f"(s1), "f"(s0));
    __nv_bfloat162 hv = *reinterpret_cast<__nv_bfloat162*>(&hi);
    float r0 = s0 - __bfloat162float(hv.x);
    float r1 = s1 - __bfloat162float(hv.y);
    asm("cvt.rn.bf16x2.f32 %0, %1, %2;" : "=r"(lo) : "f"(r1), "f"(r0));
}

// ---------------------------------------------------------------------------
// RoPE table
// ---------------------------------------------------------------------------
__global__ void rope_table_kernel()
{
    const float RATE_C = 0.14391156831212787f; // ln(10000)/64
    int i = blockIdx.x * blockDim.x + threadIdx.x;  // t*64 + j
    int t = i >> 6, j = i & 63;
    float rate = expf(-RATE_C * (float)j);
    float sv, cv;
    sincosf((float)t * rate, &sv, &cv);
    g_rope[t * 128 + j]      = cv;
    g_rope[t * 128 + 64 + j] = sv;
}

// ---------------------------------------------------------------------------
// Elementwise split: fp32 -> (hi, lo) bf16 pair.
// ---------------------------------------------------------------------------
__global__ void split_kernel(const float* __restrict__ X,
                             __nv_bfloat16* __restrict__ hi,
                             __nv_bfloat16* __restrict__ lo, int n4)
{
    int i = blockIdx.x * blockDim.x + threadIdx.x;
    if (i >= n4) return;
    float4 v = *(const float4*)(X + (size_t)i * 4);
    __nv_bfloat16 h[4], l[4];
    float vv[4] = {v.x, v.y, v.z, v.w};
#pragma unroll
    for (int j = 0; j < 4; ++j) {
        h[j] = __float2bfloat16(vv[j]);
        l[j] = __float2bfloat16(vv[j] - __bfloat162float(h[j]));
    }
    *(uint2*)(hi + (size_t)i * 4) = *(uint2*)h;
    *(uint2*)(lo + (size_t)i * 4) = *(uint2*)l;
}

// ---------------------------------------------------------------------------
// Transpose + split: W[K,N] fp32 -> Thi/Tlo [N,K] bf16 (K-major for MMA B).
// ---------------------------------------------------------------------------
__global__ __launch_bounds__(256) void transpose_split_kernel(
    const float* __restrict__ W,
    __nv_bfloat16* __restrict__ Thi, __nv_bfloat16* __restrict__ Tlo,
    int K, int N)
{
    __shared__ float tile[64][65];
    const int k0 = blockIdx.y * 64;
    const int n0 = blockIdx.x * 64;
    const int tid = threadIdx.x;

#pragma unroll
    for (int j = 0; j < 4; ++j) {
        int idx = tid + j * 256;
        int r  = idx >> 4;
        int c4 = (idx & 15) * 4;
        float4 v = *(const float4*)(W + (size_t)(k0 + r) * N + n0 + c4);
        tile[r][c4 + 0] = v.x; tile[r][c4 + 1] = v.y;
        tile[r][c4 + 2] = v.z; tile[r][c4 + 3] = v.w;
    }
    __syncthreads();

    const int n  = tid >> 2;
    const int ks = (tid & 3) * 16;
    __nv_bfloat16 h[16], l[16];
#pragma unroll
    for (int j = 0; j < 16; ++j) {
        float v = tile[ks + j][n];
        h[j] = __float2bfloat16(v);
        l[j] = __float2bfloat16(v - __bfloat162float(h[j]));
    }
    size_t base = (size_t)(n0 + n) * K + k0 + ks;
    *(uint4*)(Thi + base)     = ((uint4*)h)[0];
    *(uint4*)(Thi + base + 8) = ((uint4*)h)[1];
    *(uint4*)(Tlo + base)     = ((uint4*)l)[0];
    *(uint4*)(Tlo + base + 8) = ((uint4*)l)[1];
}

// ---------------------------------------------------------------------------
// bf16x3 HMMA GEMM, re-tiled: 128 threads = 4 warps in 2x2 grid, warp tile
// 64x64 (128 acc regs; launch_bounds(128,2) allows 256 regs/thread).
// Cuts ldmatrix traffic per MMA by 33% -> smem-BW no longer binding.
// 2-stage cp.async, 2 CTAs/SM (163840 B smem total).
// fuse_qkv == 1: QKV epilogue (rope/scale/split, head-major bf16 hi/lo).
// ---------------------------------------------------------------------------
#define GB_ROWB   80
#define GB_OP     (128 * GB_ROWB)           // 10240 B per operand tile
#define GB_STAGE  (4 * GB_OP)               // 40960 B
#define GB_NSTAGE 2
#define GB_SMEM   (GB_NSTAGE * GB_STAGE)    // 81920 B (>= 128*132*4 = 67584)

__device__ __forceinline__ void gemm_load_stage(
    uint32_t st,
    const __nv_bfloat16* __restrict__ Ahi, const __nv_bfloat16* __restrict__ Alo,
    const __nv_bfloat16* __restrict__ Bhi, const __nv_bfloat16* __restrict__ Blo,
    int bm, int bn, int k0, int K, int tid)
{
#pragma unroll
    for (int j = 0; j < 4; ++j) {
        int idx = tid + j * 128;            // 0..511
        int row = idx >> 2;                 // 0..127
        int c   = idx & 3;                  // 16B chunk within 64B row
        uint32_t off = (uint32_t)(row * GB_ROWB + c * 16);
        size_t ga = (size_t)(bm + row) * K + k0 + c * 8;
        size_t gb = (size_t)(bn + row) * K + k0 + c * 8;
        cp_async16(st + off,              Ahi + ga);
        cp_async16(st + GB_OP + off,      Alo + ga);
        cp_async16(st + 2 * GB_OP + off,  Bhi + gb);
        cp_async16(st + 3 * GB_OP + off,  Blo + gb);
    }
}

__global__ __launch_bounds__(128, 2) void gemm_bf16x3_kernel(
    const __nv_bfloat16* __restrict__ Ahi, const __nv_bfloat16* __restrict__ Alo,
    const __nv_bfloat16* __restrict__ Bhi, const __nv_bfloat16* __restrict__ Blo,
    const float* __restrict__ bias, float* __restrict__ C,
    int M, int N, int K, int fuse_qkv)
{
    extern __shared__ __align__(128) char smem[];
    const uint32_t sbase = smem_to_u32(smem);
    const int tid  = threadIdx.x;
    const int lane = tid & 31;
    const int wid  = tid >> 5;              // 0..3
    const int wm   = wid >> 1;              // 0..1 (64-row stripes)
    const int wn   = wid & 1;               // 0..1 (64-col stripes)
    const int bm   = blockIdx.y * 128;
    const int bn   = blockIdx.x * 128;

    float acc[4][8][4];
#pragma unroll
    for (int mi = 0; mi < 4; ++mi)
#pragma unroll
        for (int ni = 0; ni < 8; ++ni)
#pragma unroll
            for (int r = 0; r < 4; ++r) acc[mi][ni][r] = 0.f;

    const int nk = K / 32;

    gemm_load_stage(sbase,            Ahi, Alo, Bhi, Blo, bm, bn, 0,  K, tid);
    CP_ASYNC_COMMIT();
    gemm_load_stage(sbase + GB_STAGE, Ahi, Alo, Bhi, Blo, bm, bn, 32, K, tid);
    CP_ASYNC_COMMIT();

    const int lrowA = lane & 15, lcolA = lane >> 4;
    const int bg    = lane >> 3, blr  = lane & 7;

    for (int i = 0; i < nk; ++i) {
        const uint32_t st = sbase + (uint32_t)(i % GB_NSTAGE) * GB_STAGE;
        CP_ASYNC_WAIT_1();
        __syncthreads();

        const uint32_t aHi = st;
        const uint32_t aLo = st + GB_OP;
        const uint32_t bHi = st + 2 * GB_OP;
        const uint32_t bLo = st + 3 * GB_OP;

#pragma unroll
        for (int ks = 0; ks < 2; ++ks) {
            uint32_t ah[4][4], al[4][4];
#pragma unroll
            for (int mi = 0; mi < 4; ++mi) {
                uint32_t off = (uint32_t)((wm * 64 + mi * 16 + lrowA) * GB_ROWB
                                          + (ks * 2 + lcolA) * 16);
                ldsm4(ah[mi], aHi + off);
                ldsm4(al[mi], aLo + off);
            }
#pragma unroll
            for (int np = 0; np < 4; ++np) {
                uint32_t bh[4], bl[4];
                uint32_t off = (uint32_t)((wn * 64 + np * 16 + (bg >> 1) * 8 + blr) * GB_ROWB
                                          + (ks * 2 + (bg & 1)) * 16);
                ldsm4(bh, bHi + off);
                ldsm4(bl, bLo + off);
#pragma unroll
                for (int mi = 0; mi < 4; ++mi)
#pragma unroll
                    for (int q = 0; q < 2; ++q) {
                        int ni = np * 2 + q, pr = q * 2;
                        mma_bf16(acc[mi][ni], ah[mi], bh[pr], bh[pr + 1]);
                        mma_bf16(acc[mi][ni], ah[mi], bl[pr], bl[pr + 1]);
                        mma_bf16(acc[mi][ni], al[mi], bh[pr], bh[pr + 1]);
                    }
            }
        }

        __syncthreads();
        if (i + 2 < nk) {
            gemm_load_stage(sbase + (uint32_t)((i + 2) % GB_NSTAGE) * GB_STAGE,
                            Ahi, Alo, Bhi, Blo, bm, bn, (i + 2) * 32, K, tid);
        }
        CP_ASYNC_COMMIT();
    }

    const int gid = lane >> 2, tig = lane & 3;

    if (fuse_qkv == 0) {
        // ---- plain epilogue: bias + fp32 store ----
#pragma unroll
        for (int mi = 0; mi < 4; ++mi)
#pragma unroll
            for (int ni = 0; ni < 8; ++ni) {
                int row = bm + wm * 64 + mi * 16 + gid;
                int col = bn + wn * 64 + ni * 8 + tig * 2;
                float2 bv = *(const float2*)(bias + col);
                float2 v0 = make_float2(acc[mi][ni][0] + bv.x, acc[mi][ni][1] + bv.y);
                float2 v1 = make_float2(acc[mi][ni][2] + bv.x, acc[mi][ni][3] + bv.y);
                *(float2*)(C + (size_t)row * N + col)       = v0;
                *(float2*)(C + (size_t)(row + 8) * N + col) = v1;
            }
        return;
    }

    // ---- fused QKV epilogue: rope/scale/split, head-major bf16 hi/lo ----
    float* Cs = (float*)smem;                 // 128 x 132 fp32, reuses stages
#pragma unroll
    for (int mi = 0; mi < 4; ++mi)
#pragma unroll
        for (int ni = 0; ni < 8; ++ni) {
            int row = wm * 64 + mi * 16 + gid;
            int col = wn * 64 + ni * 8 + tig * 2;
            float2 bv = *(const float2*)(bias + bn + col);
            Cs[row * 132 + col]           = acc[mi][ni][0] + bv.x;
            Cs[row * 132 + col + 1]       = acc[mi][ni][1] + bv.y;
            Cs[(row + 8) * 132 + col]     = acc[mi][ni][2] + bv.x;
            Cs[(row + 8) * 132 + col + 1] = acc[mi][ni][3] + bv.y;
        }
    __syncthreads();

    const int sel = bn >> 11;                 // 0=Q, 1=K, 2=V
    const int hh  = (bn & 2047) >> 7;         // head
    __nv_bfloat16 *dh, *dl;
    if (sel == 0)      { dh = g_Qhi; dl = g_Qlo; }
    else if (sel == 1) { dh = g_Khi; dl = g_Klo; }
    else               { dh = g_Vhi; dl = g_Vlo; }
    const float SCALE = 0.08838834764831845f; // 1/sqrt(128)

    for (int i = tid; i < 128 * 32; i += 128) {
        int row = i >> 5, jp = (i & 31) * 2;  // two adjacent j's: jp, jp+1
        int tg = bm + row, t = tg & (SEQ - 1), bb = tg >> 11;
        float x1a = Cs[row * 132 + jp],      x1b = Cs[row * 132 + jp + 1];
        float x2a = Cs[row * 132 + jp + 64], x2b = Cs[row * 132 + jp + 65];
        float y1a, y1b, y2a, y2b;
        if (sel < 2) {
            float cva = g_rope[t * 128 + jp],     sva = g_rope[t * 128 + 64 + jp];
            float cvb = g_rope[t * 128 + jp + 1], svb = g_rope[t * 128 + 64 + jp + 1];
            y1a = x1a * cva - x2a * sva;  y2a = x1a * sva + x2a * cva;
            y1b = x1b * cvb - x2b * svb;  y2b = x1b * svb + x2b * cvb;
            if (sel == 0) { y1a *= SCALE; y2a *= SCALE; y1b *= SCALE; y2b *= SCALE; }
        } else {
            y1a = x1a; y1b = x1b; y2a = x2a; y2b = x2b;
        }
        size_t base = ((size_t)(bb * N_HEAD + hh) * SEQ + t) * HEAD_DIM;
        uint32_t hi, lo;
        split2(y1a, y1b, hi, lo);
        *(uint32_t*)(dh + base + jp)      = hi;
        *(uint32_t*)(dl + base + jp)      = lo;
        split2(y2a, y2b, hi, lo);
        *(uint32_t*)(dh + base + jp + 64) = hi;
        *(uint32_t*)(dl + base + jp + 64) = lo;
    }
}

// ---------------------------------------------------------------------------
// MMA flash attention over PREPPED bf16 operands (unchanged from R7).
// ---------------------------------------------------------------------------
#define FA_TQ 128
#define FA_TK 64
#define FA_ROWB   272
#define FA_QHI  0
#define FA_QLO  34816
#define FA_KV0  69632                 // per buffer: KHI,+17408 KLO,+34816 VHI,+52224 VLO
#define FA_KVSZ 69632
#define FA_SMEM 208896

__device__ __forceinline__ void fa_load_kv(uint32_t buf, size_t bh_elem, int k0, int tid)
{
    size_t gbase = bh_elem + (size_t)k0 * HEAD_DIM;
    for (int i = tid; i < FA_TK * 16; i += 256) {
        int row = i >> 4, c = i & 15;
        uint32_t soff = (uint32_t)(row * FA_ROWB + c * 16);
        size_t   goff = gbase + (size_t)row * HEAD_DIM + c * 8;
        cp_async16(buf + soff,         g_Khi + goff);
        cp_async16(buf + 17408 + soff, g_Klo + goff);
        cp_async16(buf + 34816 + soff, g_Vhi + goff);
        cp_async16(buf + 52224 + soff, g_Vlo + goff);
    }
}

__global__ __launch_bounds__(256, 1) void flash_attn_mma_kernel()
{
    extern __shared__ __align__(128) char sm[];
    const uint32_t sbase = smem_to_u32(sm);

    const int tid  = threadIdx.x;
    const int lane = tid & 31;
    const int wid  = tid >> 5;
    const int qt   = (gridDim.x - 1) - blockIdx.x;   // heavy tiles first
    const int q0   = qt * FA_TQ;
    const int b    = blockIdx.y >> 4;
    const int h    = blockIdx.y & 15;

    const size_t bh_elem = (size_t)(b * N_HEAD + h) * SEQ * HEAD_DIM;

    // ---- Q tile load (prepped bf16 hi/lo) ----
    {
        size_t qbase = bh_elem + (size_t)q0 * HEAD_DIM;
        for (int i = tid; i < FA_TQ * 16; i += 256) {
            int row = i >> 4, c = i & 15;
            uint32_t soff = (uint32_t)(row * FA_ROWB + c * 16);
            size_t   goff = qbase + (size_t)row * HEAD_DIM + c * 8;
            cp_async16(sbase + FA_QHI + soff, g_Qhi + goff);
            cp_async16(sbase + FA_QLO + soff, g_Qlo + goff);
        }
    }
    const int ktmax = 2 * qt + 1;
    fa_load_kv(sbase + FA_KV0, bh_elem, 0, tid);
    CP_ASYNC_COMMIT();                               // group: Q + KV0
    fa_load_kv(sbase + FA_KV0 + FA_KVSZ, bh_elem, FA_TK, tid);  // ktmax >= 1 always
    CP_ASYNC_COMMIT();                               // group: KV1

    float oacc[16][4];
#pragma unroll
    for (int ni = 0; ni < 16; ++ni)
#pragma unroll
        for (int r = 0; r < 4; ++r) oacc[ni][r] = 0.f;
    float m0 = -1e30f, m1 = -1e30f, l0 = 0.f, l1 = 0.f;

    const int gid = lane >> 2, tig = lane & 3;
    const int lrowA = lane & 15, lcolA = lane >> 4;
    const int bg = lane >> 3, blr = lane & 7;
    const int wrow_lo = q0 + wid * 16;

    for (int kt = 0; kt <= ktmax; ++kt) {
        const int k0 = kt * FA_TK;
        const uint32_t buf = sbase + FA_KV0 + (uint32_t)(kt & 1) * FA_KVSZ;
        CP_ASYNC_WAIT_1();          // KV[kt] (and Q) resident; KV[kt+1] may pend
        __syncthreads();

        if (k0 <= wrow_lo + 15) {   // warp-level causal skip
            // ---- S = Q @ K^T, bf16x3 ----
            float sacc[8][4];
#pragma unroll
            for (int ni = 0; ni < 8; ++ni)
#pragma unroll
                for (int r = 0; r < 4; ++r) sacc[ni][r] = 0.f;

#pragma unroll
            for (int ks = 0; ks < 8; ++ks) {
                uint32_t qh[4], ql[4];
                uint32_t qoff = (uint32_t)((wid * 16 + lrowA) * FA_ROWB
                                           + (ks * 16 + lcolA * 8) * 2);
                ldsm4(qh, sbase + FA_QHI + qoff);
                ldsm4(ql, sbase + FA_QLO + qoff);
                uint32_t kh[4][4], kl[4][4];
#pragma unroll
                for (int np = 0; np < 4; ++np) {
                    uint32_t koff = (uint32_t)((np * 16 + (bg >> 1) * 8 + blr) * FA_ROWB
                                               + (ks * 16 + (bg & 1) * 8) * 2);
                    ldsm4(kh[np], buf + koff);
                    ldsm4(kl[np], buf + 17408 + koff);
                }
#pragma unroll
                for (int ni = 0; ni < 8; ++ni) {
                    int np = ni >> 1, pr = (ni & 1) * 2;
                    mma_bf16(sacc[ni], qh, kh[np][pr], kh[np][pr + 1]);
                    mma_bf16(sacc[ni], qh, kl[np][pr], kl[np][pr + 1]);
                    mma_bf16(sacc[ni], ql, kh[np][pr], kh[np][pr + 1]);
                }
            }

            // ---- causal mask (partial tiles only) ----
            const int row0 = wrow_lo + gid, row1 = row0 + 8;
            if (k0 + FA_TK - 1 > q0) {
#pragma unroll
                for (int ni = 0; ni < 8; ++ni) {
                    int col = k0 + ni * 8 + tig * 2;
                    if (col     > row0) sacc[ni][0] = -1e30f;
                    if (col + 1 > row0) sacc[ni][1] = -1e30f;
                    if (col     > row1) sacc[ni][2] = -1e30f;
                    if (col + 1 > row1) sacc[ni][3] = -1e30f;
                }
            }

            // ---- online softmax ----
            float mx0 = -1e30f, mx1 = -1e30f;
#pragma unroll
            for (int ni = 0; ni < 8; ++ni) {
                mx0 = fmaxf(mx0, fmaxf(sacc[ni][0], sacc[ni][1]));
                mx1 = fmaxf(mx1, fmaxf(sacc[ni][2], sacc[ni][3]));
            }
#pragma unroll
            for (int off = 1; off < 4; off <<= 1) {
                mx0 = fmaxf(mx0, __shfl_xor_sync(0xffffffffu, mx0, off));
                mx1 = fmaxf(mx1, __shfl_xor_sync(0xffffffffu, mx1, off));
            }
            float mn0 = fmaxf(m0, mx0), mn1 = fmaxf(m1, mx1);
            float a0 = __expf(m0 - mn0), a1 = __expf(m1 - mn1);
            m0 = mn0; m1 = mn1;
            float sum0 = 0.f, sum1 = 0.f;
#pragma unroll
            for (int ni = 0; ni < 8; ++ni) {
                sacc[ni][0] = __expf(sacc[ni][0] - mn0);
                sacc[ni][1] = __expf(sacc[ni][1] - mn0);
                sacc[ni][2] = __expf(sacc[ni][2] - mn1);
                sacc[ni][3] = __expf(sacc[ni][3] - mn1);
                sum0 += sacc[ni][0] + sacc[ni][1];
                sum1 += sacc[ni][2] + sacc[ni][3];
            }
#pragma unroll
            for (int off = 1; off < 4; off <<= 1) {
                sum0 += __shfl_xor_sync(0xffffffffu, sum0, off);
                sum1 += __shfl_xor_sync(0xffffffffu, sum1, off);
            }
            l0 = l0 * a0 + sum0;
            l1 = l1 * a1 + sum1;
#pragma unroll
            for (int ni = 0; ni < 16; ++ni) {
                oacc[ni][0] *= a0; oacc[ni][1] *= a0;
                oacc[ni][2] *= a1; oacc[ni][3] *= a1;
            }

            // ---- O += P @ V, bf16x3 (V via trans ldmatrix) ----
            const uint32_t vhi = buf + 34816, vlo = buf + 52224;
#pragma unroll
            for (int kc = 0; kc < 4; ++kc) {
                uint32_t ah[4], al[4];
                split2(sacc[2 * kc][0],     sacc[2 * kc][1],     ah[0], al[0]);
                split2(sacc[2 * kc][2],     sacc[2 * kc][3],     ah[1], al[1]);
                split2(sacc[2 * kc + 1][0], sacc[2 * kc + 1][1], ah[2], al[2]);
                split2(sacc[2 * kc + 1][2], sacc[2 * kc + 1][3], ah[3], al[3]);
#pragma unroll
                for (int np = 0; np < 8; ++np) {
                    uint32_t vh[4], vl[4];
                    uint32_t voff = (uint32_t)((kc * 16 + (lane & 15)) * FA_ROWB
                                               + (np * 16 + (lane >> 4) * 8) * 2);
                    ldsm4t(vh, vhi + voff);
                    ldsm4t(vl, vlo + voff);
#pragma unroll
                    for (int q = 0; q < 2; ++q) {
                        int ni = np * 2 + q, pr = q * 2;
                        mma_bf16(oacc[ni], ah, vh[pr], vh[pr + 1]);
                        mma_bf16(oacc[ni], ah, vl[pr], vl[pr + 1]);
                        mma_bf16(oacc[ni], al, vh[pr], vh[pr + 1]);
                    }
                }
            }
        }

        __syncthreads();            // all warps done reading buf before overwrite
        if (kt + 2 <= ktmax)
            fa_load_kv(sbase + FA_KV0 + (uint32_t)(kt & 1) * FA_KVSZ,
                       bh_elem, (kt + 2) * FA_TK, tid);
        CP_ASYNC_COMMIT();
    }

    // ---- epilogue: normalize, split to bf16 hi/lo, store ----
    {
        float inv0 = 1.f / l0, inv1 = 1.f / l1;
        int t0 = wrow_lo + gid;
        size_t base0 = (size_t)(b * SEQ + t0) * D_MODEL + h * HEAD_DIM;
        size_t base1 = (size_t)(b * SEQ + t0 + 8) * D_MODEL + h * HEAD_DIM;
#pragma unroll
        for (int ni = 0; ni < 16; ++ni) {
            int col = ni * 8 + tig * 2;
            uint32_t hi, lo;
            split2(oacc[ni][0] * inv0, oacc[ni][1] * inv0, hi, lo);
            *(uint32_t*)(g_Ahi + base0 + col) = hi;
            *(uint32_t*)(g_Alo + base0 + col) = lo;
            split2(oacc[ni][2] * inv1, oacc[ni][3] * inv1, hi, lo);
            *(uint32_t*)(g_Ahi + base1 + col) = hi;
            *(uint32_t*)(g_Alo + base1 + col) = lo;
        }
    }
}

// ---------------------------------------------------------------------------
extern "C" void kernel_launch(void* const* d_in, const int* in_sizes, int n_in,
                              void* d_out, int out_size)
{
    (void)in_sizes; (void)n_in; (void)out_size;
    const float* x     = (const float*)d_in[0];
    const float* Wqkv  = (const float*)d_in[2];
    const float* bqkv  = (const float*)d_in[3];
    const float* Wproj = (const float*)d_in[4];
    const float* bproj = (const float*)d_in[5];
    float* out = (float*)d_out;

    void *ahi_p, *alo_p, *wq_hi_p, *wq_lo_p, *wp_hi_p, *wp_lo_p;
    cudaGetSymbolAddress(&ahi_p, g_Ahi);
    cudaGetSymbolAddress(&alo_p, g_Alo);
    cudaGetSymbolAddress(&wq_hi_p, g_Wqkv_hi);
    cudaGetSymbolAddress(&wq_lo_p, g_Wqkv_lo);
    cudaGetSymbolAddress(&wp_hi_p, g_Wproj_hi);
    cudaGetSymbolAddress(&wp_lo_p, g_Wproj_lo);
    __nv_bfloat16* Ahi = (__nv_bfloat16*)ahi_p;
    __nv_bfloat16* Alo = (__nv_bfloat16*)alo_p;
    __nv_bfloat16* WqH = (__nv_bfloat16*)wq_hi_p;
    __nv_bfloat16* WqL = (__nv_bfloat16*)wq_lo_p;
    __nv_bfloat16* WpH = (__nv_bfloat16*)wp_hi_p;
    __nv_bfloat16* WpL = (__nv_bfloat16*)wp_lo_p;

    cudaFuncSetAttribute(gemm_bf16x3_kernel,
                         cudaFuncAttributeMaxDynamicSharedMemorySize, GB_SMEM);
    cudaFuncSetAttribute(flash_attn_mma_kernel,
                         cudaFuncAttributeMaxDynamicSharedMemorySize, FA_SMEM);

    const int M = BATCH * SEQ;               // 4096
    const int nelem = M * D_MODEL;

    // 0) RoPE cos/sin table
    rope_table_kernel<<<SEQ * 64 / 256, 256>>>();

    // 1) split activations x -> (Ahi, Alo)
    split_kernel<<<(nelem / 4 + 255) / 256, 256>>>(x, Ahi, Alo, nelem / 4);

    // 2) weight transpose + split
    transpose_split_kernel<<<dim3(3 * D_MODEL / 64, D_MODEL / 64), 256>>>(
        Wqkv, WqH, WqL, D_MODEL, 3 * D_MODEL);
    transpose_split_kernel<<<dim3(D_MODEL / 64, D_MODEL / 64), 256>>>(
        Wproj, WpH, WpL, D_MODEL, D_MODEL);

    // 3) QKV projection with FUSED rope/split epilogue (128-thread CTAs)
    gemm_bf16x3_kernel<<<dim3(3 * D_MODEL / 128, M / 128), 128, GB_SMEM>>>(
        Ahi, Alo, WqH, WqL, bqkv, nullptr, M, 3 * D_MODEL, D_MODEL, 1);

    // 4) MMA flash attention on prepped operands (writes bf16 hi/lo directly)
    flash_attn_mma_kernel<<<dim3(SEQ / FA_TQ, BATCH * N_HEAD), 256, FA_SMEM>>>();

    // 5) output projection (plain epilogue)
    gemm_bf16x3_kernel<<<dim3(D_MODEL / 128, M / 128), 128, GB_SMEM>>>(
        Ahi, Alo, WpH, WpL, bproj, out, M, D_MODEL, D_MODEL, 0);
}

// round 9
// speedup vs baseline: 3.0188x; 1.1133x over previous
#include <cuda_runtime.h>
#include <cuda_bf16.h>
#include <math.h>
#include <stdint.h>

#define D_MODEL 2048
#define N_HEAD  16
#define HEAD_DIM 128
#define BATCH   2
#define SEQ     2048

// ---------------------------------------------------------------------------
// Static scratch (no cudaMalloc anywhere)
// ---------------------------------------------------------------------------
static __device__ float g_rope[(size_t)SEQ * 128];                // cos/sin table
static __device__ __nv_bfloat16 g_Ahi[(size_t)BATCH * SEQ * D_MODEL];
static __device__ __nv_bfloat16 g_Alo[(size_t)BATCH * SEQ * D_MODEL];
static __device__ __nv_bfloat16 g_Wqkv_hi[(size_t)3 * D_MODEL * D_MODEL]; // [N][K]
static __device__ __nv_bfloat16 g_Wqkv_lo[(size_t)3 * D_MODEL * D_MODEL];
static __device__ __nv_bfloat16 g_Wproj_hi[(size_t)D_MODEL * D_MODEL];
static __device__ __nv_bfloat16 g_Wproj_lo[(size_t)D_MODEL * D_MODEL];
// head-major prepped attention operands: [b][h][t][d]
static __device__ __nv_bfloat16 g_Qhi[(size_t)BATCH * SEQ * D_MODEL];
static __device__ __nv_bfloat16 g_Qlo[(size_t)BATCH * SEQ * D_MODEL];
static __device__ __nv_bfloat16 g_Khi[(size_t)BATCH * SEQ * D_MODEL];
static __device__ __nv_bfloat16 g_Klo[(size_t)BATCH * SEQ * D_MODEL];
static __device__ __nv_bfloat16 g_Vhi[(size_t)BATCH * SEQ * D_MODEL];
static __device__ __nv_bfloat16 g_Vlo[(size_t)BATCH * SEQ * D_MODEL];

// ---------------------------------------------------------------------------
// PTX helpers (sm_80+ subset: cp.async / ldmatrix / mma.sync)
// ---------------------------------------------------------------------------
__device__ __forceinline__ uint32_t smem_to_u32(const void* smem_ptr) {
    uint32_t addr;
    asm("{ .reg .u64 tmp; cvta.to.shared.u64 tmp, %1; cvt.u32.u64 %0, tmp; }"
        : "=r"(addr) : "l"(smem_ptr));
    return addr;
}

__device__ __forceinline__ void cp_async16(uint32_t smem_dst, const void* gmem_src) {
    asm volatile("cp.async.cg.shared.global.L2::128B [%0], [%1], 16;"
                 :: "r"(smem_dst), "l"(__cvta_generic_to_global(gmem_src)));
}
#define CP_ASYNC_COMMIT() asm volatile("cp.async.commit_group;" ::: "memory")
#define CP_ASYNC_WAIT_1() asm volatile("cp.async.wait_group 1;" ::: "memory")

__device__ __forceinline__ void ldsm4(uint32_t* r, uint32_t addr) {
    asm volatile("ldmatrix.sync.aligned.m8n8.x4.shared.b16 {%0,%1,%2,%3}, [%4];"
                 : "=r"(r[0]), "=r"(r[1]), "=r"(r[2]), "=r"(r[3]) : "r"(addr));
}
__device__ __forceinline__ void ldsm4t(uint32_t* r, uint32_t addr) {
    asm volatile("ldmatrix.sync.aligned.m8n8.x4.trans.shared.b16 {%0,%1,%2,%3}, [%4];"
                 : "=r"(r[0]), "=r"(r[1]), "=r"(r[2]), "=r"(r[3]) : "r"(addr));
}

__device__ __forceinline__ void mma_bf16(float* c, const uint32_t* a,
                                         uint32_t b0, uint32_t b1) {
    asm volatile(
        "mma.sync.aligned.m16n8k16.row.col.f32.bf16.bf16.f32 "
        "{%0,%1,%2,%3}, {%4,%5,%6,%7}, {%8,%9}, {%0,%1,%2,%3};"
        : "+f"(c[0]), "+f"(c[1]), "+f"(c[2]), "+f"(c[3])
        : "r"(a[0]), "r"(a[1]), "r"(a[2]), "r"(a[3]), "r"(b0), "r"(b1));
}

// pack (s0 -> low bf16, s1 -> high bf16) into hi; residuals into lo.
__device__ __forceinline__ void split2(float s0, float s1, uint32_t& hi, uint32_t& lo) {
    asm("cvt.rn.bf16x2.f32 %0, %1, %2;" : "=r"(hi) : "f"(s1), "f"(s0));
    __nv_bfloat162 hv = *reinterpret_cast<__nv_bfloat162*>(&hi);
    float r0 = s0 - __bfloat162float(hv.x);
    float r1 = s1 - __bfloat162float(hv.y);
    asm("cvt.rn.bf16x2.f32 %0, %1, %2;" : "=r"(lo) : "f"(r1), "f"(r0));
}

// ---------------------------------------------------------------------------
// RoPE table
// ---------------------------------------------------------------------------
__global__ void rope_table_kernel()
{
    const float RATE_C = 0.14391156831212787f; // ln(10000)/64
    int i = blockIdx.x * blockDim.x + threadIdx.x;  // t*64 + j
    int t = i >> 6, j = i & 63;
    float rate = expf(-RATE_C * (float)j);
    float sv, cv;
    sincosf((float)t * rate, &sv, &cv);
    g_rope[t * 128 + j]      = cv;
    g_rope[t * 128 + 64 + j] = sv;
}

// ---------------------------------------------------------------------------
// Elementwise split: fp32 -> (hi, lo) bf16 pair.
// ---------------------------------------------------------------------------
__global__ void split_kernel(const float* __restrict__ X,
                             __nv_bfloat16* __restrict__ hi,
                             __nv_bfloat16* __restrict__ lo, int n4)
{
    int i = blockIdx.x * blockDim.x + threadIdx.x;
    if (i >= n4) return;
    float4 v = *(const float4*)(X + (size_t)i * 4);
    __nv_bfloat16 h[4], l[4];
    float vv[4] = {v.x, v.y, v.z, v.w};
#pragma unroll
    for (int j = 0; j < 4; ++j) {
        h[j] = __float2bfloat16(vv[j]);
        l[j] = __float2bfloat16(vv[j] - __bfloat162float(h[j]));
    }
    *(uint2*)(hi + (size_t)i * 4) = *(uint2*)h;
    *(uint2*)(lo + (size_t)i * 4) = *(uint2*)l;
}

// ---------------------------------------------------------------------------
// Transpose + split: W[K,N] fp32 -> Thi/Tlo [N,K] bf16 (K-major for MMA B).
// ---------------------------------------------------------------------------
__global__ __launch_bounds__(256) void transpose_split_kernel(
    const float* __restrict__ W,
    __nv_bfloat16* __restrict__ Thi, __nv_bfloat16* __restrict__ Tlo,
    int K, int N)
{
    __shared__ float tile[64][65];
    const int k0 = blockIdx.y * 64;
    const int n0 = blockIdx.x * 64;
    const int tid = threadIdx.x;

#pragma unroll
    for (int j = 0; j < 4; ++j) {
        int idx = tid + j * 256;
        int r  = idx >> 4;
        int c4 = (idx & 15) * 4;
        float4 v = *(const float4*)(W + (size_t)(k0 + r) * N + n0 + c4);
        tile[r][c4 + 0] = v.x; tile[r][c4 + 1] = v.y;
        tile[r][c4 + 2] = v.z; tile[r][c4 + 3] = v.w;
    }
    __syncthreads();

    const int n  = tid >> 2;
    const int ks = (tid & 3) * 16;
    __nv_bfloat16 h[16], l[16];
#pragma unroll
    for (int j = 0; j < 16; ++j) {
        float v = tile[ks + j][n];
        h[j] = __float2bfloat16(v);
        l[j] = __float2bfloat16(v - __bfloat162float(h[j]));
    }
    size_t base = (size_t)(n0 + n) * K + k0 + ks;
    *(uint4*)(Thi + base)     = ((uint4*)h)[0];
    *(uint4*)(Thi + base + 8) = ((uint4*)h)[1];
    *(uint4*)(Tlo + base)     = ((uint4*)l)[0];
    *(uint4*)(Tlo + base + 8) = ((uint4*)l)[1];
}

// ---------------------------------------------------------------------------
// bf16x3 HMMA GEMM: 128 threads = 4 warps in 2x2 grid, 64x64 warp tiles.
// 3-stage cp.async pipeline with XOR-swizzled 64B rows (no padding):
//   chunk' = c ^ ((row>>1) & 3)   (verified conflict-free for ldmatrix)
// -> 32KB/stage, 96KB total, 2 CTAs/SM, ONE __syncthreads per K-iteration.
// fuse_qkv == 1: QKV epilogue (rope/scale/split, head-major bf16 hi/lo).
// ---------------------------------------------------------------------------
#define GB_OP     (128 * 64)                // 8192 B per operand tile
#define GB_STAGE  (4 * GB_OP)               // 32768 B
#define GB_NSTAGE 3
#define GB_SMEM   (GB_NSTAGE * GB_STAGE)    // 98304 B (>= 128*132*4 = 67584)

#define GB_SWIZ(row, c) ((uint32_t)((row) * 64 + (((c) ^ (((row) >> 1) & 3)) * 16)))

__device__ __forceinline__ void gemm_load_stage(
    uint32_t st,
    const __nv_bfloat16* __restrict__ Ahi, const __nv_bfloat16* __restrict__ Alo,
    const __nv_bfloat16* __restrict__ Bhi, const __nv_bfloat16* __restrict__ Blo,
    int bm, int bn, int k0, int K, int tid)
{
#pragma unroll
    for (int j = 0; j < 4; ++j) {
        int idx = tid + j * 128;            // 0..511
        int row = idx >> 2;                 // 0..127
        int c   = idx & 3;                  // 16B chunk within 64B row
        uint32_t off = GB_SWIZ(row, c);
        size_t ga = (size_t)(bm + row) * K + k0 + c * 8;
        size_t gb = (size_t)(bn + row) * K + k0 + c * 8;
        cp_async16(st + off,              Ahi + ga);
        cp_async16(st + GB_OP + off,      Alo + ga);
        cp_async16(st + 2 * GB_OP + off,  Bhi + gb);
        cp_async16(st + 3 * GB_OP + off,  Blo + gb);
    }
}

__global__ __launch_bounds__(128, 2) void gemm_bf16x3_kernel(
    const __nv_bfloat16* __restrict__ Ahi, const __nv_bfloat16* __restrict__ Alo,
    const __nv_bfloat16* __restrict__ Bhi, const __nv_bfloat16* __restrict__ Blo,
    const float* __restrict__ bias, float* __restrict__ C,
    int M, int N, int K, int fuse_qkv)
{
    extern __shared__ __align__(128) char smem[];
    const uint32_t sbase = smem_to_u32(smem);
    const int tid  = threadIdx.x;
    const int lane = tid & 31;
    const int wid  = tid >> 5;              // 0..3
    const int wm   = wid >> 1;              // 0..1 (64-row stripes)
    const int wn   = wid & 1;               // 0..1 (64-col stripes)
    const int bm   = blockIdx.y * 128;
    const int bn   = blockIdx.x * 128;

    float acc[4][8][4];
#pragma unroll
    for (int mi = 0; mi < 4; ++mi)
#pragma unroll
        for (int ni = 0; ni < 8; ++ni)
#pragma unroll
            for (int r = 0; r < 4; ++r) acc[mi][ni][r] = 0.f;

    const int nk = K / 32;

    // prologue: stages 0,1 <- iters 0,1
    gemm_load_stage(sbase,            Ahi, Alo, Bhi, Blo, bm, bn, 0,  K, tid);
    CP_ASYNC_COMMIT();
    gemm_load_stage(sbase + GB_STAGE, Ahi, Alo, Bhi, Blo, bm, bn, 32, K, tid);
    CP_ASYNC_COMMIT();

    const int lrowA = lane & 15, lcolA = lane >> 4;
    const int bg    = lane >> 3, blr  = lane & 7;

    for (int i = 0; i < nk; ++i) {
        const uint32_t st = sbase + (uint32_t)(i % GB_NSTAGE) * GB_STAGE;
        CP_ASYNC_WAIT_1();          // load(i) complete (load(i+1) may pend)
        __syncthreads();            // single barrier: also guards stage (i-1)%3 reuse

        // prefetch iter i+2 into stage (i+2)%3 (consumed at iter i-1)
        if (i + 2 < nk) {
            gemm_load_stage(sbase + (uint32_t)((i + 2) % GB_NSTAGE) * GB_STAGE,
                            Ahi, Alo, Bhi, Blo, bm, bn, (i + 2) * 32, K, tid);
        }
        CP_ASYNC_COMMIT();          // commit (possibly empty) keeps group count aligned

        const uint32_t aHi = st;
        const uint32_t aLo = st + GB_OP;
        const uint32_t bHi = st + 2 * GB_OP;
        const uint32_t bLo = st + 3 * GB_OP;

#pragma unroll
        for (int ks = 0; ks < 2; ++ks) {
            uint32_t ah[4][4], al[4][4];
#pragma unroll
            for (int mi = 0; mi < 4; ++mi) {
                int row = wm * 64 + mi * 16 + lrowA;
                uint32_t off = GB_SWIZ(row, ks * 2 + lcolA);
                ldsm4(ah[mi], aHi + off);
                ldsm4(al[mi], aLo + off);
            }
#pragma unroll
            for (int np = 0; np < 4; ++np) {
                uint32_t bh[4], bl[4];
                int row = wn * 64 + np * 16 + (bg >> 1) * 8 + blr;
                uint32_t off = GB_SWIZ(row, ks * 2 + (bg & 1));
                ldsm4(bh, bHi + off);
                ldsm4(bl, bLo + off);
#pragma unroll
                for (int mi = 0; mi < 4; ++mi)
#pragma unroll
                    for (int q = 0; q < 2; ++q) {
                        int ni = np * 2 + q, pr = q * 2;
                        mma_bf16(acc[mi][ni], ah[mi], bh[pr], bh[pr + 1]);
                        mma_bf16(acc[mi][ni], ah[mi], bl[pr], bl[pr + 1]);
                        mma_bf16(acc[mi][ni], al[mi], bh[pr], bh[pr + 1]);
                    }
            }
        }
    }

    const int gid = lane >> 2, tig = lane & 3;

    if (fuse_qkv == 0) {
        // ---- plain epilogue: bias + fp32 store ----
#pragma unroll
        for (int mi = 0; mi < 4; ++mi)
#pragma unroll
            for (int ni = 0; ni < 8; ++ni) {
                int row = bm + wm * 64 + mi * 16 + gid;
                int col = bn + wn * 64 + ni * 8 + tig * 2;
                float2 bv = *(const float2*)(bias + col);
                float2 v0 = make_float2(acc[mi][ni][0] + bv.x, acc[mi][ni][1] + bv.y);
                float2 v1 = make_float2(acc[mi][ni][2] + bv.x, acc[mi][ni][3] + bv.y);
                *(float2*)(C + (size_t)row * N + col)       = v0;
                *(float2*)(C + (size_t)(row + 8) * N + col) = v1;
            }
        return;
    }

    // ---- fused QKV epilogue: rope/scale/split, head-major bf16 hi/lo ----
    __syncthreads();                          // all MMA smem reads done before reuse
    float* Cs = (float*)smem;                 // 128 x 132 fp32, reuses stages
#pragma unroll
    for (int mi = 0; mi < 4; ++mi)
#pragma unroll
        for (int ni = 0; ni < 8; ++ni) {
            int row = wm * 64 + mi * 16 + gid;
            int col = wn * 64 + ni * 8 + tig * 2;
            float2 bv = *(const float2*)(bias + bn + col);
            Cs[row * 132 + col]           = acc[mi][ni][0] + bv.x;
            Cs[row * 132 + col + 1]       = acc[mi][ni][1] + bv.y;
            Cs[(row + 8) * 132 + col]     = acc[mi][ni][2] + bv.x;
            Cs[(row + 8) * 132 + col + 1] = acc[mi][ni][3] + bv.y;
        }
    __syncthreads();

    const int sel = bn >> 11;                 // 0=Q, 1=K, 2=V
    const int hh  = (bn & 2047) >> 7;         // head
    __nv_bfloat16 *dh, *dl;
    if (sel == 0)      { dh = g_Qhi; dl = g_Qlo; }
    else if (sel == 1) { dh = g_Khi; dl = g_Klo; }
    else               { dh = g_Vhi; dl = g_Vlo; }
    const float SCALE = 0.08838834764831845f; // 1/sqrt(128)

    for (int i = tid; i < 128 * 32; i += 128) {
        int row = i >> 5, jp = (i & 31) * 2;  // two adjacent j's: jp, jp+1
        int tg = bm + row, t = tg & (SEQ - 1), bb = tg >> 11;
        float x1a = Cs[row * 132 + jp],      x1b = Cs[row * 132 + jp + 1];
        float x2a = Cs[row * 132 + jp + 64], x2b = Cs[row * 132 + jp + 65];
        float y1a, y1b, y2a, y2b;
        if (sel < 2) {
            float cva = g_rope[t * 128 + jp],     sva = g_rope[t * 128 + 64 + jp];
            float cvb = g_rope[t * 128 + jp + 1], svb = g_rope[t * 128 + 64 + jp + 1];
            y1a = x1a * cva - x2a * sva;  y2a = x1a * sva + x2a * cva;
            y1b = x1b * cvb - x2b * svb;  y2b = x1b * svb + x2b * cvb;
            if (sel == 0) { y1a *= SCALE; y2a *= SCALE; y1b *= SCALE; y2b *= SCALE; }
        } else {
            y1a = x1a; y1b = x1b; y2a = x2a; y2b = x2b;
        }
        size_t base = ((size_t)(bb * N_HEAD + hh) * SEQ + t) * HEAD_DIM;
        uint32_t hi, lo;
        split2(y1a, y1b, hi, lo);
        *(uint32_t*)(dh + base + jp)      = hi;
        *(uint32_t*)(dl + base + jp)      = lo;
        split2(y2a, y2b, hi, lo);
        *(uint32_t*)(dh + base + jp + 64) = hi;
        *(uint32_t*)(dl + base + jp + 64) = lo;
    }
}

// ---------------------------------------------------------------------------
// MMA flash attention over PREPPED bf16 operands (unchanged from R8).
// ---------------------------------------------------------------------------
#define FA_TQ 128
#define FA_TK 64
#define FA_ROWB   272
#define FA_QHI  0
#define FA_QLO  34816
#define FA_KV0  69632                 // per buffer: KHI,+17408 KLO,+34816 VHI,+52224 VLO
#define FA_KVSZ 69632
#define FA_SMEM 208896

__device__ __forceinline__ void fa_load_kv(uint32_t buf, size_t bh_elem, int k0, int tid)
{
    size_t gbase = bh_elem + (size_t)k0 * HEAD_DIM;
    for (int i = tid; i < FA_TK * 16; i += 256) {
        int row = i >> 4, c = i & 15;
        uint32_t soff = (uint32_t)(row * FA_ROWB + c * 16);
        size_t   goff = gbase + (size_t)row * HEAD_DIM + c * 8;
        cp_async16(buf + soff,         g_Khi + goff);
        cp_async16(buf + 17408 + soff, g_Klo + goff);
        cp_async16(buf + 34816 + soff, g_Vhi + goff);
        cp_async16(buf + 52224 + soff, g_Vlo + goff);
    }
}

__global__ __launch_bounds__(256, 1) void flash_attn_mma_kernel()
{
    extern __shared__ __align__(128) char sm[];
    const uint32_t sbase = smem_to_u32(sm);

    const int tid  = threadIdx.x;
    const int lane = tid & 31;
    const int wid  = tid >> 5;
    const int qt   = (gridDim.x - 1) - blockIdx.x;   // heavy tiles first
    const int q0   = qt * FA_TQ;
    const int b    = blockIdx.y >> 4;
    const int h    = blockIdx.y & 15;

    const size_t bh_elem = (size_t)(b * N_HEAD + h) * SEQ * HEAD_DIM;

    // ---- Q tile load (prepped bf16 hi/lo) ----
    {
        size_t qbase = bh_elem + (size_t)q0 * HEAD_DIM;
        for (int i = tid; i < FA_TQ * 16; i += 256) {
            int row = i >> 4, c = i & 15;
            uint32_t soff = (uint32_t)(row * FA_ROWB + c * 16);
            size_t   goff = qbase + (size_t)row * HEAD_DIM + c * 8;
            cp_async16(sbase + FA_QHI + soff, g_Qhi + goff);
            cp_async16(sbase + FA_QLO + soff, g_Qlo + goff);
        }
    }
    const int ktmax = 2 * qt + 1;
    fa_load_kv(sbase + FA_KV0, bh_elem, 0, tid);
    CP_ASYNC_COMMIT();                               // group: Q + KV0
    fa_load_kv(sbase + FA_KV0 + FA_KVSZ, bh_elem, FA_TK, tid);  // ktmax >= 1 always
    CP_ASYNC_COMMIT();                               // group: KV1

    float oacc[16][4];
#pragma unroll
    for (int ni = 0; ni < 16; ++ni)
#pragma unroll
        for (int r = 0; r < 4; ++r) oacc[ni][r] = 0.f;
    float m0 = -1e30f, m1 = -1e30f, l0 = 0.f, l1 = 0.f;

    const int gid = lane >> 2, tig = lane & 3;
    const int lrowA = lane & 15, lcolA = lane >> 4;
    const int bg = lane >> 3, blr = lane & 7;
    const int wrow_lo = q0 + wid * 16;

    for (int kt = 0; kt <= ktmax; ++kt) {
        const int k0 = kt * FA_TK;
        const uint32_t buf = sbase + FA_KV0 + (uint32_t)(kt & 1) * FA_KVSZ;
        CP_ASYNC_WAIT_1();          // KV[kt] (and Q) resident; KV[kt+1] may pend
        __syncthreads();

        if (k0 <= wrow_lo + 15) {   // warp-level causal skip
            // ---- S = Q @ K^T, bf16x3 ----
            float sacc[8][4];
#pragma unroll
            for (int ni = 0; ni < 8; ++ni)
#pragma unroll
                for (int r = 0; r < 4; ++r) sacc[ni][r] = 0.f;

#pragma unroll
            for (int ks = 0; ks < 8; ++ks) {
                uint32_t qh[4], ql[4];
                uint32_t qoff = (uint32_t)((wid * 16 + lrowA) * FA_ROWB
                                           + (ks * 16 + lcolA * 8) * 2);
                ldsm4(qh, sbase + FA_QHI + qoff);
                ldsm4(ql, sbase + FA_QLO + qoff);
                uint32_t kh[4][4], kl[4][4];
#pragma unroll
                for (int np = 0; np < 4; ++np) {
                    uint32_t koff = (uint32_t)((np * 16 + (bg >> 1) * 8 + blr) * FA_ROWB
                                               + (ks * 16 + (bg & 1) * 8) * 2);
                    ldsm4(kh[np], buf + koff);
                    ldsm4(kl[np], buf + 17408 + koff);
                }
#pragma unroll
                for (int ni = 0; ni < 8; ++ni) {
                    int np = ni >> 1, pr = (ni & 1) * 2;
                    mma_bf16(sacc[ni], qh, kh[np][pr], kh[np][pr + 1]);
                    mma_bf16(sacc[ni], qh, kl[np][pr], kl[np][pr + 1]);
                    mma_bf16(sacc[ni], ql, kh[np][pr], kh[np][pr + 1]);
                }
            }

            // ---- causal mask (partial tiles only) ----
            const int row0 = wrow_lo + gid, row1 = row0 + 8;
            if (k0 + FA_TK - 1 > q0) {
#pragma unroll
                for (int ni = 0; ni < 8; ++ni) {
                    int col = k0 + ni * 8 + tig * 2;
                    if (col     > row0) sacc[ni][0] = -1e30f;
                    if (col + 1 > row0) sacc[ni][1] = -1e30f;
                    if (col     > row1) sacc[ni][2] = -1e30f;
                    if (col + 1 > row1) sacc[ni][3] = -1e30f;
                }
            }

            // ---- online softmax ----
            float mx0 = -1e30f, mx1 = -1e30f;
#pragma unroll
            for (int ni = 0; ni < 8; ++ni) {
                mx0 = fmaxf(mx0, fmaxf(sacc[ni][0], sacc[ni][1]));
                mx1 = fmaxf(mx1, fmaxf(sacc[ni][2], sacc[ni][3]));
            }
#pragma unroll
            for (int off = 1; off < 4; off <<= 1) {
                mx0 = fmaxf(mx0, __shfl_xor_sync(0xffffffffu, mx0, off));
                mx1 = fmaxf(mx1, __shfl_xor_sync(0xffffffffu, mx1, off));
            }
            float mn0 = fmaxf(m0, mx0), mn1 = fmaxf(m1, mx1);
            float a0 = __expf(m0 - mn0), a1 = __expf(m1 - mn1);
            m0 = mn0; m1 = mn1;
            float sum0 = 0.f, sum1 = 0.f;
#pragma unroll
            for (int ni = 0; ni < 8; ++ni) {
                sacc[ni][0] = __expf(sacc[ni][0] - mn0);
                sacc[ni][1] = __expf(sacc[ni][1] - mn0);
                sacc[ni][2] = __expf(sacc[ni][2] - mn1);
                sacc[ni][3] = __expf(sacc[ni][3] - mn1);
                sum0 += sacc[ni][0] + sacc[ni][1];
                sum1 += sacc[ni][2] + sacc[ni][3];
            }
#pragma unroll
            for (int off = 1; off < 4; off <<= 1) {
                sum0 += __shfl_xor_sync(0xffffffffu, sum0, off);
                sum1 += __shfl_xor_sync(0xffffffffu, sum1, off);
            }
            l0 = l0 * a0 + sum0;
            l1 = l1 * a1 + sum1;
#pragma unroll
            for (int ni = 0; ni < 16; ++ni) {
                oacc[ni][0] *= a0; oacc[ni][1] *= a0;
                oacc[ni][2] *= a1; oacc[ni][3] *= a1;
            }

            // ---- O += P @ V, bf16x3 (V via trans ldmatrix) ----
            const uint32_t vhi = buf + 34816, vlo = buf + 52224;
#pragma unroll
            for (int kc = 0; kc < 4; ++kc) {
                uint32_t ah[4], al[4];
                split2(sacc[2 * kc][0],     sacc[2 * kc][1],     ah[0], al[0]);
                split2(sacc[2 * kc][2],     sacc[2 * kc][3],     ah[1], al[1]);
                split2(sacc[2 * kc + 1][0], sacc[2 * kc + 1][1], ah[2], al[2]);
                split2(sacc[2 * kc + 1][2], sacc[2 * kc + 1][3], ah[3], al[3]);
#pragma unroll
                for (int np = 0; np < 8; ++np) {
                    uint32_t vh[4], vl[4];
                    uint32_t voff = (uint32_t)((kc * 16 + (lane & 15)) * FA_ROWB
                                               + (np * 16 + (lane >> 4) * 8) * 2);
                    ldsm4t(vh, vhi + voff);
                    ldsm4t(vl, vlo + voff);
#pragma unroll
                    for (int q = 0; q < 2; ++q) {
                        int ni = np * 2 + q, pr = q * 2;
                        mma_bf16(oacc[ni], ah, vh[pr], vh[pr + 1]);
                        mma_bf16(oacc[ni], ah, vl[pr], vl[pr + 1]);
                        mma_bf16(oacc[ni], al, vh[pr], vh[pr + 1]);
                    }
                }
            }
        }

        __syncthreads();            // all warps done reading buf before overwrite
        if (kt + 2 <= ktmax)
            fa_load_kv(sbase + FA_KV0 + (uint32_t)(kt & 1) * FA_KVSZ,
                       bh_elem, (kt + 2) * FA_TK, tid);
        CP_ASYNC_COMMIT();
    }

    // ---- epilogue: normalize, split to bf16 hi/lo, store ----
    {
        float inv0 = 1.f / l0, inv1 = 1.f / l1;
        int t0 = wrow_lo + gid;
        size_t base0 = (size_t)(b * SEQ + t0) * D_MODEL + h * HEAD_DIM;
        size_t base1 = (size_t)(b * SEQ + t0 + 8) * D_MODEL + h * HEAD_DIM;
#pragma unroll
        for (int ni = 0; ni < 16; ++ni) {
            int col = ni * 8 + tig * 2;
            uint32_t hi, lo;
            split2(oacc[ni][0] * inv0, oacc[ni][1] * inv0, hi, lo);
            *(uint32_t*)(g_Ahi + base0 + col) = hi;
            *(uint32_t*)(g_Alo + base0 + col) = lo;
            split2(oacc[ni][2] * inv1, oacc[ni][3] * inv1, hi, lo);
            *(uint32_t*)(g_Ahi + base1 + col) = hi;
            *(uint32_t*)(g_Alo + base1 + col) = lo;
        }
    }
}

// ---------------------------------------------------------------------------
extern "C" void kernel_launch(void* const* d_in, const int* in_sizes, int n_in,
                              void* d_out, int out_size)
{
    (void)in_sizes; (void)n_in; (void)out_size;
    const float* x     = (const float*)d_in[0];
    const float* Wqkv  = (const float*)d_in[2];
    const float* bqkv  = (const float*)d_in[3];
    const float* Wproj = (const float*)d_in[4];
    const float* bproj = (const float*)d_in[5];
    float* out = (float*)d_out;

    void *ahi_p, *alo_p, *wq_hi_p, *wq_lo_p, *wp_hi_p, *wp_lo_p;
    cudaGetSymbolAddress(&ahi_p, g_Ahi);
    cudaGetSymbolAddress(&alo_p, g_Alo);
    cudaGetSymbolAddress(&wq_hi_p, g_Wqkv_hi);
    cudaGetSymbolAddress(&wq_lo_p, g_Wqkv_lo);
    cudaGetSymbolAddress(&wp_hi_p, g_Wproj_hi);
    cudaGetSymbolAddress(&wp_lo_p, g_Wproj_lo);
    __nv_bfloat16* Ahi = (__nv_bfloat16*)ahi_p;
    __nv_bfloat16* Alo = (__nv_bfloat16*)alo_p;
    __nv_bfloat16* WqH = (__nv_bfloat16*)wq_hi_p;
    __nv_bfloat16* WqL = (__nv_bfloat16*)wq_lo_p;
    __nv_bfloat16* WpH = (__nv_bfloat16*)wp_hi_p;
    __nv_bfloat16* WpL = (__nv_bfloat16*)wp_lo_p;

    cudaFuncSetAttribute(gemm_bf16x3_kernel,
                         cudaFuncAttributeMaxDynamicSharedMemorySize, GB_SMEM);
    cudaFuncSetAttribute(flash_attn_mma_kernel,
                         cudaFuncAttributeMaxDynamicSharedMemorySize, FA_SMEM);

    const int M = BATCH * SEQ;               // 4096
    const int nelem = M * D_MODEL;

    // 0) RoPE cos/sin table
    rope_table_kernel<<<SEQ * 64 / 256, 256>>>();

    // 1) split activations x -> (Ahi, Alo)
    split_kernel<<<(nelem / 4 + 255) / 256, 256>>>(x, Ahi, Alo, nelem / 4);

    // 2) weight transpose + split
    transpose_split_kernel<<<dim3(3 * D_MODEL / 64, D_MODEL / 64), 256>>>(
        Wqkv, WqH, WqL, D_MODEL, 3 * D_MODEL);
    transpose_split_kernel<<<dim3(D_MODEL / 64, D_MODEL / 64), 256>>>(
        Wproj, WpH, WpL, D_MODEL, D_MODEL);

    // 3) QKV projection with FUSED rope/split epilogue (3-stage, 1 sync/iter)
    gemm_bf16x3_kernel<<<dim3(3 * D_MODEL / 128, M / 128), 128, GB_SMEM>>>(
        Ahi, Alo, WqH, WqL, bqkv, nullptr, M, 3 * D_MODEL, D_MODEL, 1);

    // 4) MMA flash attention on prepped operands (writes bf16 hi/lo directly)
    flash_attn_mma_kernel<<<dim3(SEQ / FA_TQ, BATCH * N_HEAD), 256, FA_SMEM>>>();

    // 5) output projection (plain epilogue)
    gemm_bf16x3_kernel<<<dim3(D_MODEL / 128, M / 128), 128, GB_SMEM>>>(
        Ahi, Alo, WpH, WpL, bproj, out, M, D_MODEL, D_MODEL, 0);
}

// round 10
// speedup vs baseline: 3.0362x; 1.0058x over previous
#include <cuda_runtime.h>
#include <cuda_bf16.h>
#include <math.h>
#include <stdint.h>

#define D_MODEL 2048
#define N_HEAD  16
#define HEAD_DIM 128
#define BATCH   2
#define SEQ     2048

// ---------------------------------------------------------------------------
// Static scratch (no cudaMalloc anywhere)
// ---------------------------------------------------------------------------
static __device__ float g_rope[(size_t)SEQ * 128];                // cos/sin table
static __device__ __nv_bfloat16 g_Ahi[(size_t)BATCH * SEQ * D_MODEL];
static __device__ __nv_bfloat16 g_Alo[(size_t)BATCH * SEQ * D_MODEL];
static __device__ __nv_bfloat16 g_Wqkv_hi[(size_t)3 * D_MODEL * D_MODEL]; // [N][K]
static __device__ __nv_bfloat16 g_Wqkv_lo[(size_t)3 * D_MODEL * D_MODEL];
static __device__ __nv_bfloat16 g_Wproj_hi[(size_t)D_MODEL * D_MODEL];
static __device__ __nv_bfloat16 g_Wproj_lo[(size_t)D_MODEL * D_MODEL];
// head-major prepped attention operands: [b][h][t][d]
static __device__ __nv_bfloat16 g_Qhi[(size_t)BATCH * SEQ * D_MODEL];
static __device__ __nv_bfloat16 g_Qlo[(size_t)BATCH * SEQ * D_MODEL];
static __device__ __nv_bfloat16 g_Khi[(size_t)BATCH * SEQ * D_MODEL];
static __device__ __nv_bfloat16 g_Klo[(size_t)BATCH * SEQ * D_MODEL];
static __device__ __nv_bfloat16 g_Vhi[(size_t)BATCH * SEQ * D_MODEL];
static __device__ __nv_bfloat16 g_Vlo[(size_t)BATCH * SEQ * D_MODEL];

// ---------------------------------------------------------------------------
// PTX helpers (sm_80+ subset: cp.async / ldmatrix / mma.sync)
// ---------------------------------------------------------------------------
__device__ __forceinline__ uint32_t smem_to_u32(const void* smem_ptr) {
    uint32_t addr;
    asm("{ .reg .u64 tmp; cvta.to.shared.u64 tmp, %1; cvt.u32.u64 %0, tmp; }"
        : "=r"(addr) : "l"(smem_ptr));
    return addr;
}

__device__ __forceinline__ void cp_async16(uint32_t smem_dst, const void* gmem_src) {
    asm volatile("cp.async.cg.shared.global.L2::128B [%0], [%1], 16;"
                 :: "r"(smem_dst), "l"(__cvta_generic_to_global(gmem_src)));
}
#define CP_ASYNC_COMMIT() asm volatile("cp.async.commit_group;" ::: "memory")
#define CP_ASYNC_WAIT_1() asm volatile("cp.async.wait_group 1;" ::: "memory")
#define CP_ASYNC_WAIT_2() asm volatile("cp.async.wait_group 2;" ::: "memory")

__device__ __forceinline__ void ldsm4(uint32_t* r, uint32_t addr) {
    asm volatile("ldmatrix.sync.aligned.m8n8.x4.shared.b16 {%0,%1,%2,%3}, [%4];"
                 : "=r"(r[0]), "=r"(r[1]), "=r"(r[2]), "=r"(r[3]) : "r"(addr));
}
__device__ __forceinline__ void ldsm4t(uint32_t* r, uint32_t addr) {
    asm volatile("ldmatrix.sync.aligned.m8n8.x4.trans.shared.b16 {%0,%1,%2,%3}, [%4];"
                 : "=r"(r[0]), "=r"(r[1]), "=r"(r[2]), "=r"(r[3]) : "r"(addr));
}

__device__ __forceinline__ void mma_bf16(float* c, const uint32_t* a,
                                         uint32_t b0, uint32_t b1) {
    asm volatile(
        "mma.sync.aligned.m16n8k16.row.col.f32.bf16.bf16.f32 "
        "{%0,%1,%2,%3}, {%4,%5,%6,%7}, {%8,%9}, {%0,%1,%2,%3};"
        : "+f"(c[0]), "+f"(c[1]), "+f"(c[2]), "+f"(c[3])
        : "r"(a[0]), "r"(a[1]), "r"(a[2]), "r"(a[3]), "r"(b0), "r"(b1));
}

// pack (s0 -> low bf16, s1 -> high bf16) into hi; residuals into lo.
__device__ __forceinline__ void split2(float s0, float s1, uint32_t& hi, uint32_t& lo) {
    asm("cvt.rn.bf16x2.f32 %0, %1, %2;" : "=r"(hi) : "f"(s1), "f"(s0));
    __nv_bfloat162 hv = *reinterpret_cast<__nv_bfloat162*>(&hi);
    float r0 = s0 - __bfloat162float(hv.x);
    float r1 = s1 - __bfloat162float(hv.y);
    asm("cvt.rn.bf16x2.f32 %0, %1, %2;" : "=r"(lo) : "f"(r1), "f"(r0));
}

// ---------------------------------------------------------------------------
// RoPE table
// ---------------------------------------------------------------------------
__global__ void rope_table_kernel()
{
    const float RATE_C = 0.14391156831212787f; // ln(10000)/64
    int i = blockIdx.x * blockDim.x + threadIdx.x;  // t*64 + j
    int t = i >> 6, j = i & 63;
    float rate = expf(-RATE_C * (float)j);
    float sv, cv;
    sincosf((float)t * rate, &sv, &cv);
    g_rope[t * 128 + j]      = cv;
    g_rope[t * 128 + 64 + j] = sv;
}

// ---------------------------------------------------------------------------
// Elementwise split: fp32 -> (hi, lo) bf16 pair.
// ---------------------------------------------------------------------------
__global__ void split_kernel(const float* __restrict__ X,
                             __nv_bfloat16* __restrict__ hi,
                             __nv_bfloat16* __restrict__ lo, int n4)
{
    int i = blockIdx.x * blockDim.x + threadIdx.x;
    if (i >= n4) return;
    float4 v = *(const float4*)(X + (size_t)i * 4);
    __nv_bfloat16 h[4], l[4];
    float vv[4] = {v.x, v.y, v.z, v.w};
#pragma unroll
    for (int j = 0; j < 4; ++j) {
        h[j] = __float2bfloat16(vv[j]);
        l[j] = __float2bfloat16(vv[j] - __bfloat162float(h[j]));
    }
    *(uint2*)(hi + (size_t)i * 4) = *(uint2*)h;
    *(uint2*)(lo + (size_t)i * 4) = *(uint2*)l;
}

// ---------------------------------------------------------------------------
// Transpose + split: W[K,N] fp32 -> Thi/Tlo [N,K] bf16 (K-major for MMA B).
// ---------------------------------------------------------------------------
__global__ __launch_bounds__(256) void transpose_split_kernel(
    const float* __restrict__ W,
    __nv_bfloat16* __restrict__ Thi, __nv_bfloat16* __restrict__ Tlo,
    int K, int N)
{
    __shared__ float tile[64][65];
    const int k0 = blockIdx.y * 64;
    const int n0 = blockIdx.x * 64;
    const int tid = threadIdx.x;

#pragma unroll
    for (int j = 0; j < 4; ++j) {
        int idx = tid + j * 256;
        int r  = idx >> 4;
        int c4 = (idx & 15) * 4;
        float4 v = *(const float4*)(W + (size_t)(k0 + r) * N + n0 + c4);
        tile[r][c4 + 0] = v.x; tile[r][c4 + 1] = v.y;
        tile[r][c4 + 2] = v.z; tile[r][c4 + 3] = v.w;
    }
    __syncthreads();

    const int n  = tid >> 2;
    const int ks = (tid & 3) * 16;
    __nv_bfloat16 h[16], l[16];
#pragma unroll
    for (int j = 0; j < 16; ++j) {
        float v = tile[ks + j][n];
        h[j] = __float2bfloat16(v);
        l[j] = __float2bfloat16(v - __bfloat162float(h[j]));
    }
    size_t base = (size_t)(n0 + n) * K + k0 + ks;
    *(uint4*)(Thi + base)     = ((uint4*)h)[0];
    *(uint4*)(Thi + base + 8) = ((uint4*)h)[1];
    *(uint4*)(Tlo + base)     = ((uint4*)l)[0];
    *(uint4*)(Tlo + base + 8) = ((uint4*)l)[1];
}

// ---------------------------------------------------------------------------
// bf16x3 HMMA GEMM (unchanged from R9): 4 warps 2x2, 64x64 warp tiles,
// 3-stage XOR-swizzled cp.async pipeline, 1 barrier/iter, 2 CTAs/SM.
// ---------------------------------------------------------------------------
#define GB_OP     (128 * 64)                // 8192 B per operand tile
#define GB_STAGE  (4 * GB_OP)               // 32768 B
#define GB_NSTAGE 3
#define GB_SMEM   (GB_NSTAGE * GB_STAGE)    // 98304 B (>= 128*132*4 = 67584)

#define GB_SWIZ(row, c) ((uint32_t)((row) * 64 + (((c) ^ (((row) >> 1) & 3)) * 16)))

__device__ __forceinline__ void gemm_load_stage(
    uint32_t st,
    const __nv_bfloat16* __restrict__ Ahi, const __nv_bfloat16* __restrict__ Alo,
    const __nv_bfloat16* __restrict__ Bhi, const __nv_bfloat16* __restrict__ Blo,
    int bm, int bn, int k0, int K, int tid)
{
#pragma unroll
    for (int j = 0; j < 4; ++j) {
        int idx = tid + j * 128;            // 0..511
        int row = idx >> 2;                 // 0..127
        int c   = idx & 3;                  // 16B chunk within 64B row
        uint32_t off = GB_SWIZ(row, c);
        size_t ga = (size_t)(bm + row) * K + k0 + c * 8;
        size_t gb = (size_t)(bn + row) * K + k0 + c * 8;
        cp_async16(st + off,              Ahi + ga);
        cp_async16(st + GB_OP + off,      Alo + ga);
        cp_async16(st + 2 * GB_OP + off,  Bhi + gb);
        cp_async16(st + 3 * GB_OP + off,  Blo + gb);
    }
}

__global__ __launch_bounds__(128, 2) void gemm_bf16x3_kernel(
    const __nv_bfloat16* __restrict__ Ahi, const __nv_bfloat16* __restrict__ Alo,
    const __nv_bfloat16* __restrict__ Bhi, const __nv_bfloat16* __restrict__ Blo,
    const float* __restrict__ bias, float* __restrict__ C,
    int M, int N, int K, int fuse_qkv)
{
    extern __shared__ __align__(128) char smem[];
    const uint32_t sbase = smem_to_u32(smem);
    const int tid  = threadIdx.x;
    const int lane = tid & 31;
    const int wid  = tid >> 5;              // 0..3
    const int wm   = wid >> 1;              // 0..1 (64-row stripes)
    const int wn   = wid & 1;               // 0..1 (64-col stripes)
    const int bm   = blockIdx.y * 128;
    const int bn   = blockIdx.x * 128;

    float acc[4][8][4];
#pragma unroll
    for (int mi = 0; mi < 4; ++mi)
#pragma unroll
        for (int ni = 0; ni < 8; ++ni)
#pragma unroll
            for (int r = 0; r < 4; ++r) acc[mi][ni][r] = 0.f;

    const int nk = K / 32;

    gemm_load_stage(sbase,            Ahi, Alo, Bhi, Blo, bm, bn, 0,  K, tid);
    CP_ASYNC_COMMIT();
    gemm_load_stage(sbase + GB_STAGE, Ahi, Alo, Bhi, Blo, bm, bn, 32, K, tid);
    CP_ASYNC_COMMIT();

    const int lrowA = lane & 15, lcolA = lane >> 4;
    const int bg    = lane >> 3, blr  = lane & 7;

    for (int i = 0; i < nk; ++i) {
        const uint32_t st = sbase + (uint32_t)(i % GB_NSTAGE) * GB_STAGE;
        CP_ASYNC_WAIT_1();
        __syncthreads();

        if (i + 2 < nk) {
            gemm_load_stage(sbase + (uint32_t)((i + 2) % GB_NSTAGE) * GB_STAGE,
                            Ahi, Alo, Bhi, Blo, bm, bn, (i + 2) * 32, K, tid);
        }
        CP_ASYNC_COMMIT();

        const uint32_t aHi = st;
        const uint32_t aLo = st + GB_OP;
        const uint32_t bHi = st + 2 * GB_OP;
        const uint32_t bLo = st + 3 * GB_OP;

#pragma unroll
        for (int ks = 0; ks < 2; ++ks) {
            uint32_t ah[4][4], al[4][4];
#pragma unroll
            for (int mi = 0; mi < 4; ++mi) {
                int row = wm * 64 + mi * 16 + lrowA;
                uint32_t off = GB_SWIZ(row, ks * 2 + lcolA);
                ldsm4(ah[mi], aHi + off);
                ldsm4(al[mi], aLo + off);
            }
#pragma unroll
            for (int np = 0; np < 4; ++np) {
                uint32_t bh[4], bl[4];
                int row = wn * 64 + np * 16 + (bg >> 1) * 8 + blr;
                uint32_t off = GB_SWIZ(row, ks * 2 + (bg & 1));
                ldsm4(bh, bHi + off);
                ldsm4(bl, bLo + off);
#pragma unroll
                for (int mi = 0; mi < 4; ++mi)
#pragma unroll
                    for (int q = 0; q < 2; ++q) {
                        int ni = np * 2 + q, pr = q * 2;
                        mma_bf16(acc[mi][ni], ah[mi], bh[pr], bh[pr + 1]);
                        mma_bf16(acc[mi][ni], ah[mi], bl[pr], bl[pr + 1]);
                        mma_bf16(acc[mi][ni], al[mi], bh[pr], bh[pr + 1]);
                    }
            }
        }
    }

    const int gid = lane >> 2, tig = lane & 3;

    if (fuse_qkv == 0) {
#pragma unroll
        for (int mi = 0; mi < 4; ++mi)
#pragma unroll
            for (int ni = 0; ni < 8; ++ni) {
                int row = bm + wm * 64 + mi * 16 + gid;
                int col = bn + wn * 64 + ni * 8 + tig * 2;
                float2 bv = *(const float2*)(bias + col);
                float2 v0 = make_float2(acc[mi][ni][0] + bv.x, acc[mi][ni][1] + bv.y);
                float2 v1 = make_float2(acc[mi][ni][2] + bv.x, acc[mi][ni][3] + bv.y);
                *(float2*)(C + (size_t)row * N + col)       = v0;
                *(float2*)(C + (size_t)(row + 8) * N + col) = v1;
            }
        return;
    }

    // ---- fused QKV epilogue: rope/scale/split, head-major bf16 hi/lo ----
    __syncthreads();
    float* Cs = (float*)smem;                 // 128 x 132 fp32, reuses stages
#pragma unroll
    for (int mi = 0; mi < 4; ++mi)
#pragma unroll
        for (int ni = 0; ni < 8; ++ni) {
            int row = wm * 64 + mi * 16 + gid;
            int col = wn * 64 + ni * 8 + tig * 2;
            float2 bv = *(const float2*)(bias + bn + col);
            Cs[row * 132 + col]           = acc[mi][ni][0] + bv.x;
            Cs[row * 132 + col + 1]       = acc[mi][ni][1] + bv.y;
            Cs[(row + 8) * 132 + col]     = acc[mi][ni][2] + bv.x;
            Cs[(row + 8) * 132 + col + 1] = acc[mi][ni][3] + bv.y;
        }
    __syncthreads();

    const int sel = bn >> 11;                 // 0=Q, 1=K, 2=V
    const int hh  = (bn & 2047) >> 7;         // head
    __nv_bfloat16 *dh, *dl;
    if (sel == 0)      { dh = g_Qhi; dl = g_Qlo; }
    else if (sel == 1) { dh = g_Khi; dl = g_Klo; }
    else               { dh = g_Vhi; dl = g_Vlo; }
    const float SCALE = 0.08838834764831845f; // 1/sqrt(128)

    for (int i = tid; i < 128 * 32; i += 128) {
        int row = i >> 5, jp = (i & 31) * 2;
        int tg = bm + row, t = tg & (SEQ - 1), bb = tg >> 11;
        float x1a = Cs[row * 132 + jp],      x1b = Cs[row * 132 + jp + 1];
        float x2a = Cs[row * 132 + jp + 64], x2b = Cs[row * 132 + jp + 65];
        float y1a, y1b, y2a, y2b;
        if (sel < 2) {
            float cva = g_rope[t * 128 + jp],     sva = g_rope[t * 128 + 64 + jp];
            float cvb = g_rope[t * 128 + jp + 1], svb = g_rope[t * 128 + 64 + jp + 1];
            y1a = x1a * cva - x2a * sva;  y2a = x1a * sva + x2a * cva;
            y1b = x1b * cvb - x2b * svb;  y2b = x1b * svb + x2b * cvb;
            if (sel == 0) { y1a *= SCALE; y2a *= SCALE; y1b *= SCALE; y2b *= SCALE; }
        } else {
            y1a = x1a; y1b = x1b; y2a = x2a; y2b = x2b;
        }
        size_t base = ((size_t)(bb * N_HEAD + hh) * SEQ + t) * HEAD_DIM;
        uint32_t hi, lo;
        split2(y1a, y1b, hi, lo);
        *(uint32_t*)(dh + base + jp)      = hi;
        *(uint32_t*)(dl + base + jp)      = lo;
        split2(y2a, y2b, hi, lo);
        *(uint32_t*)(dh + base + jp + 64) = hi;
        *(uint32_t*)(dl + base + jp + 64) = lo;
    }
}

// ---------------------------------------------------------------------------
// MMA flash attention, R10: Q hoisted to REGISTERS, Q smem reused as third KV
// buffer -> 3-stage KV pipeline, ONE __syncthreads per K-tile, prefetch
// issued before MMA (overlaps full compute phase).
// ---------------------------------------------------------------------------
#define FA_TQ 128
#define FA_TK 64
#define FA_ROWB 272
#define FA_BUF  69632                 // KV buffer: KHI +0, KLO +17408, VHI +34816, VLO +52224
#define FA_SMEM (3 * FA_BUF)          // 208896; Q staged in buf2 then recycled

__device__ __forceinline__ void fa_load_kv(uint32_t buf, size_t bh_elem, int k0, int tid)
{
    size_t gbase = bh_elem + (size_t)k0 * HEAD_DIM;
    for (int i = tid; i < FA_TK * 16; i += 256) {
        int row = i >> 4, c = i & 15;
        uint32_t soff = (uint32_t)(row * FA_ROWB + c * 16);
        size_t   goff = gbase + (size_t)row * HEAD_DIM + c * 8;
        cp_async16(buf + soff,         g_Khi + goff);
        cp_async16(buf + 17408 + soff, g_Klo + goff);
        cp_async16(buf + 34816 + soff, g_Vhi + goff);
        cp_async16(buf + 52224 + soff, g_Vlo + goff);
    }
}

__global__ __launch_bounds__(256, 1) void flash_attn_mma_kernel()
{
    extern __shared__ __align__(128) char sm[];
    const uint32_t sbase = smem_to_u32(sm);

    const int tid  = threadIdx.x;
    const int lane = tid & 31;
    const int wid  = tid >> 5;
    const int qt   = (gridDim.x - 1) - blockIdx.x;   // heavy tiles first
    const int q0   = qt * FA_TQ;
    const int b    = blockIdx.y >> 4;
    const int h    = blockIdx.y & 15;

    const size_t bh_elem = (size_t)(b * N_HEAD + h) * SEQ * HEAD_DIM;
    const int ktmax = 2 * qt + 1;                    // >= 1 always

    // ---- prologue loads: Q -> buf2 region (group 0), KV0 (g1), KV1 (g2) ----
    {
        size_t qbase = bh_elem + (size_t)q0 * HEAD_DIM;
        const uint32_t qarea = sbase + 2 * FA_BUF;   // QHI +0 (128*272), QLO +34816
        for (int i = tid; i < FA_TQ * 16; i += 256) {
            int row = i >> 4, c = i & 15;
            uint32_t soff = (uint32_t)(row * FA_ROWB + c * 16);
            size_t   goff = qbase + (size_t)row * HEAD_DIM + c * 8;
            cp_async16(qarea + soff,         g_Qhi + goff);
            cp_async16(qarea + 34816 + soff, g_Qlo + goff);
        }
    }
    CP_ASYNC_COMMIT();                               // g0: Q
    fa_load_kv(sbase, bh_elem, 0, tid);
    CP_ASYNC_COMMIT();                               // g1: KV0
    fa_load_kv(sbase + FA_BUF, bh_elem, FA_TK, tid);
    CP_ASYNC_COMMIT();                               // g2: KV1

    const int gid = lane >> 2, tig = lane & 3;
    const int lrowA = lane & 15, lcolA = lane >> 4;
    const int bg = lane >> 3, blr = lane & 7;
    const int wrow_lo = q0 + wid * 16;

    // ---- hoist Q into registers (then buf2 is recycled as KV buffer) ----
    uint32_t qh[8][4], ql[8][4];
    CP_ASYNC_WAIT_2();              // g0 (Q) complete
    __syncthreads();
    {
        const uint32_t qarea = sbase + 2 * FA_BUF;
#pragma unroll
        for (int ks = 0; ks < 8; ++ks) {
            uint32_t qoff = (uint32_t)((wid * 16 + lrowA) * FA_ROWB
                                       + (ks * 16 + lcolA * 8) * 2);
            ldsm4(qh[ks], qarea + qoff);
            ldsm4(ql[ks], qarea + 34816 + qoff);
        }
    }
    __syncthreads();                // Q reads done -> buf2 free for KV2

    float oacc[16][4];
#pragma unroll
    for (int ni = 0; ni < 16; ++ni)
#pragma unroll
        for (int r = 0; r < 4; ++r) oacc[ni][r] = 0.f;
    float m0 = -1e30f, m1 = -1e30f, l0 = 0.f, l1 = 0.f;

    for (int kt = 0; kt <= ktmax; ++kt) {
        const int k0 = kt * FA_TK;
        const uint32_t buf = sbase + (uint32_t)(kt % 3) * FA_BUF;
        CP_ASYNC_WAIT_1();          // KV[kt] resident; KV[kt+1] may pend
        __syncthreads();            // data visible + prior-iter buffer reads done

        // prefetch KV[kt+2] into buf (kt+2)%3 (consumed at iter kt-1) -> overlaps MMA
        if (kt + 2 <= ktmax)
            fa_load_kv(sbase + (uint32_t)((kt + 2) % 3) * FA_BUF,
                       bh_elem, (kt + 2) * FA_TK, tid);
        CP_ASYNC_COMMIT();

        if (k0 <= wrow_lo + 15) {   // warp-level causal skip
            // ---- S = Q(regs) @ K^T, bf16x3 ----
            float sacc[8][4];
#pragma unroll
            for (int ni = 0; ni < 8; ++ni)
#pragma unroll
                for (int r = 0; r < 4; ++r) sacc[ni][r] = 0.f;

#pragma unroll
            for (int ks = 0; ks < 8; ++ks) {
#pragma unroll
                for (int np = 0; np < 4; ++np) {
                    uint32_t kh[4], kl[4];
                    uint32_t koff = (uint32_t)((np * 16 + (bg >> 1) * 8 + blr) * FA_ROWB
                                               + (ks * 16 + (bg & 1) * 8) * 2);
                    ldsm4(kh, buf + koff);
                    ldsm4(kl, buf + 17408 + koff);
#pragma unroll
                    for (int q = 0; q < 2; ++q) {
                        int ni = np * 2 + q, pr = q * 2;
                        mma_bf16(sacc[ni], qh[ks], kh[pr], kh[pr + 1]);
                        mma_bf16(sacc[ni], qh[ks], kl[pr], kl[pr + 1]);
                        mma_bf16(sacc[ni], ql[ks], kh[pr], kh[pr + 1]);
                    }
                }
            }

            // ---- causal mask (partial tiles only) ----
            const int row0 = wrow_lo + gid, row1 = row0 + 8;
            if (k0 + FA_TK - 1 > q0) {
#pragma unroll
                for (int ni = 0; ni < 8; ++ni) {
                    int col = k0 + ni * 8 + tig * 2;
                    if (col     > row0) sacc[ni][0] = -1e30f;
                    if (col + 1 > row0) sacc[ni][1] = -1e30f;
                    if (col     > row1) sacc[ni][2] = -1e30f;
                    if (col + 1 > row1) sacc[ni][3] = -1e30f;
                }
            }

            // ---- online softmax ----
            float mx0 = -1e30f, mx1 = -1e30f;
#pragma unroll
            for (int ni = 0; ni < 8; ++ni) {
                mx0 = fmaxf(mx0, fmaxf(sacc[ni][0], sacc[ni][1]));
                mx1 = fmaxf(mx1, fmaxf(sacc[ni][2], sacc[ni][3]));
            }
#pragma unroll
            for (int off = 1; off < 4; off <<= 1) {
                mx0 = fmaxf(mx0, __shfl_xor_sync(0xffffffffu, mx0, off));
                mx1 = fmaxf(mx1, __shfl_xor_sync(0xffffffffu, mx1, off));
            }
            float mn0 = fmaxf(m0, mx0), mn1 = fmaxf(m1, mx1);
            float a0 = __expf(m0 - mn0), a1 = __expf(m1 - mn1);
            m0 = mn0; m1 = mn1;
            float sum0 = 0.f, sum1 = 0.f;
#pragma unroll
            for (int ni = 0; ni < 8; ++ni) {
                sacc[ni][0] = __expf(sacc[ni][0] - mn0);
                sacc[ni][1] = __expf(sacc[ni][1] - mn0);
                sacc[ni][2] = __expf(sacc[ni][2] - mn1);
                sacc[ni][3] = __expf(sacc[ni][3] - mn1);
                sum0 += sacc[ni][0] + sacc[ni][1];
                sum1 += sacc[ni][2] + sacc[ni][3];
            }
#pragma unroll
            for (int off = 1; off < 4; off <<= 1) {
                sum0 += __shfl_xor_sync(0xffffffffu, sum0, off);
                sum1 += __shfl_xor_sync(0xffffffffu, sum1, off);
            }
            l0 = l0 * a0 + sum0;
            l1 = l1 * a1 + sum1;
#pragma unroll
            for (int ni = 0; ni < 16; ++ni) {
                oacc[ni][0] *= a0; oacc[ni][1] *= a0;
                oacc[ni][2] *= a1; oacc[ni][3] *= a1;
            }

            // ---- O += P @ V, bf16x3 (V via trans ldmatrix) ----
            const uint32_t vhi = buf + 34816, vlo = buf + 52224;
#pragma unroll
            for (int kc = 0; kc < 4; ++kc) {
                uint32_t ah[4], al[4];
                split2(sacc[2 * kc][0],     sacc[2 * kc][1],     ah[0], al[0]);
                split2(sacc[2 * kc][2],     sacc[2 * kc][3],     ah[1], al[1]);
                split2(sacc[2 * kc + 1][0], sacc[2 * kc + 1][1], ah[2], al[2]);
                split2(sacc[2 * kc + 1][2], sacc[2 * kc + 1][3], ah[3], al[3]);
#pragma unroll
                for (int np = 0; np < 8; ++np) {
                    uint32_t vh[4], vl[4];
                    uint32_t voff = (uint32_t)((kc * 16 + (lane & 15)) * FA_ROWB
                                               + (np * 16 + (lane >> 4) * 8) * 2);
                    ldsm4t(vh, vhi + voff);
                    ldsm4t(vl, vlo + voff);
#pragma unroll
                    for (int q = 0; q < 2; ++q) {
                        int ni = np * 2 + q, pr = q * 2;
                        mma_bf16(oacc[ni], ah, vh[pr], vh[pr + 1]);
                        mma_bf16(oacc[ni], ah, vl[pr], vl[pr + 1]);
                        mma_bf16(oacc[ni], al, vh[pr], vh[pr + 1]);
                    }
                }
            }
        }
    }

    // ---- epilogue: normalize, split to bf16 hi/lo, store ----
    {
        float inv0 = 1.f / l0, inv1 = 1.f / l1;
        int t0 = wrow_lo + gid;
        size_t base0 = (size_t)(b * SEQ + t0) * D_MODEL + h * HEAD_DIM;
        size_t base1 = (size_t)(b * SEQ + t0 + 8) * D_MODEL + h * HEAD_DIM;
#pragma unroll
        for (int ni = 0; ni < 16; ++ni) {
            int col = ni * 8 + tig * 2;
            uint32_t hi, lo;
            split2(oacc[ni][0] * inv0, oacc[ni][1] * inv0, hi, lo);
            *(uint32_t*)(g_Ahi + base0 + col) = hi;
            *(uint32_t*)(g_Alo + base0 + col) = lo;
            split2(oacc[ni][2] * inv1, oacc[ni][3] * inv1, hi, lo);
            *(uint32_t*)(g_Ahi + base1 + col) = hi;
            *(uint32_t*)(g_Alo + base1 + col) = lo;
        }
    }
}

// ---------------------------------------------------------------------------
extern "C" void kernel_launch(void* const* d_in, const int* in_sizes, int n_in,
                              void* d_out, int out_size)
{
    (void)in_sizes; (void)n_in; (void)out_size;
    const float* x     = (const float*)d_in[0];
    const float* Wqkv  = (const float*)d_in[2];
    const float* bqkv  = (const float*)d_in[3];
    const float* Wproj = (const float*)d_in[4];
    const float* bproj = (const float*)d_in[5];
    float* out = (float*)d_out;

    void *ahi_p, *alo_p, *wq_hi_p, *wq_lo_p, *wp_hi_p, *wp_lo_p;
    cudaGetSymbolAddress(&ahi_p, g_Ahi);
    cudaGetSymbolAddress(&alo_p, g_Alo);
    cudaGetSymbolAddress(&wq_hi_p, g_Wqkv_hi);
    cudaGetSymbolAddress(&wq_lo_p, g_Wqkv_lo);
    cudaGetSymbolAddress(&wp_hi_p, g_Wproj_hi);
    cudaGetSymbolAddress(&wp_lo_p, g_Wproj_lo);
    __nv_bfloat16* Ahi = (__nv_bfloat16*)ahi_p;
    __nv_bfloat16* Alo = (__nv_bfloat16*)alo_p;
    __nv_bfloat16* WqH = (__nv_bfloat16*)wq_hi_p;
    __nv_bfloat16* WqL = (__nv_bfloat16*)wq_lo_p;
    __nv_bfloat16* WpH = (__nv_bfloat16*)wp_hi_p;
    __nv_bfloat16* WpL = (__nv_bfloat16*)wp_lo_p;

    cudaFuncSetAttribute(gemm_bf16x3_kernel,
                         cudaFuncAttributeMaxDynamicSharedMemorySize, GB_SMEM);
    cudaFuncSetAttribute(flash_attn_mma_kernel,
                         cudaFuncAttributeMaxDynamicSharedMemorySize, FA_SMEM);

    const int M = BATCH * SEQ;               // 4096
    const int nelem = M * D_MODEL;

    // 0) RoPE cos/sin table
    rope_table_kernel<<<SEQ * 64 / 256, 256>>>();

    // 1) split activations x -> (Ahi, Alo)
    split_kernel<<<(nelem / 4 + 255) / 256, 256>>>(x, Ahi, Alo, nelem / 4);

    // 2) weight transpose + split
    transpose_split_kernel<<<dim3(3 * D_MODEL / 64, D_MODEL / 64), 256>>>(
        Wqkv, WqH, WqL, D_MODEL, 3 * D_MODEL);
    transpose_split_kernel<<<dim3(D_MODEL / 64, D_MODEL / 64), 256>>>(
        Wproj, WpH, WpL, D_MODEL, D_MODEL);

    // 3) QKV projection with FUSED rope/split epilogue (3-stage, 1 sync/iter)
    gemm_bf16x3_kernel<<<dim3(3 * D_MODEL / 128, M / 128), 128, GB_SMEM>>>(
        Ahi, Alo, WqH, WqL, bqkv, nullptr, M, 3 * D_MODEL, D_MODEL, 1);

    // 4) MMA flash attention: Q in regs, tri-buffered KV, 1 sync/iter
    flash_attn_mma_kernel<<<dim3(SEQ / FA_TQ, BATCH * N_HEAD), 256, FA_SMEM>>>();

    // 5) output projection (plain epilogue)
    gemm_bf16x3_kernel<<<dim3(D_MODEL / 128, M / 128), 128, GB_SMEM>>>(
        Ahi, Alo, WpH, WpL, bproj, out, M, D_MODEL, D_MODEL, 0);
}